// round 2
// baseline (speedup 1.0000x reference)
#include <cuda_runtime.h>
#include <math.h>

#define BB 8
#define HH 128
#define WW 128
#define CC 768
#define NB 8
#define BS 96
#define WF 65
#define LAMBDA 0.01f

// Frequency-domain scratch: [b][wf][h][c], complex
__device__ float2 g_F[(size_t)BB * WF * HH * CC];
// Twiddles: g_tw[k] = exp(-2*pi*i*k/128), k=0..64
__device__ float2 g_tw[65];

__device__ __forceinline__ float2 cmul(float2 a, float2 b) {
    return make_float2(a.x * b.x - a.y * b.y, a.x * b.y + a.y * b.x);
}

__global__ void k_init_tw() {
    int i = threadIdx.x;
    if (i < 65) {
        double a = -2.0 * 3.14159265358979323846264338327950288 * (double)i / 128.0;
        g_tw[i] = make_float2((float)cos(a), (float)sin(a));
    }
}

// ---------------------------------------------------------------------------
// Pass 1: real FFT length 128 along W for every (b,h,c).
// Pack x[2m]+i*x[2m+1] -> 64-pt complex FFT (per-thread serial, smem column)
// -> untangle to X[0..64]. Unnormalized. Writes g_F[b][wf][h][c].
// ---------------------------------------------------------------------------
__global__ void k_fwd_w(const float* __restrict__ x) {
    extern __shared__ float2 sm[];
    float2* sz = sm;             // [64][256]
    float2* stw = sm + 64 * 256; // [65]
    const int t = threadIdx.x;
    if (t < 65) stw[t] = g_tw[t];
    const int b = blockIdx.z, h = blockIdx.y;
    const int c = blockIdx.x * 256 + t;
    const float* xp = x + ((size_t)(b * HH + h) * WW) * CC + c;

    for (int m = 0; m < 64; m++) {
        float re = xp[(size_t)(2 * m) * CC];
        float im = xp[(size_t)(2 * m + 1) * CC];
        sz[(__brev((unsigned)m) >> 26) * 256 + t] = make_float2(re, im);
    }
    __syncthreads();

    for (int s = 0; s < 6; s++) {
        int half = 1 << s;
        for (int j = 0; j < 32; j++) {
            int k = j & (half - 1);
            int i0 = ((j >> s) << (s + 1)) + k;
            float2 w = stw[k << (6 - s)];
            float2 a = sz[i0 * 256 + t];
            float2 bb = sz[(i0 + half) * 256 + t];
            float2 bw = cmul(bb, w);
            sz[i0 * 256 + t] = make_float2(a.x + bw.x, a.y + bw.y);
            sz[(i0 + half) * 256 + t] = make_float2(a.x - bw.x, a.y - bw.y);
        }
    }

    size_t base = ((size_t)b * WF * HH + h) * CC + c; // wf stride = HH*CC
    const size_t ws = (size_t)HH * CC;
    float2 Z0 = sz[t];
    g_F[base] = make_float2(Z0.x + Z0.y, 0.f);
    g_F[base + 64 * ws] = make_float2(Z0.x - Z0.y, 0.f);
    for (int k = 1; k <= 32; k++) {
        float2 Zk = sz[k * 256 + t];
        float2 Zm = sz[(64 - k) * 256 + t];
        float2 E = make_float2(0.5f * (Zk.x + Zm.x), 0.5f * (Zk.y - Zm.y));
        float2 D = make_float2(0.5f * (Zk.x - Zm.x), 0.5f * (Zk.y + Zm.y));
        float2 O = make_float2(D.y, -D.x); // -i*D
        float2 w1v = stw[k];
        float2 p = cmul(w1v, O);
        g_F[base + (size_t)k * ws] = make_float2(E.x + p.x, E.y + p.y);
        float2 Ec = make_float2(E.x, -E.y);
        float2 Oc = make_float2(O.x, -O.y);
        float2 w2v = stw[64 - k];
        float2 q = cmul(w2v, Oc);
        g_F[base + (size_t)(64 - k) * ws] = make_float2(Ec.x + q.x, Ec.y + q.y);
    }
}

// ---------------------------------------------------------------------------
// Pass 2/4: complex FFT length 128 along H (in place).
// ---------------------------------------------------------------------------
template <bool INV, bool SCALE>
__global__ void k_fft_h() {
    extern __shared__ float2 sm[];
    float2* sz = sm;              // [128][128]
    float2* stw = sm + 128 * 128; // [65]
    const int t = threadIdx.x;
    if (t < 65) stw[t] = g_tw[t];
    const int b = blockIdx.z, wf = blockIdx.y;
    const int c = blockIdx.x * 128 + t;
    size_t base = ((size_t)(b * WF + wf) * HH) * CC + c;

    for (int h = 0; h < 128; h++)
        sz[(__brev((unsigned)h) >> 25) * 128 + t] = g_F[base + (size_t)h * CC];
    __syncthreads();

    for (int s = 0; s < 7; s++) {
        int half = 1 << s;
        for (int j = 0; j < 64; j++) {
            int k = j & (half - 1);
            int i0 = ((j >> s) << (s + 1)) + k;
            float2 w = stw[k << (6 - s)];
            if (INV) w.y = -w.y;
            float2 a = sz[i0 * 128 + t];
            float2 bb = sz[(i0 + half) * 128 + t];
            float2 bw = cmul(bb, w);
            sz[i0 * 128 + t] = make_float2(a.x + bw.x, a.y + bw.y);
            sz[(i0 + half) * 128 + t] = make_float2(a.x - bw.x, a.y - bw.y);
        }
    }

    for (int h = 0; h < 128; h++) {
        float2 v = sz[h * 128 + t];
        if (SCALE) { v.x *= (1.f / 128.f); v.y *= (1.f / 128.f); }
        g_F[base + (size_t)h * CC] = v;
    }
}

// ---------------------------------------------------------------------------
// Pass 3: block-diagonal complex MLP + softshrink, in place on g_F.
// ---------------------------------------------------------------------------
__global__ void k_mlp(const float* __restrict__ w1, const float* __restrict__ b1,
                      const float* __restrict__ w2, const float* __restrict__ b2) {
    extern __shared__ float2 sm[];
    float2* sX = sm;          // 6144
    float2* sO = sm + 6144;   // 6144
    float2* sW = sm + 12288;  // 9216
    const int tid = threadIdx.x;
    const int tx = tid & 31, ty = tid >> 5;
    const int n = blockIdx.y;
    const int pt0 = blockIdx.x * 64;

    for (int idx = tid; idx < 6144; idx += 256) {
        int p = idx / 96, i = idx - p * 96;
        sX[idx] = g_F[(size_t)(pt0 + p) * CC + n * BS + i];
    }
    {
        const float* wr = w1 + n * BS * BS;
        const float* wi = w1 + NB * BS * BS + n * BS * BS;
        for (int idx = tid; idx < 9216; idx += 256)
            sW[idx] = make_float2(wr[idx], wi[idx]);
    }
    __syncthreads();

    float ar[8][3], ai[8][3];
#pragma unroll
    for (int j = 0; j < 3; j++) {
        int o = tx + 32 * j;
        float brv = b1[n * BS + o], biv = b1[NB * BS + n * BS + o];
#pragma unroll
        for (int pp = 0; pp < 8; pp++) { ar[pp][j] = brv; ai[pp][j] = biv; }
    }
    for (int k = 0; k < 96; k++) {
        float2 w0 = sW[k * 96 + tx];
        float2 w1v = sW[k * 96 + tx + 32];
        float2 w2v = sW[k * 96 + tx + 64];
#pragma unroll
        for (int pp = 0; pp < 8; pp++) {
            float2 xv = sX[(ty * 8 + pp) * 96 + k];
            ar[pp][0] = fmaf(xv.x, w0.x, fmaf(-xv.y, w0.y, ar[pp][0]));
            ai[pp][0] = fmaf(xv.y, w0.x, fmaf( xv.x, w0.y, ai[pp][0]));
            ar[pp][1] = fmaf(xv.x, w1v.x, fmaf(-xv.y, w1v.y, ar[pp][1]));
            ai[pp][1] = fmaf(xv.y, w1v.x, fmaf( xv.x, w1v.y, ai[pp][1]));
            ar[pp][2] = fmaf(xv.x, w2v.x, fmaf(-xv.y, w2v.y, ar[pp][2]));
            ai[pp][2] = fmaf(xv.y, w2v.x, fmaf( xv.x, w2v.y, ai[pp][2]));
        }
    }
#pragma unroll
    for (int j = 0; j < 3; j++) {
        int o = tx + 32 * j;
#pragma unroll
        for (int pp = 0; pp < 8; pp++)
            sO[(ty * 8 + pp) * 96 + o] =
                make_float2(fmaxf(ar[pp][j], 0.f), fmaxf(ai[pp][j], 0.f));
    }
    __syncthreads();
    {
        const float* wr = w2 + n * BS * BS;
        const float* wi = w2 + NB * BS * BS + n * BS * BS;
        for (int idx = tid; idx < 9216; idx += 256)
            sW[idx] = make_float2(wr[idx], wi[idx]);
    }
    __syncthreads();

#pragma unroll
    for (int j = 0; j < 3; j++) {
        int o = tx + 32 * j;
        float brv = b2[n * BS + o], biv = b2[NB * BS + n * BS + o];
#pragma unroll
        for (int pp = 0; pp < 8; pp++) { ar[pp][j] = brv; ai[pp][j] = biv; }
    }
    for (int k = 0; k < 96; k++) {
        float2 w0 = sW[k * 96 + tx];
        float2 w1v = sW[k * 96 + tx + 32];
        float2 w2v = sW[k * 96 + tx + 64];
#pragma unroll
        for (int pp = 0; pp < 8; pp++) {
            float2 xv = sO[(ty * 8 + pp) * 96 + k];
            ar[pp][0] = fmaf(xv.x, w0.x, fmaf(-xv.y, w0.y, ar[pp][0]));
            ai[pp][0] = fmaf(xv.y, w0.x, fmaf( xv.x, w0.y, ai[pp][0]));
            ar[pp][1] = fmaf(xv.x, w1v.x, fmaf(-xv.y, w1v.y, ar[pp][1]));
            ai[pp][1] = fmaf(xv.y, w1v.x, fmaf( xv.x, w1v.y, ai[pp][1]));
            ar[pp][2] = fmaf(xv.x, w2v.x, fmaf(-xv.y, w2v.y, ar[pp][2]));
            ai[pp][2] = fmaf(xv.y, w2v.x, fmaf( xv.x, w2v.y, ai[pp][2]));
        }
    }
#pragma unroll
    for (int j = 0; j < 3; j++) {
        int o = tx + 32 * j;
#pragma unroll
        for (int pp = 0; pp < 8; pp++) {
            float vr = ar[pp][j], vi = ai[pp][j];
            vr = vr > LAMBDA ? vr - LAMBDA : (vr < -LAMBDA ? vr + LAMBDA : 0.f);
            vi = vi > LAMBDA ? vi - LAMBDA : (vi < -LAMBDA ? vi + LAMBDA : 0.f);
            g_F[(size_t)(pt0 + ty * 8 + pp) * CC + n * BS + o] = make_float2(vr, vi);
        }
    }
}

// ---------------------------------------------------------------------------
// Pass 5: inverse real FFT length 128 along W + 1/128 scale + residual add.
// NOTE: irfft ignores the imaginary parts of bins 0 and N/2 (C2R semantics).
// The nonlinear MLP breaks Hermitian symmetry there, so we must zero those
// imag parts explicitly to match the reference.
// ---------------------------------------------------------------------------
__global__ void k_inv_w(const float* __restrict__ x, float* __restrict__ out) {
    extern __shared__ float2 sm[];
    float2* sz = sm;
    float2* stw = sm + 64 * 256;
    const int t = threadIdx.x;
    if (t < 65) stw[t] = g_tw[t];
    __syncthreads();
    const int b = blockIdx.z, h = blockIdx.y;
    const int c = blockIdx.x * 256 + t;
    size_t base = ((size_t)b * WF * HH + h) * CC + c;
    const size_t ws = (size_t)HH * CC;

    for (int k = 0; k <= 32; k++) {
        float2 Xk = g_F[base + (size_t)k * ws];
        float2 Xm = g_F[base + (size_t)(64 - k) * ws];
        if (k == 0) { Xk.y = 0.f; Xm.y = 0.f; }  // C2R: drop imag of DC & Nyquist
        float2 A = make_float2(Xk.x + Xm.x, Xk.y - Xm.y);
        float2 D = make_float2(Xk.x - Xm.x, Xk.y + Xm.y);
        float2 wc = make_float2(stw[k].x, -stw[k].y);
        float2 tv = cmul(wc, D);
        sz[(__brev((unsigned)k) >> 26) * 256 + t] = make_float2(A.x - tv.y, A.y + tv.x);
        if (k >= 1 && k <= 31) {
            float2 A2 = make_float2(Xm.x + Xk.x, Xm.y - Xk.y);
            float2 D2 = make_float2(Xm.x - Xk.x, Xm.y + Xk.y);
            float2 wc2 = make_float2(stw[64 - k].x, -stw[64 - k].y);
            float2 t2 = cmul(wc2, D2);
            sz[(__brev((unsigned)(64 - k)) >> 26) * 256 + t] =
                make_float2(A2.x - t2.y, A2.y + t2.x);
        }
    }

    for (int s = 0; s < 6; s++) {
        int half = 1 << s;
        for (int j = 0; j < 32; j++) {
            int k = j & (half - 1);
            int i0 = ((j >> s) << (s + 1)) + k;
            float2 w = stw[k << (6 - s)];
            w.y = -w.y;
            float2 a = sz[i0 * 256 + t];
            float2 bb = sz[(i0 + half) * 256 + t];
            float2 bw = cmul(bb, w);
            sz[i0 * 256 + t] = make_float2(a.x + bw.x, a.y + bw.y);
            sz[(i0 + half) * 256 + t] = make_float2(a.x - bw.x, a.y - bw.y);
        }
    }

    const size_t xbase = ((size_t)(b * HH + h) * WW) * CC + c;
    for (int m = 0; m < 64; m++) {
        float2 z = sz[m * 256 + t];
        size_t i0 = xbase + (size_t)(2 * m) * CC;
        size_t i1 = xbase + (size_t)(2 * m + 1) * CC;
        out[i0] = z.x * (1.f / 128.f) + x[i0];
        out[i1] = z.y * (1.f / 128.f) + x[i1];
    }
}

// ---------------------------------------------------------------------------
extern "C" void kernel_launch(void* const* d_in, const int* in_sizes, int n_in,
                              void* d_out, int out_size) {
    const float* x  = (const float*)d_in[0];
    const float* w1 = (const float*)d_in[1];
    const float* b1 = (const float*)d_in[2];
    const float* w2 = (const float*)d_in[3];
    const float* b2 = (const float*)d_in[4];
    float* out = (float*)d_out;

    const size_t sm_fft1 = (size_t)(64 * 256 + 65) * sizeof(float2);
    const size_t sm_fft2 = (size_t)(128 * 128 + 65) * sizeof(float2);
    const size_t sm_mlp  = (size_t)(6144 + 6144 + 9216) * sizeof(float2);

    cudaFuncSetAttribute(k_fwd_w, cudaFuncAttributeMaxDynamicSharedMemorySize, (int)sm_fft1);
    cudaFuncSetAttribute(k_fft_h<false, true>, cudaFuncAttributeMaxDynamicSharedMemorySize, (int)sm_fft2);
    cudaFuncSetAttribute(k_fft_h<true, false>, cudaFuncAttributeMaxDynamicSharedMemorySize, (int)sm_fft2);
    cudaFuncSetAttribute(k_mlp, cudaFuncAttributeMaxDynamicSharedMemorySize, (int)sm_mlp);
    cudaFuncSetAttribute(k_inv_w, cudaFuncAttributeMaxDynamicSharedMemorySize, (int)sm_fft1);

    k_init_tw<<<1, 128>>>();
    k_fwd_w<<<dim3(3, 128, 8), 256, sm_fft1>>>(x);
    k_fft_h<false, true><<<dim3(6, 65, 8), 128, sm_fft2>>>();
    k_mlp<<<dim3(1040, 8), 256, sm_mlp>>>(w1, b1, w2, b2);
    k_fft_h<true, false><<<dim3(6, 65, 8), 128, sm_fft2>>>();
    k_inv_w<<<dim3(3, 128, 8), 256, sm_fft1>>>(x, out);
}

// round 3
// speedup vs baseline: 1.7922x; 1.7922x over previous
#include <cuda_runtime.h>
#include <math.h>

#define BB 8
#define HH 128
#define WW 128
#define CC 768
#define NB 8
#define BS 96
#define WF 65
#define LAMBDA 0.01f

// Frequency-domain scratch: [b][wf][h][c], complex
__device__ float2 g_F[(size_t)BB * WF * HH * CC];
// Twiddles: g_tw[k] = exp(-2*pi*i*k/128), k=0..64
__device__ float2 g_tw[65];

__device__ __forceinline__ float2 cmul(float2 a, float2 b) {
    return make_float2(a.x * b.x - a.y * b.y, a.x * b.y + a.y * b.x);
}

__device__ __forceinline__ unsigned f2tf(float f) {
    unsigned u;
    asm("cvt.rna.tf32.f32 %0, %1;" : "=r"(u) : "f"(f));
    return u;
}

__device__ __forceinline__ void mma8(float c[4], unsigned a0, unsigned a1,
                                     unsigned a2, unsigned a3,
                                     unsigned b0, unsigned b1) {
    asm volatile(
        "mma.sync.aligned.m16n8k8.row.col.f32.tf32.tf32.f32 "
        "{%0,%1,%2,%3}, {%4,%5,%6,%7}, {%8,%9}, {%0,%1,%2,%3};"
        : "+f"(c[0]), "+f"(c[1]), "+f"(c[2]), "+f"(c[3])
        : "r"(a0), "r"(a1), "r"(a2), "r"(a3), "r"(b0), "r"(b1));
}

__device__ __forceinline__ float sshrink(float v) {
    return v > LAMBDA ? v - LAMBDA : (v < -LAMBDA ? v + LAMBDA : 0.f);
}

__global__ void k_init_tw() {
    int i = threadIdx.x;
    if (i < 65) {
        double a = -2.0 * 3.14159265358979323846264338327950288 * (double)i / 128.0;
        g_tw[i] = make_float2((float)cos(a), (float)sin(a));
    }
}

// ---------------------------------------------------------------------------
// Pass 1: real FFT length 128 along W. Pack pairs -> 64-pt complex FFT with
// butterflies parallelized across threads -> untangle. Tile [64][128 c].
// 512 threads: cl = t&127 (channel), q = t>>7 (0..3).
// ---------------------------------------------------------------------------
__global__ __launch_bounds__(512, 1) void k_fwd_w(const float* __restrict__ x) {
    extern __shared__ float2 sm2[];
    float2* sz = sm2;               // [64][128]
    float2* stw = sm2 + 64 * 128;   // [65]
    const int t = threadIdx.x;
    if (t < 65) stw[t] = g_tw[t];
    const int cl = t & 127, q = t >> 7;
    const int b = blockIdx.z, h = blockIdx.y;
    const int c = blockIdx.x * 128 + cl;
    const float* xp = x + ((size_t)(b * HH + h) * WW) * CC + c;

#pragma unroll
    for (int mm = 0; mm < 16; mm++) {
        int m = q * 16 + mm;
        float re = xp[(size_t)(2 * m) * CC];
        float im = xp[(size_t)(2 * m + 1) * CC];
        sz[(__brev((unsigned)m) >> 26) * 128 + cl] = make_float2(re, im);
    }
    __syncthreads();

    for (int s = 0; s < 6; s++) {
        int half = 1 << s;
#pragma unroll
        for (int jj = 0; jj < 8; jj++) {
            int j = q * 8 + jj;
            int k = j & (half - 1);
            int i0 = ((j >> s) << (s + 1)) + k;
            float2 w = stw[k << (6 - s)];
            float2 a = sz[i0 * 128 + cl];
            float2 bb = sz[(i0 + half) * 128 + cl];
            float2 bw = cmul(bb, w);
            sz[i0 * 128 + cl] = make_float2(a.x + bw.x, a.y + bw.y);
            sz[(i0 + half) * 128 + cl] = make_float2(a.x - bw.x, a.y - bw.y);
        }
        __syncthreads();
    }

    size_t base = ((size_t)b * WF * HH + h) * CC + c;
    const size_t ws = (size_t)HH * CC;
#pragma unroll
    for (int jj = 0; jj < 8; jj++) {
        int idx = q * 8 + jj;
        if (idx == 0) {
            float2 Z0 = sz[cl];
            g_F[base] = make_float2(Z0.x + Z0.y, 0.f);
            g_F[base + 64 * ws] = make_float2(Z0.x - Z0.y, 0.f);
            float2 Z32 = sz[32 * 128 + cl];
            g_F[base + 32 * ws] = make_float2(Z32.x, -Z32.y);
        } else {
            int k = idx;  // 1..31
            float2 Zk = sz[k * 128 + cl];
            float2 Zm = sz[(64 - k) * 128 + cl];
            float2 E = make_float2(0.5f * (Zk.x + Zm.x), 0.5f * (Zk.y - Zm.y));
            float2 D = make_float2(0.5f * (Zk.x - Zm.x), 0.5f * (Zk.y + Zm.y));
            float2 O = make_float2(D.y, -D.x);
            float2 p = cmul(stw[k], O);
            g_F[base + (size_t)k * ws] = make_float2(E.x + p.x, E.y + p.y);
            float2 Ec = make_float2(E.x, -E.y);
            float2 Oc = make_float2(O.x, -O.y);
            float2 qv = cmul(stw[64 - k], Oc);
            g_F[base + (size_t)(64 - k) * ws] = make_float2(Ec.x + qv.x, Ec.y + qv.y);
        }
    }
}

// ---------------------------------------------------------------------------
// Pass 2/4: complex FFT length 128 along H, tile [128 h][64 c], 512 threads:
// cl = t&63 (channel), oct = t>>6 (0..7), 8 butterflies/thread/stage.
// ---------------------------------------------------------------------------
template <bool INV, bool SCALE>
__global__ __launch_bounds__(512, 1) void k_fft_h() {
    extern __shared__ float2 sm2[];
    float2* sz = sm2;               // [128][64]
    float2* stw = sm2 + 128 * 64;   // [65]
    const int t = threadIdx.x;
    if (t < 65) stw[t] = g_tw[t];
    const int cl = t & 63, oct = t >> 6;
    const int b = blockIdx.z, wf = blockIdx.y;
    const int c = blockIdx.x * 64 + cl;
    size_t base = ((size_t)(b * WF + wf) * HH) * CC + c;

#pragma unroll
    for (int hh = 0; hh < 16; hh++) {
        int h = oct * 16 + hh;
        sz[(__brev((unsigned)h) >> 25) * 64 + cl] = g_F[base + (size_t)h * CC];
    }
    __syncthreads();

    for (int s = 0; s < 7; s++) {
        int half = 1 << s;
#pragma unroll
        for (int jj = 0; jj < 8; jj++) {
            int j = oct * 8 + jj;
            int k = j & (half - 1);
            int i0 = ((j >> s) << (s + 1)) + k;
            float2 w = stw[k << (6 - s)];
            if (INV) w.y = -w.y;
            float2 a = sz[i0 * 64 + cl];
            float2 bb = sz[(i0 + half) * 64 + cl];
            float2 bw = cmul(bb, w);
            sz[i0 * 64 + cl] = make_float2(a.x + bw.x, a.y + bw.y);
            sz[(i0 + half) * 64 + cl] = make_float2(a.x - bw.x, a.y - bw.y);
        }
        __syncthreads();
    }

#pragma unroll
    for (int hh = 0; hh < 16; hh++) {
        int h = oct * 16 + hh;
        float2 v = sz[h * 64 + cl];
        if (SCALE) { v.x *= (1.f / 128.f); v.y *= (1.f / 128.f); }
        g_F[base + (size_t)h * CC] = v;
    }
}

// ---------------------------------------------------------------------------
// Pass 3: block-diagonal complex MLP via tf32 mma.sync.
// Complex GEMM as real GEMM: In[64pts][192] @ Wc[192][192],
//   Wc = [[wr, wi], [-wi, wr]]. Per block: n = channel-block, 64 points.
// 256 threads = 8 warps: warp = mrow(0..3) x nhalf(0..1).
// smem (words): sA[64][196] tf32 | sWr[96][104] | sWi[96][104] | sO[64][196]
// Padded strides chosen for conflict-free fragment loads.
// ---------------------------------------------------------------------------
__global__ __launch_bounds__(256, 1) void k_mlp(const float* __restrict__ w1,
                                                const float* __restrict__ b1,
                                                const float* __restrict__ w2,
                                                const float* __restrict__ b2) {
    extern __shared__ unsigned sm_u[];
    unsigned* sA = sm_u;                     // [64][196]
    unsigned* sWr = sm_u + 64 * 196;         // [96][104]
    unsigned* sWi = sWr + 96 * 104;          // [96][104]
    unsigned* sO = sWi + 96 * 104;           // [64][196]
    float* sAf = (float*)sA;

    const int tid = threadIdx.x;
    const int lane = tid & 31, warp = tid >> 5;
    const int mrow = warp & 3, nhalf = warp >> 2;
    const int g = lane >> 2, tig = lane & 3;
    const int n = blockIdx.y;
    const int pt0 = blockIdx.x * 64;
    const int arow = mrow * 16 + g;

    // Stage X: A[p][i] = xr(i), A[p][96+i] = xi(i)
    for (int idx = tid; idx < 64 * 96; idx += 256) {
        int p = idx / 96, i = idx - p * 96;
        float2 v = g_F[(size_t)(pt0 + p) * CC + n * BS + i];
        sA[p * 196 + i] = f2tf(v.x);
        sA[p * 196 + 96 + i] = f2tf(v.y);
    }
    // Stage W1 (tf32)
    {
        const float* wr = w1 + n * BS * BS;
        const float* wi = w1 + NB * BS * BS + n * BS * BS;
        for (int idx = tid; idx < 9216; idx += 256) {
            int r = idx / 96, ci = idx - r * 96;
            sWr[r * 104 + ci] = f2tf(wr[idx]);
            sWi[r * 104 + ci] = f2tf(wi[idx]);
        }
    }
    __syncthreads();

    float acc[12][4];

    // ================= layer 1 =================
    {
        const float* bptr = (nhalf == 0) ? (b1 + n * BS) : (b1 + NB * BS + n * BS);
#pragma unroll
        for (int nt = 0; nt < 12; nt++) {
            float bv0 = bptr[nt * 8 + 2 * tig];
            float bv1 = bptr[nt * 8 + 2 * tig + 1];
            acc[nt][0] = bv0; acc[nt][1] = bv1;
            acc[nt][2] = bv0; acc[nt][3] = bv1;
        }
#pragma unroll 1
        for (int kc = 0; kc < 24; kc++) {
            const unsigned* Ain = sA + kc * 8;
            unsigned a0 = Ain[arow * 196 + tig];
            unsigned a1 = Ain[(arow + 8) * 196 + tig];
            unsigned a2 = Ain[arow * 196 + tig + 4];
            unsigned a3 = Ain[(arow + 8) * 196 + tig + 4];
            const unsigned* Bsrc;
            unsigned sgn;
            if (kc < 12) {
                Bsrc = ((nhalf == 0) ? sWr : sWi) + kc * 8 * 104;
                sgn = 0u;
            } else {
                Bsrc = ((nhalf == 0) ? sWi : sWr) + (kc - 12) * 8 * 104;
                sgn = (nhalf == 0) ? 0x80000000u : 0u;
            }
#pragma unroll
            for (int nt = 0; nt < 12; nt++) {
                unsigned b0 = Bsrc[tig * 104 + nt * 8 + g] ^ sgn;
                unsigned b1v = Bsrc[(tig + 4) * 104 + nt * 8 + g] ^ sgn;
                mma8(acc[nt], a0, a1, a2, a3, b0, b1v);
            }
        }
        // ReLU -> sO (tf32)
#pragma unroll
        for (int nt = 0; nt < 12; nt++) {
            int col = nhalf * 96 + nt * 8 + 2 * tig;
            uint2 v0 = make_uint2(f2tf(fmaxf(acc[nt][0], 0.f)),
                                  f2tf(fmaxf(acc[nt][1], 0.f)));
            uint2 v1 = make_uint2(f2tf(fmaxf(acc[nt][2], 0.f)),
                                  f2tf(fmaxf(acc[nt][3], 0.f)));
            *(uint2*)(sO + arow * 196 + col) = v0;
            *(uint2*)(sO + (arow + 8) * 196 + col) = v1;
        }
    }
    __syncthreads();
    // Stage W2 over W1
    {
        const float* wr = w2 + n * BS * BS;
        const float* wi = w2 + NB * BS * BS + n * BS * BS;
        for (int idx = tid; idx < 9216; idx += 256) {
            int r = idx / 96, ci = idx - r * 96;
            sWr[r * 104 + ci] = f2tf(wr[idx]);
            sWi[r * 104 + ci] = f2tf(wi[idx]);
        }
    }
    __syncthreads();

    // ================= layer 2 =================
    {
        const float* bptr = (nhalf == 0) ? (b2 + n * BS) : (b2 + NB * BS + n * BS);
#pragma unroll
        for (int nt = 0; nt < 12; nt++) {
            float bv0 = bptr[nt * 8 + 2 * tig];
            float bv1 = bptr[nt * 8 + 2 * tig + 1];
            acc[nt][0] = bv0; acc[nt][1] = bv1;
            acc[nt][2] = bv0; acc[nt][3] = bv1;
        }
#pragma unroll 1
        for (int kc = 0; kc < 24; kc++) {
            const unsigned* Ain = sO + kc * 8;
            unsigned a0 = Ain[arow * 196 + tig];
            unsigned a1 = Ain[(arow + 8) * 196 + tig];
            unsigned a2 = Ain[arow * 196 + tig + 4];
            unsigned a3 = Ain[(arow + 8) * 196 + tig + 4];
            const unsigned* Bsrc;
            unsigned sgn;
            if (kc < 12) {
                Bsrc = ((nhalf == 0) ? sWr : sWi) + kc * 8 * 104;
                sgn = 0u;
            } else {
                Bsrc = ((nhalf == 0) ? sWi : sWr) + (kc - 12) * 8 * 104;
                sgn = (nhalf == 0) ? 0x80000000u : 0u;
            }
#pragma unroll
            for (int nt = 0; nt < 12; nt++) {
                unsigned b0 = Bsrc[tig * 104 + nt * 8 + g] ^ sgn;
                unsigned b1v = Bsrc[(tig + 4) * 104 + nt * 8 + g] ^ sgn;
                mma8(acc[nt], a0, a1, a2, a3, b0, b1v);
            }
        }
        // softshrink + stage interleaved complex into sA (as floats)
#pragma unroll
        for (int nt = 0; nt < 12; nt++) {
            int jl = nt * 8 + 2 * tig;   // channel index within block (0..95)
            float v00 = sshrink(acc[nt][0]), v01 = sshrink(acc[nt][1]);
            float v10 = sshrink(acc[nt][2]), v11 = sshrink(acc[nt][3]);
            sAf[arow * 196 + 2 * jl + nhalf] = v00;
            sAf[arow * 196 + 2 * (jl + 1) + nhalf] = v01;
            sAf[(arow + 8) * 196 + 2 * jl + nhalf] = v10;
            sAf[(arow + 8) * 196 + 2 * (jl + 1) + nhalf] = v11;
        }
    }
    __syncthreads();

    // Coalesced write-back
    for (int idx = tid; idx < 64 * 96; idx += 256) {
        int p = idx / 96, i = idx - p * 96;
        float2 v = make_float2(sAf[p * 196 + 2 * i], sAf[p * 196 + 2 * i + 1]);
        g_F[(size_t)(pt0 + p) * CC + n * BS + i] = v;
    }
}

// ---------------------------------------------------------------------------
// Pass 5: inverse real FFT length 128 along W + 1/128 scale + residual add.
// C2R semantics: imag of DC & Nyquist ignored (only .x used for k==0 task).
// ---------------------------------------------------------------------------
__global__ __launch_bounds__(512, 1) void k_inv_w(const float* __restrict__ x,
                                                  float* __restrict__ out) {
    extern __shared__ float2 sm2[];
    float2* sz = sm2;               // [64][128]
    float2* stw = sm2 + 64 * 128;   // [65]
    const int t = threadIdx.x;
    if (t < 65) stw[t] = g_tw[t];
    __syncthreads();
    const int cl = t & 127, q = t >> 7;
    const int b = blockIdx.z, h = blockIdx.y;
    const int c = blockIdx.x * 128 + cl;
    size_t base = ((size_t)b * WF * HH + h) * CC + c;
    const size_t ws = (size_t)HH * CC;

#pragma unroll
    for (int jj = 0; jj < 8; jj++) {
        int idx = q * 8 + jj;
        if (idx == 0) {
            float2 X0 = g_F[base];
            float2 X64 = g_F[base + 64 * ws];
            sz[cl] = make_float2(X0.x + X64.x, X0.x - X64.x);  // imag dropped
            float2 X32 = g_F[base + 32 * ws];
            sz[1 * 128 + cl] = make_float2(2.f * X32.x, -2.f * X32.y);
        } else {
            int k = idx;  // 1..31
            float2 Xk = g_F[base + (size_t)k * ws];
            float2 Xm = g_F[base + (size_t)(64 - k) * ws];
            float2 A = make_float2(Xk.x + Xm.x, Xk.y - Xm.y);
            float2 D = make_float2(Xk.x - Xm.x, Xk.y + Xm.y);
            float2 wc = make_float2(stw[k].x, -stw[k].y);
            float2 tv = cmul(wc, D);
            sz[(__brev((unsigned)k) >> 26) * 128 + cl] =
                make_float2(A.x - tv.y, A.y + tv.x);
            float2 A2 = make_float2(Xm.x + Xk.x, Xm.y - Xk.y);
            float2 D2 = make_float2(Xm.x - Xk.x, Xm.y + Xk.y);
            float2 wc2 = make_float2(stw[64 - k].x, -stw[64 - k].y);
            float2 t2 = cmul(wc2, D2);
            sz[(__brev((unsigned)(64 - k)) >> 26) * 128 + cl] =
                make_float2(A2.x - t2.y, A2.y + t2.x);
        }
    }
    __syncthreads();

    for (int s = 0; s < 6; s++) {
        int half = 1 << s;
#pragma unroll
        for (int jj = 0; jj < 8; jj++) {
            int j = q * 8 + jj;
            int k = j & (half - 1);
            int i0 = ((j >> s) << (s + 1)) + k;
            float2 w = stw[k << (6 - s)];
            w.y = -w.y;
            float2 a = sz[i0 * 128 + cl];
            float2 bb = sz[(i0 + half) * 128 + cl];
            float2 bw = cmul(bb, w);
            sz[i0 * 128 + cl] = make_float2(a.x + bw.x, a.y + bw.y);
            sz[(i0 + half) * 128 + cl] = make_float2(a.x - bw.x, a.y - bw.y);
        }
        __syncthreads();
    }

    const size_t xbase = ((size_t)(b * HH + h) * WW) * CC + c;
#pragma unroll
    for (int mm = 0; mm < 16; mm++) {
        int m = q * 16 + mm;
        float2 z = sz[m * 128 + cl];
        size_t i0 = xbase + (size_t)(2 * m) * CC;
        size_t i1 = xbase + (size_t)(2 * m + 1) * CC;
        out[i0] = z.x * (1.f / 128.f) + x[i0];
        out[i1] = z.y * (1.f / 128.f) + x[i1];
    }
}

// ---------------------------------------------------------------------------
extern "C" void kernel_launch(void* const* d_in, const int* in_sizes, int n_in,
                              void* d_out, int out_size) {
    const float* x  = (const float*)d_in[0];
    const float* w1 = (const float*)d_in[1];
    const float* b1 = (const float*)d_in[2];
    const float* w2 = (const float*)d_in[3];
    const float* b2 = (const float*)d_in[4];
    float* out = (float*)d_out;

    const size_t sm_fftw = (size_t)(64 * 128 + 65) * sizeof(float2);   // 66056
    const size_t sm_ffth = (size_t)(128 * 64 + 65) * sizeof(float2);   // 66056
    const size_t sm_mlp  = (size_t)(64 * 196 * 2 + 96 * 104 * 2) * 4;  // 180224

    cudaFuncSetAttribute(k_fwd_w, cudaFuncAttributeMaxDynamicSharedMemorySize, (int)sm_fftw);
    cudaFuncSetAttribute(k_fft_h<false, true>, cudaFuncAttributeMaxDynamicSharedMemorySize, (int)sm_ffth);
    cudaFuncSetAttribute(k_fft_h<true, false>, cudaFuncAttributeMaxDynamicSharedMemorySize, (int)sm_ffth);
    cudaFuncSetAttribute(k_mlp, cudaFuncAttributeMaxDynamicSharedMemorySize, (int)sm_mlp);
    cudaFuncSetAttribute(k_inv_w, cudaFuncAttributeMaxDynamicSharedMemorySize, (int)sm_fftw);

    k_init_tw<<<1, 128>>>();
    k_fwd_w<<<dim3(6, 128, 8), 512, sm_fftw>>>(x);
    k_fft_h<false, true><<<dim3(12, 65, 8), 512, sm_ffth>>>();
    k_mlp<<<dim3(1040, 8), 256, sm_mlp>>>(w1, b1, w2, b2);
    k_fft_h<true, false><<<dim3(12, 65, 8), 512, sm_ffth>>>();
    k_inv_w<<<dim3(6, 128, 8), 512, sm_fftw>>>(x, out);
}

// round 4
// speedup vs baseline: 1.8415x; 1.0275x over previous
#include <cuda_runtime.h>
#include <math.h>

#define BB 8
#define HH 128
#define WW 128
#define CC 768
#define NB 8
#define BS 96
#define WF 65
#define LAMBDA 0.01f

// Frequency-domain scratch: [b][wf][h][c], complex
__device__ float2 g_F[(size_t)BB * WF * HH * CC];
// Twiddles: g_tw[k] = exp(-2*pi*i*k/128), k=0..64
__device__ float2 g_tw[65];

__device__ __forceinline__ float2 cmul(float2 a, float2 b) {
    return make_float2(a.x * b.x - a.y * b.y, a.x * b.y + a.y * b.x);
}

__device__ __forceinline__ unsigned f2tf(float f) {
    unsigned u;
    asm("cvt.rna.tf32.f32 %0, %1;" : "=r"(u) : "f"(f));
    return u;
}

__device__ __forceinline__ void mma8(float c[4], unsigned a0, unsigned a1,
                                     unsigned a2, unsigned a3,
                                     unsigned b0, unsigned b1) {
    asm volatile(
        "mma.sync.aligned.m16n8k8.row.col.f32.tf32.tf32.f32 "
        "{%0,%1,%2,%3}, {%4,%5,%6,%7}, {%8,%9}, {%0,%1,%2,%3};"
        : "+f"(c[0]), "+f"(c[1]), "+f"(c[2]), "+f"(c[3])
        : "r"(a0), "r"(a1), "r"(a2), "r"(a3), "r"(b0), "r"(b1));
}

__device__ __forceinline__ float sshrink(float v) {
    return v > LAMBDA ? v - LAMBDA : (v < -LAMBDA ? v + LAMBDA : 0.f);
}

__global__ void k_init_tw() {
    int i = threadIdx.x;
    if (i < 65) {
        double a = -2.0 * 3.14159265358979323846264338327950288 * (double)i / 128.0;
        g_tw[i] = make_float2((float)cos(a), (float)sin(a));
    }
}

// ---------------------------------------------------------------------------
// Pass 1: real FFT length 128 along W. Pack pairs -> 64-pt complex FFT with
// butterflies parallelized across threads -> untangle. Tile [64][128 c].
// ---------------------------------------------------------------------------
__global__ __launch_bounds__(512, 2) void k_fwd_w(const float* __restrict__ x) {
    extern __shared__ float2 sm2[];
    float2* sz = sm2;               // [64][128]
    float2* stw = sm2 + 64 * 128;   // [65]
    const int t = threadIdx.x;
    if (t < 65) stw[t] = g_tw[t];
    const int cl = t & 127, q = t >> 7;
    const int b = blockIdx.z, h = blockIdx.y;
    const int c = blockIdx.x * 128 + cl;
    const float* xp = x + ((size_t)(b * HH + h) * WW) * CC + c;

#pragma unroll
    for (int mm = 0; mm < 16; mm++) {
        int m = q * 16 + mm;
        float re = xp[(size_t)(2 * m) * CC];
        float im = xp[(size_t)(2 * m + 1) * CC];
        sz[(__brev((unsigned)m) >> 26) * 128 + cl] = make_float2(re, im);
    }
    __syncthreads();

    for (int s = 0; s < 6; s++) {
        int half = 1 << s;
#pragma unroll
        for (int jj = 0; jj < 8; jj++) {
            int j = q * 8 + jj;
            int k = j & (half - 1);
            int i0 = ((j >> s) << (s + 1)) + k;
            float2 w = stw[k << (6 - s)];
            float2 a = sz[i0 * 128 + cl];
            float2 bb = sz[(i0 + half) * 128 + cl];
            float2 bw = cmul(bb, w);
            sz[i0 * 128 + cl] = make_float2(a.x + bw.x, a.y + bw.y);
            sz[(i0 + half) * 128 + cl] = make_float2(a.x - bw.x, a.y - bw.y);
        }
        __syncthreads();
    }

    size_t base = ((size_t)b * WF * HH + h) * CC + c;
    const size_t ws = (size_t)HH * CC;
#pragma unroll
    for (int jj = 0; jj < 8; jj++) {
        int idx = q * 8 + jj;
        if (idx == 0) {
            float2 Z0 = sz[cl];
            g_F[base] = make_float2(Z0.x + Z0.y, 0.f);
            g_F[base + 64 * ws] = make_float2(Z0.x - Z0.y, 0.f);
            float2 Z32 = sz[32 * 128 + cl];
            g_F[base + 32 * ws] = make_float2(Z32.x, -Z32.y);
        } else {
            int k = idx;  // 1..31
            float2 Zk = sz[k * 128 + cl];
            float2 Zm = sz[(64 - k) * 128 + cl];
            float2 E = make_float2(0.5f * (Zk.x + Zm.x), 0.5f * (Zk.y - Zm.y));
            float2 D = make_float2(0.5f * (Zk.x - Zm.x), 0.5f * (Zk.y + Zm.y));
            float2 O = make_float2(D.y, -D.x);
            float2 p = cmul(stw[k], O);
            g_F[base + (size_t)k * ws] = make_float2(E.x + p.x, E.y + p.y);
            float2 Ec = make_float2(E.x, -E.y);
            float2 Oc = make_float2(O.x, -O.y);
            float2 qv = cmul(stw[64 - k], Oc);
            g_F[base + (size_t)(64 - k) * ws] = make_float2(Ec.x + qv.x, Ec.y + qv.y);
        }
    }
}

// ---------------------------------------------------------------------------
// Pass 2/4: complex FFT length 128 along H, tile [128 h][64 c].
// ---------------------------------------------------------------------------
template <bool INV, bool SCALE>
__global__ __launch_bounds__(512, 2) void k_fft_h() {
    extern __shared__ float2 sm2[];
    float2* sz = sm2;               // [128][64]
    float2* stw = sm2 + 128 * 64;   // [65]
    const int t = threadIdx.x;
    if (t < 65) stw[t] = g_tw[t];
    const int cl = t & 63, oct = t >> 6;
    const int b = blockIdx.z, wf = blockIdx.y;
    const int c = blockIdx.x * 64 + cl;
    size_t base = ((size_t)(b * WF + wf) * HH) * CC + c;

#pragma unroll
    for (int hh = 0; hh < 16; hh++) {
        int h = oct * 16 + hh;
        sz[(__brev((unsigned)h) >> 25) * 64 + cl] = g_F[base + (size_t)h * CC];
    }
    __syncthreads();

    for (int s = 0; s < 7; s++) {
        int half = 1 << s;
#pragma unroll
        for (int jj = 0; jj < 8; jj++) {
            int j = oct * 8 + jj;
            int k = j & (half - 1);
            int i0 = ((j >> s) << (s + 1)) + k;
            float2 w = stw[k << (6 - s)];
            if (INV) w.y = -w.y;
            float2 a = sz[i0 * 64 + cl];
            float2 bb = sz[(i0 + half) * 64 + cl];
            float2 bw = cmul(bb, w);
            sz[i0 * 64 + cl] = make_float2(a.x + bw.x, a.y + bw.y);
            sz[(i0 + half) * 64 + cl] = make_float2(a.x - bw.x, a.y - bw.y);
        }
        __syncthreads();
    }

#pragma unroll
    for (int hh = 0; hh < 16; hh++) {
        int h = oct * 16 + hh;
        float2 v = sz[h * 64 + cl];
        if (SCALE) { v.x *= (1.f / 128.f); v.y *= (1.f / 128.f); }
        g_F[base + (size_t)h * CC] = v;
    }
}

// ---------------------------------------------------------------------------
// Pass 3: block-diagonal complex MLP via tf32 mma.sync, 512 threads/16 warps.
// warp = mrow(0..3) x ngrp(0..3); each warp: 16 rows x 48 cols (6 n-tiles).
// Column half nh = ngrp>>1 (0: real outputs, 1: imag outputs).
// Pre-negated Wi copy kills per-mma XORs.
// smem (words): sA[64][196] | sWr[96][104] | sWi[96][104] | sWiN[96][104] |
//               sO[64][196]
// ---------------------------------------------------------------------------
__global__ __launch_bounds__(512, 1) void k_mlp(const float* __restrict__ w1,
                                                const float* __restrict__ b1,
                                                const float* __restrict__ w2,
                                                const float* __restrict__ b2) {
    extern __shared__ unsigned sm_u[];
    unsigned* sA = sm_u;                     // [64][196]
    unsigned* sWr = sm_u + 64 * 196;         // [96][104]
    unsigned* sWi = sWr + 96 * 104;          // [96][104]
    unsigned* sWiN = sWi + 96 * 104;         // [96][104] = -Wi
    unsigned* sO = sWiN + 96 * 104;          // [64][196]
    float* sAf = (float*)sA;

    const int tid = threadIdx.x;
    const int lane = tid & 31, warp = tid >> 5;
    const int mrow = warp & 3, ngrp = warp >> 2;
    const int nh = ngrp >> 1;                // column half (0 real / 1 imag)
    const int jbase = (ngrp & 1) * 6;        // first n-tile within the half
    const int g = lane >> 2, tig = lane & 3;
    const int n = blockIdx.y;
    const int pt0 = blockIdx.x * 64;
    const int arow = mrow * 16 + g;

    // Stage X: A[p][i] = xr(i), A[p][96+i] = xi(i)
    for (int idx = tid; idx < 64 * 96; idx += 512) {
        int p = idx / 96, i = idx - p * 96;
        float2 v = g_F[(size_t)(pt0 + p) * CC + n * BS + i];
        sA[p * 196 + i] = f2tf(v.x);
        sA[p * 196 + 96 + i] = f2tf(v.y);
    }
    // Stage W1 (tf32): Wr, Wi, -Wi
    {
        const float* wr = w1 + n * BS * BS;
        const float* wi = w1 + NB * BS * BS + n * BS * BS;
        for (int idx = tid; idx < 9216; idx += 512) {
            int r = idx / 96, ci = idx - r * 96;
            sWr[r * 104 + ci] = f2tf(wr[idx]);
            unsigned wiv = f2tf(wi[idx]);
            sWi[r * 104 + ci] = wiv;
            sWiN[r * 104 + ci] = wiv ^ 0x80000000u;
        }
    }
    __syncthreads();

    float acc[6][4];

    // ================= layer 1 =================
    {
        const float* bptr = (nh == 0) ? (b1 + n * BS) : (b1 + NB * BS + n * BS);
#pragma unroll
        for (int j = 0; j < 6; j++) {
            int cih = (jbase + j) * 8 + 2 * tig;
            float bv0 = bptr[cih], bv1 = bptr[cih + 1];
            acc[j][0] = bv0; acc[j][1] = bv1;
            acc[j][2] = bv0; acc[j][3] = bv1;
        }
        const unsigned* Blo = (nh == 0) ? sWr : sWi;   // kc < 12
        const unsigned* Bhi = (nh == 0) ? sWiN : sWr;  // kc >= 12
#pragma unroll 1
        for (int kc = 0; kc < 24; kc++) {
            const unsigned* Ain = sA + kc * 8;
            unsigned a0 = Ain[arow * 196 + tig];
            unsigned a1 = Ain[(arow + 8) * 196 + tig];
            unsigned a2 = Ain[arow * 196 + tig + 4];
            unsigned a3 = Ain[(arow + 8) * 196 + tig + 4];
            const unsigned* Bsrc = (kc < 12) ? (Blo + kc * 8 * 104)
                                             : (Bhi + (kc - 12) * 8 * 104);
            const unsigned* Bt = Bsrc + tig * 104 + jbase * 8 + g;
#pragma unroll
            for (int j = 0; j < 6; j++) {
                unsigned b0 = Bt[j * 8];
                unsigned b1v = Bt[4 * 104 + j * 8];
                mma8(acc[j], a0, a1, a2, a3, b0, b1v);
            }
        }
        // ReLU -> sO (tf32)
#pragma unroll
        for (int j = 0; j < 6; j++) {
            int colg = nh * 96 + (jbase + j) * 8 + 2 * tig;
            uint2 v0 = make_uint2(f2tf(fmaxf(acc[j][0], 0.f)),
                                  f2tf(fmaxf(acc[j][1], 0.f)));
            uint2 v1 = make_uint2(f2tf(fmaxf(acc[j][2], 0.f)),
                                  f2tf(fmaxf(acc[j][3], 0.f)));
            *(uint2*)(sO + arow * 196 + colg) = v0;
            *(uint2*)(sO + (arow + 8) * 196 + colg) = v1;
        }
    }
    __syncthreads();
    // Stage W2 over W1
    {
        const float* wr = w2 + n * BS * BS;
        const float* wi = w2 + NB * BS * BS + n * BS * BS;
        for (int idx = tid; idx < 9216; idx += 512) {
            int r = idx / 96, ci = idx - r * 96;
            sWr[r * 104 + ci] = f2tf(wr[idx]);
            unsigned wiv = f2tf(wi[idx]);
            sWi[r * 104 + ci] = wiv;
            sWiN[r * 104 + ci] = wiv ^ 0x80000000u;
        }
    }
    __syncthreads();

    // ================= layer 2 =================
    {
        const float* bptr = (nh == 0) ? (b2 + n * BS) : (b2 + NB * BS + n * BS);
#pragma unroll
        for (int j = 0; j < 6; j++) {
            int cih = (jbase + j) * 8 + 2 * tig;
            float bv0 = bptr[cih], bv1 = bptr[cih + 1];
            acc[j][0] = bv0; acc[j][1] = bv1;
            acc[j][2] = bv0; acc[j][3] = bv1;
        }
        const unsigned* Blo = (nh == 0) ? sWr : sWi;
        const unsigned* Bhi = (nh == 0) ? sWiN : sWr;
#pragma unroll 1
        for (int kc = 0; kc < 24; kc++) {
            const unsigned* Ain = sO + kc * 8;
            unsigned a0 = Ain[arow * 196 + tig];
            unsigned a1 = Ain[(arow + 8) * 196 + tig];
            unsigned a2 = Ain[arow * 196 + tig + 4];
            unsigned a3 = Ain[(arow + 8) * 196 + tig + 4];
            const unsigned* Bsrc = (kc < 12) ? (Blo + kc * 8 * 104)
                                             : (Bhi + (kc - 12) * 8 * 104);
            const unsigned* Bt = Bsrc + tig * 104 + jbase * 8 + g;
#pragma unroll
            for (int j = 0; j < 6; j++) {
                unsigned b0 = Bt[j * 8];
                unsigned b1v = Bt[4 * 104 + j * 8];
                mma8(acc[j], a0, a1, a2, a3, b0, b1v);
            }
        }
        // softshrink + stage interleaved complex into sA (as floats)
#pragma unroll
        for (int j = 0; j < 6; j++) {
            int jl = (jbase + j) * 8 + 2 * tig;  // channel within block
            float v00 = sshrink(acc[j][0]), v01 = sshrink(acc[j][1]);
            float v10 = sshrink(acc[j][2]), v11 = sshrink(acc[j][3]);
            sAf[arow * 196 + 2 * jl + nh] = v00;
            sAf[arow * 196 + 2 * (jl + 1) + nh] = v01;
            sAf[(arow + 8) * 196 + 2 * jl + nh] = v10;
            sAf[(arow + 8) * 196 + 2 * (jl + 1) + nh] = v11;
        }
    }
    __syncthreads();

    // Coalesced write-back
    for (int idx = tid; idx < 64 * 96; idx += 512) {
        int p = idx / 96, i = idx - p * 96;
        float2 v = make_float2(sAf[p * 196 + 2 * i], sAf[p * 196 + 2 * i + 1]);
        g_F[(size_t)(pt0 + p) * CC + n * BS + i] = v;
    }
}

// ---------------------------------------------------------------------------
// Pass 5: inverse real FFT length 128 along W + 1/128 scale + residual add.
// C2R semantics: imag of DC & Nyquist ignored.
// ---------------------------------------------------------------------------
__global__ __launch_bounds__(512, 2) void k_inv_w(const float* __restrict__ x,
                                                  float* __restrict__ out) {
    extern __shared__ float2 sm2[];
    float2* sz = sm2;               // [64][128]
    float2* stw = sm2 + 64 * 128;   // [65]
    const int t = threadIdx.x;
    if (t < 65) stw[t] = g_tw[t];
    __syncthreads();
    const int cl = t & 127, q = t >> 7;
    const int b = blockIdx.z, h = blockIdx.y;
    const int c = blockIdx.x * 128 + cl;
    size_t base = ((size_t)b * WF * HH + h) * CC + c;
    const size_t ws = (size_t)HH * CC;

#pragma unroll
    for (int jj = 0; jj < 8; jj++) {
        int idx = q * 8 + jj;
        if (idx == 0) {
            float2 X0 = g_F[base];
            float2 X64 = g_F[base + 64 * ws];
            sz[cl] = make_float2(X0.x + X64.x, X0.x - X64.x);  // imag dropped
            float2 X32 = g_F[base + 32 * ws];
            sz[1 * 128 + cl] = make_float2(2.f * X32.x, -2.f * X32.y);
        } else {
            int k = idx;  // 1..31
            float2 Xk = g_F[base + (size_t)k * ws];
            float2 Xm = g_F[base + (size_t)(64 - k) * ws];
            float2 A = make_float2(Xk.x + Xm.x, Xk.y - Xm.y);
            float2 D = make_float2(Xk.x - Xm.x, Xk.y + Xm.y);
            float2 wc = make_float2(stw[k].x, -stw[k].y);
            float2 tv = cmul(wc, D);
            sz[(__brev((unsigned)k) >> 26) * 128 + cl] =
                make_float2(A.x - tv.y, A.y + tv.x);
            float2 A2 = make_float2(Xm.x + Xk.x, Xm.y - Xk.y);
            float2 D2 = make_float2(Xm.x - Xk.x, Xm.y + Xk.y);
            float2 wc2 = make_float2(stw[64 - k].x, -stw[64 - k].y);
            float2 t2 = cmul(wc2, D2);
            sz[(__brev((unsigned)(64 - k)) >> 26) * 128 + cl] =
                make_float2(A2.x - t2.y, A2.y + t2.x);
        }
    }
    __syncthreads();

    for (int s = 0; s < 6; s++) {
        int half = 1 << s;
#pragma unroll
        for (int jj = 0; jj < 8; jj++) {
            int j = q * 8 + jj;
            int k = j & (half - 1);
            int i0 = ((j >> s) << (s + 1)) + k;
            float2 w = stw[k << (6 - s)];
            w.y = -w.y;
            float2 a = sz[i0 * 128 + cl];
            float2 bb = sz[(i0 + half) * 128 + cl];
            float2 bw = cmul(bb, w);
            sz[i0 * 128 + cl] = make_float2(a.x + bw.x, a.y + bw.y);
            sz[(i0 + half) * 128 + cl] = make_float2(a.x - bw.x, a.y - bw.y);
        }
        __syncthreads();
    }

    const size_t xbase = ((size_t)(b * HH + h) * WW) * CC + c;
#pragma unroll
    for (int mm = 0; mm < 16; mm++) {
        int m = q * 16 + mm;
        float2 z = sz[m * 128 + cl];
        size_t i0 = xbase + (size_t)(2 * m) * CC;
        size_t i1 = xbase + (size_t)(2 * m + 1) * CC;
        out[i0] = z.x * (1.f / 128.f) + x[i0];
        out[i1] = z.y * (1.f / 128.f) + x[i1];
    }
}

// ---------------------------------------------------------------------------
extern "C" void kernel_launch(void* const* d_in, const int* in_sizes, int n_in,
                              void* d_out, int out_size) {
    const float* x  = (const float*)d_in[0];
    const float* w1 = (const float*)d_in[1];
    const float* b1 = (const float*)d_in[2];
    const float* w2 = (const float*)d_in[3];
    const float* b2 = (const float*)d_in[4];
    float* out = (float*)d_out;

    const size_t sm_fftw = (size_t)(64 * 128 + 65) * sizeof(float2);   // 66056
    const size_t sm_ffth = (size_t)(128 * 64 + 65) * sizeof(float2);   // 66056
    const size_t sm_mlp  = (size_t)(64 * 196 * 2 + 96 * 104 * 3) * 4;  // 220160

    cudaFuncSetAttribute(k_fwd_w, cudaFuncAttributeMaxDynamicSharedMemorySize, (int)sm_fftw);
    cudaFuncSetAttribute(k_fft_h<false, true>, cudaFuncAttributeMaxDynamicSharedMemorySize, (int)sm_ffth);
    cudaFuncSetAttribute(k_fft_h<true, false>, cudaFuncAttributeMaxDynamicSharedMemorySize, (int)sm_ffth);
    cudaFuncSetAttribute(k_mlp, cudaFuncAttributeMaxDynamicSharedMemorySize, (int)sm_mlp);
    cudaFuncSetAttribute(k_inv_w, cudaFuncAttributeMaxDynamicSharedMemorySize, (int)sm_fftw);

    k_init_tw<<<1, 128>>>();
    k_fwd_w<<<dim3(6, 128, 8), 512, sm_fftw>>>(x);
    k_fft_h<false, true><<<dim3(12, 65, 8), 512, sm_ffth>>>();
    k_mlp<<<dim3(1040, 8), 512, sm_mlp>>>(w1, b1, w2, b2);
    k_fft_h<true, false><<<dim3(12, 65, 8), 512, sm_ffth>>>();
    k_inv_w<<<dim3(6, 128, 8), 512, sm_fftw>>>(x, out);
}

// round 5
// speedup vs baseline: 2.3324x; 1.2666x over previous
#include <cuda_runtime.h>
#include <math.h>

#define BB 8
#define HH 128
#define WW 128
#define CC 768
#define NB 8
#define BS 96
#define WF 65
#define LAMBDA 0.01f

// Frequency-domain scratch: [b][wf][h][c], complex
__device__ float2 g_F[(size_t)BB * WF * HH * CC];
// Twiddles: g_tw[k] = exp(-2*pi*i*k/128), k=0..64
__device__ float2 g_tw[65];

__device__ __forceinline__ float2 cmul(float2 a, float2 b) {
    return make_float2(a.x * b.x - a.y * b.y, a.x * b.y + a.y * b.x);
}

__device__ __forceinline__ unsigned f2tf(float f) {
    unsigned u;
    asm("cvt.rna.tf32.f32 %0, %1;" : "=r"(u) : "f"(f));
    return u;
}

__device__ __forceinline__ void mma8(float c[4], unsigned a0, unsigned a1,
                                     unsigned a2, unsigned a3,
                                     unsigned b0, unsigned b1) {
    asm volatile(
        "mma.sync.aligned.m16n8k8.row.col.f32.tf32.tf32.f32 "
        "{%0,%1,%2,%3}, {%4,%5,%6,%7}, {%8,%9}, {%0,%1,%2,%3};"
        : "+f"(c[0]), "+f"(c[1]), "+f"(c[2]), "+f"(c[3])
        : "r"(a0), "r"(a1), "r"(a2), "r"(a3), "r"(b0), "r"(b1));
}

__device__ __forceinline__ float sshrink(float v) {
    return v > LAMBDA ? v - LAMBDA : (v < -LAMBDA ? v + LAMBDA : 0.f);
}

__global__ void k_init_tw() {
    int i = threadIdx.x;
    if (i < 65) {
        double a = -2.0 * 3.14159265358979323846264338327950288 * (double)i / 128.0;
        g_tw[i] = make_float2((float)cos(a), (float)sin(a));
    }
}

// ---------------------------------------------------------------------------
// Pass 1: real FFT length 128 along W (pack-in-pairs trick). Unchanged.
// ---------------------------------------------------------------------------
__global__ __launch_bounds__(512, 2) void k_fwd_w(const float* __restrict__ x) {
    extern __shared__ float2 sm2[];
    float2* sz = sm2;               // [64][128]
    float2* stw = sm2 + 64 * 128;   // [65]
    const int t = threadIdx.x;
    if (t < 65) stw[t] = g_tw[t];
    const int cl = t & 127, q = t >> 7;
    const int b = blockIdx.z, h = blockIdx.y;
    const int c = blockIdx.x * 128 + cl;
    const float* xp = x + ((size_t)(b * HH + h) * WW) * CC + c;

#pragma unroll
    for (int mm = 0; mm < 16; mm++) {
        int m = q * 16 + mm;
        float re = xp[(size_t)(2 * m) * CC];
        float im = xp[(size_t)(2 * m + 1) * CC];
        sz[(__brev((unsigned)m) >> 26) * 128 + cl] = make_float2(re, im);
    }
    __syncthreads();

    for (int s = 0; s < 6; s++) {
        int half = 1 << s;
#pragma unroll
        for (int jj = 0; jj < 8; jj++) {
            int j = q * 8 + jj;
            int k = j & (half - 1);
            int i0 = ((j >> s) << (s + 1)) + k;
            float2 w = stw[k << (6 - s)];
            float2 a = sz[i0 * 128 + cl];
            float2 bb = sz[(i0 + half) * 128 + cl];
            float2 bw = cmul(bb, w);
            sz[i0 * 128 + cl] = make_float2(a.x + bw.x, a.y + bw.y);
            sz[(i0 + half) * 128 + cl] = make_float2(a.x - bw.x, a.y - bw.y);
        }
        __syncthreads();
    }

    size_t base = ((size_t)b * WF * HH + h) * CC + c;
    const size_t ws = (size_t)HH * CC;
#pragma unroll
    for (int jj = 0; jj < 8; jj++) {
        int idx = q * 8 + jj;
        if (idx == 0) {
            float2 Z0 = sz[cl];
            g_F[base] = make_float2(Z0.x + Z0.y, 0.f);
            g_F[base + 64 * ws] = make_float2(Z0.x - Z0.y, 0.f);
            float2 Z32 = sz[32 * 128 + cl];
            g_F[base + 32 * ws] = make_float2(Z32.x, -Z32.y);
        } else {
            int k = idx;  // 1..31
            float2 Zk = sz[k * 128 + cl];
            float2 Zm = sz[(64 - k) * 128 + cl];
            float2 E = make_float2(0.5f * (Zk.x + Zm.x), 0.5f * (Zk.y - Zm.y));
            float2 D = make_float2(0.5f * (Zk.x - Zm.x), 0.5f * (Zk.y + Zm.y));
            float2 O = make_float2(D.y, -D.x);
            float2 p = cmul(stw[k], O);
            g_F[base + (size_t)k * ws] = make_float2(E.x + p.x, E.y + p.y);
            float2 Ec = make_float2(E.x, -E.y);
            float2 Oc = make_float2(O.x, -O.y);
            float2 qv = cmul(stw[64 - k], Oc);
            g_F[base + (size_t)(64 - k) * ws] = make_float2(Ec.x + qv.x, Ec.y + qv.y);
        }
    }
}

// ---------------------------------------------------------------------------
// Fused pass: FFT-H forward + complex MLP (tf32 mma) + FFT-H inverse.
// One CTA per (n, wf, b). Tile = [128 h][96 c] complex of one channel block.
// Buffer reuse: sBIG holds (in time) the float2 FFT tile -> tf32 A matrix
// [128][196] -> tf32 O matrix -> float2 result tile (bit-reversed rows).
// Weights: sWr/sWi [96][104] tf32, staged per layer; sign flip by XOR at use.
// MLP warp tile: m32 x n48 (16 warps = 4 mgrp x 4 ngrp) -> 1.67 LDS/mma.
// Ortho 1/128 (fwd) folded into tf32 conversion; inverse 1/128 in pass 5.
// ---------------------------------------------------------------------------
__global__ __launch_bounds__(512, 1) void k_fused(const float* __restrict__ w1,
                                                  const float* __restrict__ b1,
                                                  const float* __restrict__ w2,
                                                  const float* __restrict__ b2) {
    extern __shared__ unsigned smu[];
    unsigned* sBIG = smu;                       // [128][196] words
    unsigned* sWr = smu + 128 * 196;            // [96][104]
    unsigned* sWi = sWr + 96 * 104;             // [96][104]
    float2* stw = (float2*)(sWi + 96 * 104);    // [65]
    float2* tz = (float2*)sBIG;                 // tile view, row stride 98

    const int t = threadIdx.x;
    const int lane = t & 31, warp = t >> 5;
    if (t < 65) stw[t] = g_tw[t];
    const int n = blockIdx.x, wf = blockIdx.y, b = blockIdx.z;
    const size_t base = ((size_t)(b * WF + wf) * HH) * CC + n * BS;

    // Load tile (bit-reversed rows for DIT)
    for (int i = t; i < 128 * 96; i += 512) {
        int h = i / 96, col = i - h * 96;
        tz[(__brev((unsigned)h) >> 25) * 98 + col] = g_F[base + (size_t)h * CC + col];
    }
    // Stage W1
    {
        const float* wr = w1 + n * BS * BS;
        const float* wi = w1 + NB * BS * BS + n * BS * BS;
        for (int idx = t; idx < 9216; idx += 512) {
            int r = idx / 96, ci = idx - r * 96;
            sWr[r * 104 + ci] = f2tf(wr[idx]);
            sWi[r * 104 + ci] = f2tf(wi[idx]);
        }
    }
    __syncthreads();

    // Butterfly (j, col) mapping is stage-independent: precompute.
    int colv[12], jv[12];
#pragma unroll
    for (int r = 0; r < 12; r++) {
        int idx = r * 512 + t;
        jv[r] = idx / 96;
        colv[r] = idx - jv[r] * 96;
    }

    // ---------------- forward FFT over h ----------------
    for (int s = 0; s < 7; s++) {
        int half = 1 << s;
#pragma unroll
        for (int r = 0; r < 12; r++) {
            int j = jv[r], col = colv[r];
            int k = j & (half - 1);
            int i0 = ((j >> s) << (s + 1)) + k;
            float2 w = stw[k << (6 - s)];
            float2 a = tz[i0 * 98 + col];
            float2 bb = tz[(i0 + half) * 98 + col];
            float2 bw = cmul(bb, w);
            tz[i0 * 98 + col] = make_float2(a.x + bw.x, a.y + bw.y);
            tz[(i0 + half) * 98 + col] = make_float2(a.x - bw.x, a.y - bw.y);
        }
        __syncthreads();
    }

    // ---------------- deinterleave tile -> A tf32 (x 1/128), in place ------
    {
#pragma unroll
        for (int rr = 0; rr < 8; rr++) {
            int row = warp * 8 + rr;
            float2 v0 = tz[row * 98 + lane];
            float2 v1 = tz[row * 98 + lane + 32];
            float2 v2 = tz[row * 98 + lane + 64];
            __syncwarp();
            unsigned* Ar = sBIG + row * 196;
            Ar[lane]       = f2tf(v0.x * 0.0078125f);
            Ar[lane + 96]  = f2tf(v0.y * 0.0078125f);
            Ar[lane + 32]  = f2tf(v1.x * 0.0078125f);
            Ar[lane + 128] = f2tf(v1.y * 0.0078125f);
            Ar[lane + 64]  = f2tf(v2.x * 0.0078125f);
            Ar[lane + 160] = f2tf(v2.y * 0.0078125f);
            __syncwarp();
        }
    }
    __syncthreads();

    // ---------------- MLP ----------------
    const int mgrp = warp & 3, ngrp = warp >> 2;
    const int nh = ngrp >> 1;             // 0: real outputs, 1: imag outputs
    const int jbase = (ngrp & 1) * 6;     // first n-tile within the half
    const int g = lane >> 2, tig = lane & 3;
    const int arow = mgrp * 32 + g;

    float acc[2][6][4];

    // ===== layer 1 =====
    {
        const float* bp = (nh == 0) ? (b1 + n * BS) : (b1 + NB * BS + n * BS);
#pragma unroll
        for (int j = 0; j < 6; j++) {
            int cih = (jbase + j) * 8 + 2 * tig;
            float bv0 = bp[cih], bv1 = bp[cih + 1];
#pragma unroll
            for (int mt = 0; mt < 2; mt++) {
                acc[mt][j][0] = bv0; acc[mt][j][1] = bv1;
                acc[mt][j][2] = bv0; acc[mt][j][3] = bv1;
            }
        }
        const unsigned* Blo = (nh == 0) ? sWr : sWi;
        const unsigned* Bhi = (nh == 0) ? sWi : sWr;
        const unsigned sgnHi = (nh == 0) ? 0x80000000u : 0u;
#pragma unroll 1
        for (int kc = 0; kc < 24; kc++) {
            const unsigned* Ain = sBIG + kc * 8;
            unsigned a0 = Ain[arow * 196 + tig];
            unsigned a1 = Ain[(arow + 8) * 196 + tig];
            unsigned a2 = Ain[arow * 196 + tig + 4];
            unsigned a3 = Ain[(arow + 8) * 196 + tig + 4];
            unsigned a4 = Ain[(arow + 16) * 196 + tig];
            unsigned a5 = Ain[(arow + 24) * 196 + tig];
            unsigned a6 = Ain[(arow + 16) * 196 + tig + 4];
            unsigned a7 = Ain[(arow + 24) * 196 + tig + 4];
            unsigned sgn = (kc < 12) ? 0u : sgnHi;
            const unsigned* Bsrc = (kc < 12) ? (Blo + kc * 8 * 104)
                                             : (Bhi + (kc - 12) * 8 * 104);
            const unsigned* Bt = Bsrc + tig * 104 + jbase * 8 + g;
#pragma unroll
            for (int j = 0; j < 6; j++) {
                unsigned b0 = Bt[j * 8] ^ sgn;
                unsigned b1v = Bt[4 * 104 + j * 8] ^ sgn;
                mma8(acc[0][j], a0, a1, a2, a3, b0, b1v);
                mma8(acc[1][j], a4, a5, a6, a7, b0, b1v);
            }
        }
    }
    __syncthreads();  // all A reads done

    // write relu(O) over A; stage W2 over W1
#pragma unroll
    for (int j = 0; j < 6; j++) {
        int colg = nh * 96 + (jbase + j) * 8 + 2 * tig;
#pragma unroll
        for (int mt = 0; mt < 2; mt++) {
            int r0 = arow + 16 * mt;
            uint2 v0 = make_uint2(f2tf(fmaxf(acc[mt][j][0], 0.f)),
                                  f2tf(fmaxf(acc[mt][j][1], 0.f)));
            uint2 v1 = make_uint2(f2tf(fmaxf(acc[mt][j][2], 0.f)),
                                  f2tf(fmaxf(acc[mt][j][3], 0.f)));
            *(uint2*)(sBIG + r0 * 196 + colg) = v0;
            *(uint2*)(sBIG + (r0 + 8) * 196 + colg) = v1;
        }
    }
    {
        const float* wr = w2 + n * BS * BS;
        const float* wi = w2 + NB * BS * BS + n * BS * BS;
        for (int idx = t; idx < 9216; idx += 512) {
            int r = idx / 96, ci = idx - r * 96;
            sWr[r * 104 + ci] = f2tf(wr[idx]);
            sWi[r * 104 + ci] = f2tf(wi[idx]);
        }
    }
    __syncthreads();

    // ===== layer 2 =====
    {
        const float* bp = (nh == 0) ? (b2 + n * BS) : (b2 + NB * BS + n * BS);
#pragma unroll
        for (int j = 0; j < 6; j++) {
            int cih = (jbase + j) * 8 + 2 * tig;
            float bv0 = bp[cih], bv1 = bp[cih + 1];
#pragma unroll
            for (int mt = 0; mt < 2; mt++) {
                acc[mt][j][0] = bv0; acc[mt][j][1] = bv1;
                acc[mt][j][2] = bv0; acc[mt][j][3] = bv1;
            }
        }
        const unsigned* Blo = (nh == 0) ? sWr : sWi;
        const unsigned* Bhi = (nh == 0) ? sWi : sWr;
        const unsigned sgnHi = (nh == 0) ? 0x80000000u : 0u;
#pragma unroll 1
        for (int kc = 0; kc < 24; kc++) {
            const unsigned* Ain = sBIG + kc * 8;
            unsigned a0 = Ain[arow * 196 + tig];
            unsigned a1 = Ain[(arow + 8) * 196 + tig];
            unsigned a2 = Ain[arow * 196 + tig + 4];
            unsigned a3 = Ain[(arow + 8) * 196 + tig + 4];
            unsigned a4 = Ain[(arow + 16) * 196 + tig];
            unsigned a5 = Ain[(arow + 24) * 196 + tig];
            unsigned a6 = Ain[(arow + 16) * 196 + tig + 4];
            unsigned a7 = Ain[(arow + 24) * 196 + tig + 4];
            unsigned sgn = (kc < 12) ? 0u : sgnHi;
            const unsigned* Bsrc = (kc < 12) ? (Blo + kc * 8 * 104)
                                             : (Bhi + (kc - 12) * 8 * 104);
            const unsigned* Bt = Bsrc + tig * 104 + jbase * 8 + g;
#pragma unroll
            for (int j = 0; j < 6; j++) {
                unsigned b0 = Bt[j * 8] ^ sgn;
                unsigned b1v = Bt[4 * 104 + j * 8] ^ sgn;
                mma8(acc[0][j], a0, a1, a2, a3, b0, b1v);
                mma8(acc[1][j], a4, a5, a6, a7, b0, b1v);
            }
        }
    }
    __syncthreads();  // all O reads done

    // softshrink -> tile (float2 components), rows bit-reversed for iFFT
    {
        float* Tf = (float*)sBIG;
#pragma unroll
        for (int j = 0; j < 6; j++) {
            int ch = (jbase + j) * 8 + 2 * tig;
#pragma unroll
            for (int mt = 0; mt < 2; mt++) {
                int r0 = arow + 16 * mt, r1 = r0 + 8;
                int br0 = __brev((unsigned)r0) >> 25;
                int br1 = __brev((unsigned)r1) >> 25;
                Tf[br0 * 196 + 2 * ch + nh] = sshrink(acc[mt][j][0]);
                Tf[br0 * 196 + 2 * (ch + 1) + nh] = sshrink(acc[mt][j][1]);
                Tf[br1 * 196 + 2 * ch + nh] = sshrink(acc[mt][j][2]);
                Tf[br1 * 196 + 2 * (ch + 1) + nh] = sshrink(acc[mt][j][3]);
            }
        }
    }
    __syncthreads();

    // ---------------- inverse FFT over h (conj twiddles) ----------------
    for (int s = 0; s < 7; s++) {
        int half = 1 << s;
#pragma unroll
        for (int r = 0; r < 12; r++) {
            int j = jv[r], col = colv[r];
            int k = j & (half - 1);
            int i0 = ((j >> s) << (s + 1)) + k;
            float2 w = stw[k << (6 - s)];
            w.y = -w.y;
            float2 a = tz[i0 * 98 + col];
            float2 bb = tz[(i0 + half) * 98 + col];
            float2 bw = cmul(bb, w);
            tz[i0 * 98 + col] = make_float2(a.x + bw.x, a.y + bw.y);
            tz[(i0 + half) * 98 + col] = make_float2(a.x - bw.x, a.y - bw.y);
        }
        __syncthreads();
    }

    // Store back
    for (int i = t; i < 128 * 96; i += 512) {
        int h = i / 96, col = i - h * 96;
        g_F[base + (size_t)h * CC + col] = tz[h * 98 + col];
    }
}

// ---------------------------------------------------------------------------
// Pass 5: inverse real FFT length 128 along W + 1/128 scale + residual add.
// C2R semantics: imag of DC & Nyquist ignored.
// ---------------------------------------------------------------------------
__global__ __launch_bounds__(512, 2) void k_inv_w(const float* __restrict__ x,
                                                  float* __restrict__ out) {
    extern __shared__ float2 sm2[];
    float2* sz = sm2;               // [64][128]
    float2* stw = sm2 + 64 * 128;   // [65]
    const int t = threadIdx.x;
    if (t < 65) stw[t] = g_tw[t];
    __syncthreads();
    const int cl = t & 127, q = t >> 7;
    const int b = blockIdx.z, h = blockIdx.y;
    const int c = blockIdx.x * 128 + cl;
    size_t base = ((size_t)b * WF * HH + h) * CC + c;
    const size_t ws = (size_t)HH * CC;

#pragma unroll
    for (int jj = 0; jj < 8; jj++) {
        int idx = q * 8 + jj;
        if (idx == 0) {
            float2 X0 = g_F[base];
            float2 X64 = g_F[base + 64 * ws];
            sz[cl] = make_float2(X0.x + X64.x, X0.x - X64.x);  // imag dropped
            float2 X32 = g_F[base + 32 * ws];
            sz[1 * 128 + cl] = make_float2(2.f * X32.x, -2.f * X32.y);
        } else {
            int k = idx;  // 1..31
            float2 Xk = g_F[base + (size_t)k * ws];
            float2 Xm = g_F[base + (size_t)(64 - k) * ws];
            float2 A = make_float2(Xk.x + Xm.x, Xk.y - Xm.y);
            float2 D = make_float2(Xk.x - Xm.x, Xk.y + Xm.y);
            float2 wc = make_float2(stw[k].x, -stw[k].y);
            float2 tv = cmul(wc, D);
            sz[(__brev((unsigned)k) >> 26) * 128 + cl] =
                make_float2(A.x - tv.y, A.y + tv.x);
            float2 A2 = make_float2(Xm.x + Xk.x, Xm.y - Xk.y);
            float2 D2 = make_float2(Xm.x - Xk.x, Xm.y + Xk.y);
            float2 wc2 = make_float2(stw[64 - k].x, -stw[64 - k].y);
            float2 t2 = cmul(wc2, D2);
            sz[(__brev((unsigned)(64 - k)) >> 26) * 128 + cl] =
                make_float2(A2.x - t2.y, A2.y + t2.x);
        }
    }
    __syncthreads();

    for (int s = 0; s < 6; s++) {
        int half = 1 << s;
#pragma unroll
        for (int jj = 0; jj < 8; jj++) {
            int j = q * 8 + jj;
            int k = j & (half - 1);
            int i0 = ((j >> s) << (s + 1)) + k;
            float2 w = stw[k << (6 - s)];
            w.y = -w.y;
            float2 a = sz[i0 * 128 + cl];
            float2 bb = sz[(i0 + half) * 128 + cl];
            float2 bw = cmul(bb, w);
            sz[i0 * 128 + cl] = make_float2(a.x + bw.x, a.y + bw.y);
            sz[(i0 + half) * 128 + cl] = make_float2(a.x - bw.x, a.y - bw.y);
        }
        __syncthreads();
    }

    const size_t xbase = ((size_t)(b * HH + h) * WW) * CC + c;
#pragma unroll
    for (int mm = 0; mm < 16; mm++) {
        int m = q * 16 + mm;
        float2 z = sz[m * 128 + cl];
        size_t i0 = xbase + (size_t)(2 * m) * CC;
        size_t i1 = xbase + (size_t)(2 * m + 1) * CC;
        out[i0] = z.x * (1.f / 128.f) + x[i0];
        out[i1] = z.y * (1.f / 128.f) + x[i1];
    }
}

// ---------------------------------------------------------------------------
extern "C" void kernel_launch(void* const* d_in, const int* in_sizes, int n_in,
                              void* d_out, int out_size) {
    const float* x  = (const float*)d_in[0];
    const float* w1 = (const float*)d_in[1];
    const float* b1 = (const float*)d_in[2];
    const float* w2 = (const float*)d_in[3];
    const float* b2 = (const float*)d_in[4];
    float* out = (float*)d_out;

    const size_t sm_fftw = (size_t)(64 * 128 + 65) * sizeof(float2);   // 66056
    const size_t sm_fus  = (size_t)(128 * 196 + 2 * 96 * 104) * 4 + 65 * 8; // 180744

    cudaFuncSetAttribute(k_fwd_w, cudaFuncAttributeMaxDynamicSharedMemorySize, (int)sm_fftw);
    cudaFuncSetAttribute(k_fused, cudaFuncAttributeMaxDynamicSharedMemorySize, (int)sm_fus);
    cudaFuncSetAttribute(k_inv_w, cudaFuncAttributeMaxDynamicSharedMemorySize, (int)sm_fftw);

    k_init_tw<<<1, 128>>>();
    k_fwd_w<<<dim3(6, 128, 8), 512, sm_fftw>>>(x);
    k_fused<<<dim3(8, 65, 8), 512, sm_fus>>>(w1, b1, w2, b2);
    k_inv_w<<<dim3(6, 128, 8), 512, sm_fftw>>>(x, out);
}

// round 6
// speedup vs baseline: 2.6207x; 1.1236x over previous
#include <cuda_runtime.h>
#include <math.h>

#define BB 8
#define HH 128
#define WW 128
#define CC 768
#define NB 8
#define BS 96
#define WF 65
#define LAMBDA 0.01f

// Frequency-domain scratch: [b][wf][h][c], complex
__device__ float2 g_F[(size_t)BB * WF * HH * CC];
// Twiddles: g_tw[k] = exp(-2*pi*i*k/128), k=0..64
__device__ float2 g_tw[65];

__device__ __forceinline__ float2 cmul(float2 a, float2 b) {
    return make_float2(a.x * b.x - a.y * b.y, a.x * b.y + a.y * b.x);
}

__device__ __forceinline__ unsigned f2tf(float f) {
    unsigned u;
    asm("cvt.rna.tf32.f32 %0, %1;" : "=r"(u) : "f"(f));
    return u;
}

__device__ __forceinline__ void mma8(float c[4], unsigned a0, unsigned a1,
                                     unsigned a2, unsigned a3,
                                     unsigned b0, unsigned b1) {
    asm volatile(
        "mma.sync.aligned.m16n8k8.row.col.f32.tf32.tf32.f32 "
        "{%0,%1,%2,%3}, {%4,%5,%6,%7}, {%8,%9}, {%0,%1,%2,%3};"
        : "+f"(c[0]), "+f"(c[1]), "+f"(c[2]), "+f"(c[3])
        : "r"(a0), "r"(a1), "r"(a2), "r"(a3), "r"(b0), "r"(b1));
}

__device__ __forceinline__ float sshrink(float v) {
    return v > LAMBDA ? v - LAMBDA : (v < -LAMBDA ? v + LAMBDA : 0.f);
}

__global__ void k_init_tw() {
    int i = threadIdx.x;
    if (i < 65) {
        double a = -2.0 * 3.14159265358979323846264338327950288 * (double)i / 128.0;
        g_tw[i] = make_float2((float)cos(a), (float)sin(a));
    }
}

// Radix-2^2: two DIT radix-2 stages (s, s+1) fused in registers.
// x0..x3 at i0, i0+h, i0+2h, i0+3h; w1 = tw(stage s), w2/w3 = tw(stage s+1).
__device__ __forceinline__ void bf4(float2& x0, float2& x1, float2& x2,
                                    float2& x3, float2 w1, float2 w2,
                                    float2 w3) {
    float2 t1 = cmul(x1, w1), t3 = cmul(x3, w1);
    float2 y0 = make_float2(x0.x + t1.x, x0.y + t1.y);
    float2 y1 = make_float2(x0.x - t1.x, x0.y - t1.y);
    float2 y2 = make_float2(x2.x + t3.x, x2.y + t3.y);
    float2 y3 = make_float2(x2.x - t3.x, x2.y - t3.y);
    float2 u2 = cmul(y2, w2), u3 = cmul(y3, w3);
    x0 = make_float2(y0.x + u2.x, y0.y + u2.y);
    x2 = make_float2(y0.x - u2.x, y0.y - u2.y);
    x1 = make_float2(y1.x + u3.x, y1.y + u3.y);
    x3 = make_float2(y1.x - u3.x, y1.y - u3.y);
}

// ---------------------------------------------------------------------------
// Pass 1: real FFT length 128 along W (pack-in-pairs). 64-pt FFT with 3
// radix-2^2 passes. Tile [64][128 c], 512 thr: cl = t&127, q = t>>7.
// ---------------------------------------------------------------------------
__global__ __launch_bounds__(512, 2) void k_fwd_w(const float* __restrict__ x) {
    extern __shared__ float2 sm2[];
    float2* sz = sm2;               // [64][128]
    float2* stw = sm2 + 64 * 128;   // [65]
    const int t = threadIdx.x;
    if (t < 65) stw[t] = g_tw[t];
    const int cl = t & 127, q = t >> 7;
    const int b = blockIdx.z, h = blockIdx.y;
    const int c = blockIdx.x * 128 + cl;
    const float* xp = x + ((size_t)(b * HH + h) * WW) * CC + c;

#pragma unroll
    for (int mm = 0; mm < 16; mm++) {
        int m = q * 16 + mm;
        float re = xp[(size_t)(2 * m) * CC];
        float im = xp[(size_t)(2 * m + 1) * CC];
        sz[(__brev((unsigned)m) >> 26) * 128 + cl] = make_float2(re, im);
    }
    __syncthreads();

#pragma unroll
    for (int s = 0; s < 6; s += 2) {
        int hf = 1 << s;
#pragma unroll
        for (int r = 0; r < 4; r++) {
            int j = q * 4 + r;
            int k = j & (hf - 1);
            int i0 = ((j >> s) << (s + 2)) + k;
            float2 w1 = stw[k << (6 - s)];
            float2 w2 = stw[k << (5 - s)];
            float2 w3 = stw[(k + hf) << (5 - s)];
            float2 x0 = sz[i0 * 128 + cl];
            float2 x1 = sz[(i0 + hf) * 128 + cl];
            float2 x2 = sz[(i0 + 2 * hf) * 128 + cl];
            float2 x3 = sz[(i0 + 3 * hf) * 128 + cl];
            bf4(x0, x1, x2, x3, w1, w2, w3);
            sz[i0 * 128 + cl] = x0;
            sz[(i0 + hf) * 128 + cl] = x1;
            sz[(i0 + 2 * hf) * 128 + cl] = x2;
            sz[(i0 + 3 * hf) * 128 + cl] = x3;
        }
        __syncthreads();
    }

    size_t base = ((size_t)b * WF * HH + h) * CC + c;
    const size_t ws = (size_t)HH * CC;
#pragma unroll
    for (int jj = 0; jj < 8; jj++) {
        int idx = q * 8 + jj;
        if (idx == 0) {
            float2 Z0 = sz[cl];
            g_F[base] = make_float2(Z0.x + Z0.y, 0.f);
            g_F[base + 64 * ws] = make_float2(Z0.x - Z0.y, 0.f);
            float2 Z32 = sz[32 * 128 + cl];
            g_F[base + 32 * ws] = make_float2(Z32.x, -Z32.y);
        } else {
            int k = idx;  // 1..31
            float2 Zk = sz[k * 128 + cl];
            float2 Zm = sz[(64 - k) * 128 + cl];
            float2 E = make_float2(0.5f * (Zk.x + Zm.x), 0.5f * (Zk.y - Zm.y));
            float2 D = make_float2(0.5f * (Zk.x - Zm.x), 0.5f * (Zk.y + Zm.y));
            float2 O = make_float2(D.y, -D.x);
            float2 p = cmul(stw[k], O);
            g_F[base + (size_t)k * ws] = make_float2(E.x + p.x, E.y + p.y);
            float2 Ec = make_float2(E.x, -E.y);
            float2 Oc = make_float2(O.x, -O.y);
            float2 qv = cmul(stw[64 - k], Oc);
            g_F[base + (size_t)(64 - k) * ws] = make_float2(Ec.x + qv.x, Ec.y + qv.y);
        }
    }
}

// ---------------------------------------------------------------------------
// Fused pass: FFT-H fwd + complex MLP (tf32 mma) + FFT-H inv.
// 128-pt FFTs use 3 radix-2^2 passes + 1 radix-2 pass each direction.
// ---------------------------------------------------------------------------
__global__ __launch_bounds__(512, 1) void k_fused(const float* __restrict__ w1,
                                                  const float* __restrict__ b1,
                                                  const float* __restrict__ w2,
                                                  const float* __restrict__ b2) {
    extern __shared__ unsigned smu[];
    unsigned* sBIG = smu;                       // [128][196] words
    unsigned* sWr = smu + 128 * 196;            // [96][104]
    unsigned* sWi = sWr + 96 * 104;             // [96][104]
    float2* stw = (float2*)(sWi + 96 * 104);    // [65]
    float2* tz = (float2*)sBIG;                 // tile view, row stride 98

    const int t = threadIdx.x;
    const int lane = t & 31, warp = t >> 5;
    if (t < 65) stw[t] = g_tw[t];
    const int n = blockIdx.x, wf = blockIdx.y, b = blockIdx.z;
    const size_t base = ((size_t)(b * WF + wf) * HH) * CC + n * BS;

    // Load tile (bit-reversed rows for DIT)
    for (int i = t; i < 128 * 96; i += 512) {
        int h = i / 96, col = i - h * 96;
        tz[(__brev((unsigned)h) >> 25) * 98 + col] = g_F[base + (size_t)h * CC + col];
    }
    // Stage W1
    {
        const float* wr = w1 + n * BS * BS;
        const float* wi = w1 + NB * BS * BS + n * BS * BS;
        for (int idx = t; idx < 9216; idx += 512) {
            int r = idx / 96, ci = idx - r * 96;
            sWr[r * 104 + ci] = f2tf(wr[idx]);
            sWi[r * 104 + ci] = f2tf(wi[idx]);
        }
    }
    __syncthreads();

    // Group maps (stage-independent):
    // radix-2^2 passes: 32 groups x 96 cols = 3072 -> 6/thread
    int j4v[6], c4v[6];
#pragma unroll
    for (int r = 0; r < 6; r++) {
        int idx = r * 512 + t;
        j4v[r] = idx / 96;
        c4v[r] = idx - j4v[r] * 96;
    }
    // final radix-2 stage: 64 butterflies x 96 cols = 6144 -> 12/thread
    int jv[12], colv[12];
#pragma unroll
    for (int r = 0; r < 12; r++) {
        int idx = r * 512 + t;
        jv[r] = idx / 96;
        colv[r] = idx - jv[r] * 96;
    }

    // ---------------- forward FFT over h ----------------
#pragma unroll
    for (int s = 0; s < 6; s += 2) {
        int hf = 1 << s;
#pragma unroll
        for (int r = 0; r < 6; r++) {
            int j = j4v[r], col = c4v[r];
            int k = j & (hf - 1);
            int i0 = ((j >> s) << (s + 2)) + k;
            float2 w1v = stw[k << (6 - s)];
            float2 w2v = stw[k << (5 - s)];
            float2 w3v = stw[(k + hf) << (5 - s)];
            float2 x0 = tz[i0 * 98 + col];
            float2 x1 = tz[(i0 + hf) * 98 + col];
            float2 x2 = tz[(i0 + 2 * hf) * 98 + col];
            float2 x3 = tz[(i0 + 3 * hf) * 98 + col];
            bf4(x0, x1, x2, x3, w1v, w2v, w3v);
            tz[i0 * 98 + col] = x0;
            tz[(i0 + hf) * 98 + col] = x1;
            tz[(i0 + 2 * hf) * 98 + col] = x2;
            tz[(i0 + 3 * hf) * 98 + col] = x3;
        }
        __syncthreads();
    }
    // final radix-2 stage (s=6, half=64)
    {
#pragma unroll
        for (int r = 0; r < 12; r++) {
            int j = jv[r], col = colv[r];
            float2 w = stw[j];
            float2 a = tz[j * 98 + col];
            float2 bb = tz[(j + 64) * 98 + col];
            float2 bw = cmul(bb, w);
            tz[j * 98 + col] = make_float2(a.x + bw.x, a.y + bw.y);
            tz[(j + 64) * 98 + col] = make_float2(a.x - bw.x, a.y - bw.y);
        }
        __syncthreads();
    }

    // ---------------- deinterleave tile -> A tf32 (x 1/128), in place ------
    {
#pragma unroll
        for (int rr = 0; rr < 8; rr++) {
            int row = warp * 8 + rr;
            float2 v0 = tz[row * 98 + lane];
            float2 v1 = tz[row * 98 + lane + 32];
            float2 v2 = tz[row * 98 + lane + 64];
            __syncwarp();
            unsigned* Ar = sBIG + row * 196;
            Ar[lane]       = f2tf(v0.x * 0.0078125f);
            Ar[lane + 96]  = f2tf(v0.y * 0.0078125f);
            Ar[lane + 32]  = f2tf(v1.x * 0.0078125f);
            Ar[lane + 128] = f2tf(v1.y * 0.0078125f);
            Ar[lane + 64]  = f2tf(v2.x * 0.0078125f);
            Ar[lane + 160] = f2tf(v2.y * 0.0078125f);
            __syncwarp();
        }
    }
    __syncthreads();

    // ---------------- MLP ----------------
    const int mgrp = warp & 3, ngrp = warp >> 2;
    const int nh = ngrp >> 1;             // 0: real outputs, 1: imag outputs
    const int jbase = (ngrp & 1) * 6;     // first n-tile within the half
    const int g = lane >> 2, tig = lane & 3;
    const int arow = mgrp * 32 + g;

    float acc[2][6][4];

    // ===== layer 1 =====
    {
        const float* bp = (nh == 0) ? (b1 + n * BS) : (b1 + NB * BS + n * BS);
#pragma unroll
        for (int j = 0; j < 6; j++) {
            int cih = (jbase + j) * 8 + 2 * tig;
            float bv0 = bp[cih], bv1 = bp[cih + 1];
#pragma unroll
            for (int mt = 0; mt < 2; mt++) {
                acc[mt][j][0] = bv0; acc[mt][j][1] = bv1;
                acc[mt][j][2] = bv0; acc[mt][j][3] = bv1;
            }
        }
        const unsigned* Blo = (nh == 0) ? sWr : sWi;
        const unsigned* Bhi = (nh == 0) ? sWi : sWr;
        const unsigned sgnHi = (nh == 0) ? 0x80000000u : 0u;
#pragma unroll 1
        for (int kc = 0; kc < 24; kc++) {
            const unsigned* Ain = sBIG + kc * 8;
            unsigned a0 = Ain[arow * 196 + tig];
            unsigned a1 = Ain[(arow + 8) * 196 + tig];
            unsigned a2 = Ain[arow * 196 + tig + 4];
            unsigned a3 = Ain[(arow + 8) * 196 + tig + 4];
            unsigned a4 = Ain[(arow + 16) * 196 + tig];
            unsigned a5 = Ain[(arow + 24) * 196 + tig];
            unsigned a6 = Ain[(arow + 16) * 196 + tig + 4];
            unsigned a7 = Ain[(arow + 24) * 196 + tig + 4];
            unsigned sgn = (kc < 12) ? 0u : sgnHi;
            const unsigned* Bsrc = (kc < 12) ? (Blo + kc * 8 * 104)
                                             : (Bhi + (kc - 12) * 8 * 104);
            const unsigned* Bt = Bsrc + tig * 104 + jbase * 8 + g;
#pragma unroll
            for (int j = 0; j < 6; j++) {
                unsigned b0 = Bt[j * 8] ^ sgn;
                unsigned b1v = Bt[4 * 104 + j * 8] ^ sgn;
                mma8(acc[0][j], a0, a1, a2, a3, b0, b1v);
                mma8(acc[1][j], a4, a5, a6, a7, b0, b1v);
            }
        }
    }
    __syncthreads();  // all A reads done

    // write relu(O) over A; stage W2 over W1
#pragma unroll
    for (int j = 0; j < 6; j++) {
        int colg = nh * 96 + (jbase + j) * 8 + 2 * tig;
#pragma unroll
        for (int mt = 0; mt < 2; mt++) {
            int r0 = arow + 16 * mt;
            uint2 v0 = make_uint2(f2tf(fmaxf(acc[mt][j][0], 0.f)),
                                  f2tf(fmaxf(acc[mt][j][1], 0.f)));
            uint2 v1 = make_uint2(f2tf(fmaxf(acc[mt][j][2], 0.f)),
                                  f2tf(fmaxf(acc[mt][j][3], 0.f)));
            *(uint2*)(sBIG + r0 * 196 + colg) = v0;
            *(uint2*)(sBIG + (r0 + 8) * 196 + colg) = v1;
        }
    }
    {
        const float* wr = w2 + n * BS * BS;
        const float* wi = w2 + NB * BS * BS + n * BS * BS;
        for (int idx = t; idx < 9216; idx += 512) {
            int r = idx / 96, ci = idx - r * 96;
            sWr[r * 104 + ci] = f2tf(wr[idx]);
            sWi[r * 104 + ci] = f2tf(wi[idx]);
        }
    }
    __syncthreads();

    // ===== layer 2 =====
    {
        const float* bp = (nh == 0) ? (b2 + n * BS) : (b2 + NB * BS + n * BS);
#pragma unroll
        for (int j = 0; j < 6; j++) {
            int cih = (jbase + j) * 8 + 2 * tig;
            float bv0 = bp[cih], bv1 = bp[cih + 1];
#pragma unroll
            for (int mt = 0; mt < 2; mt++) {
                acc[mt][j][0] = bv0; acc[mt][j][1] = bv1;
                acc[mt][j][2] = bv0; acc[mt][j][3] = bv1;
            }
        }
        const unsigned* Blo = (nh == 0) ? sWr : sWi;
        const unsigned* Bhi = (nh == 0) ? sWi : sWr;
        const unsigned sgnHi = (nh == 0) ? 0x80000000u : 0u;
#pragma unroll 1
        for (int kc = 0; kc < 24; kc++) {
            const unsigned* Ain = sBIG + kc * 8;
            unsigned a0 = Ain[arow * 196 + tig];
            unsigned a1 = Ain[(arow + 8) * 196 + tig];
            unsigned a2 = Ain[arow * 196 + tig + 4];
            unsigned a3 = Ain[(arow + 8) * 196 + tig + 4];
            unsigned a4 = Ain[(arow + 16) * 196 + tig];
            unsigned a5 = Ain[(arow + 24) * 196 + tig];
            unsigned a6 = Ain[(arow + 16) * 196 + tig + 4];
            unsigned a7 = Ain[(arow + 24) * 196 + tig + 4];
            unsigned sgn = (kc < 12) ? 0u : sgnHi;
            const unsigned* Bsrc = (kc < 12) ? (Blo + kc * 8 * 104)
                                             : (Bhi + (kc - 12) * 8 * 104);
            const unsigned* Bt = Bsrc + tig * 104 + jbase * 8 + g;
#pragma unroll
            for (int j = 0; j < 6; j++) {
                unsigned b0 = Bt[j * 8] ^ sgn;
                unsigned b1v = Bt[4 * 104 + j * 8] ^ sgn;
                mma8(acc[0][j], a0, a1, a2, a3, b0, b1v);
                mma8(acc[1][j], a4, a5, a6, a7, b0, b1v);
            }
        }
    }
    __syncthreads();  // all O reads done

    // softshrink -> tile (float2 components), rows bit-reversed for iFFT
    {
        float* Tf = (float*)sBIG;
#pragma unroll
        for (int j = 0; j < 6; j++) {
            int ch = (jbase + j) * 8 + 2 * tig;
#pragma unroll
            for (int mt = 0; mt < 2; mt++) {
                int r0 = arow + 16 * mt, r1 = r0 + 8;
                int br0 = __brev((unsigned)r0) >> 25;
                int br1 = __brev((unsigned)r1) >> 25;
                Tf[br0 * 196 + 2 * ch + nh] = sshrink(acc[mt][j][0]);
                Tf[br0 * 196 + 2 * (ch + 1) + nh] = sshrink(acc[mt][j][1]);
                Tf[br1 * 196 + 2 * ch + nh] = sshrink(acc[mt][j][2]);
                Tf[br1 * 196 + 2 * (ch + 1) + nh] = sshrink(acc[mt][j][3]);
            }
        }
    }
    __syncthreads();

    // ---------------- inverse FFT over h (conj twiddles) ----------------
#pragma unroll
    for (int s = 0; s < 6; s += 2) {
        int hf = 1 << s;
#pragma unroll
        for (int r = 0; r < 6; r++) {
            int j = j4v[r], col = c4v[r];
            int k = j & (hf - 1);
            int i0 = ((j >> s) << (s + 2)) + k;
            float2 w1v = stw[k << (6 - s)]; w1v.y = -w1v.y;
            float2 w2v = stw[k << (5 - s)]; w2v.y = -w2v.y;
            float2 w3v = stw[(k + hf) << (5 - s)]; w3v.y = -w3v.y;
            float2 x0 = tz[i0 * 98 + col];
            float2 x1 = tz[(i0 + hf) * 98 + col];
            float2 x2 = tz[(i0 + 2 * hf) * 98 + col];
            float2 x3 = tz[(i0 + 3 * hf) * 98 + col];
            bf4(x0, x1, x2, x3, w1v, w2v, w3v);
            tz[i0 * 98 + col] = x0;
            tz[(i0 + hf) * 98 + col] = x1;
            tz[(i0 + 2 * hf) * 98 + col] = x2;
            tz[(i0 + 3 * hf) * 98 + col] = x3;
        }
        __syncthreads();
    }
    {
#pragma unroll
        for (int r = 0; r < 12; r++) {
            int j = jv[r], col = colv[r];
            float2 w = stw[j]; w.y = -w.y;
            float2 a = tz[j * 98 + col];
            float2 bb = tz[(j + 64) * 98 + col];
            float2 bw = cmul(bb, w);
            tz[j * 98 + col] = make_float2(a.x + bw.x, a.y + bw.y);
            tz[(j + 64) * 98 + col] = make_float2(a.x - bw.x, a.y - bw.y);
        }
        __syncthreads();
    }

    // Store back
    for (int i = t; i < 128 * 96; i += 512) {
        int h = i / 96, col = i - h * 96;
        g_F[base + (size_t)h * CC + col] = tz[h * 98 + col];
    }
}

// ---------------------------------------------------------------------------
// Pass 5: inverse real FFT length 128 along W + 1/128 scale + residual add.
// 64-pt inverse FFT with 3 radix-2^2 passes (conj twiddles).
// C2R semantics: imag of DC & Nyquist ignored.
// ---------------------------------------------------------------------------
__global__ __launch_bounds__(512, 2) void k_inv_w(const float* __restrict__ x,
                                                  float* __restrict__ out) {
    extern __shared__ float2 sm2[];
    float2* sz = sm2;               // [64][128]
    float2* stw = sm2 + 64 * 128;   // [65]
    const int t = threadIdx.x;
    if (t < 65) stw[t] = g_tw[t];
    __syncthreads();
    const int cl = t & 127, q = t >> 7;
    const int b = blockIdx.z, h = blockIdx.y;
    const int c = blockIdx.x * 128 + cl;
    size_t base = ((size_t)b * WF * HH + h) * CC + c;
    const size_t ws = (size_t)HH * CC;

#pragma unroll
    for (int jj = 0; jj < 8; jj++) {
        int idx = q * 8 + jj;
        if (idx == 0) {
            float2 X0 = g_F[base];
            float2 X64 = g_F[base + 64 * ws];
            sz[cl] = make_float2(X0.x + X64.x, X0.x - X64.x);  // imag dropped
            float2 X32 = g_F[base + 32 * ws];
            sz[1 * 128 + cl] = make_float2(2.f * X32.x, -2.f * X32.y);
        } else {
            int k = idx;  // 1..31
            float2 Xk = g_F[base + (size_t)k * ws];
            float2 Xm = g_F[base + (size_t)(64 - k) * ws];
            float2 A = make_float2(Xk.x + Xm.x, Xk.y - Xm.y);
            float2 D = make_float2(Xk.x - Xm.x, Xk.y + Xm.y);
            float2 wc = make_float2(stw[k].x, -stw[k].y);
            float2 tv = cmul(wc, D);
            sz[(__brev((unsigned)k) >> 26) * 128 + cl] =
                make_float2(A.x - tv.y, A.y + tv.x);
            float2 A2 = make_float2(Xm.x + Xk.x, Xm.y - Xk.y);
            float2 D2 = make_float2(Xm.x - Xk.x, Xm.y + Xk.y);
            float2 wc2 = make_float2(stw[64 - k].x, -stw[64 - k].y);
            float2 t2 = cmul(wc2, D2);
            sz[(__brev((unsigned)(64 - k)) >> 26) * 128 + cl] =
                make_float2(A2.x - t2.y, A2.y + t2.x);
        }
    }
    __syncthreads();

#pragma unroll
    for (int s = 0; s < 6; s += 2) {
        int hf = 1 << s;
#pragma unroll
        for (int r = 0; r < 4; r++) {
            int j = q * 4 + r;
            int k = j & (hf - 1);
            int i0 = ((j >> s) << (s + 2)) + k;
            float2 w1 = stw[k << (6 - s)]; w1.y = -w1.y;
            float2 w2 = stw[k << (5 - s)]; w2.y = -w2.y;
            float2 w3 = stw[(k + hf) << (5 - s)]; w3.y = -w3.y;
            float2 x0 = sz[i0 * 128 + cl];
            float2 x1 = sz[(i0 + hf) * 128 + cl];
            float2 x2 = sz[(i0 + 2 * hf) * 128 + cl];
            float2 x3 = sz[(i0 + 3 * hf) * 128 + cl];
            bf4(x0, x1, x2, x3, w1, w2, w3);
            sz[i0 * 128 + cl] = x0;
            sz[(i0 + hf) * 128 + cl] = x1;
            sz[(i0 + 2 * hf) * 128 + cl] = x2;
            sz[(i0 + 3 * hf) * 128 + cl] = x3;
        }
        __syncthreads();
    }

    const size_t xbase = ((size_t)(b * HH + h) * WW) * CC + c;
#pragma unroll
    for (int mm = 0; mm < 16; mm++) {
        int m = q * 16 + mm;
        float2 z = sz[m * 128 + cl];
        size_t i0 = xbase + (size_t)(2 * m) * CC;
        size_t i1 = xbase + (size_t)(2 * m + 1) * CC;
        out[i0] = z.x * (1.f / 128.f) + x[i0];
        out[i1] = z.y * (1.f / 128.f) + x[i1];
    }
}

// ---------------------------------------------------------------------------
extern "C" void kernel_launch(void* const* d_in, const int* in_sizes, int n_in,
                              void* d_out, int out_size) {
    const float* x  = (const float*)d_in[0];
    const float* w1 = (const float*)d_in[1];
    const float* b1 = (const float*)d_in[2];
    const float* w2 = (const float*)d_in[3];
    const float* b2 = (const float*)d_in[4];
    float* out = (float*)d_out;

    const size_t sm_fftw = (size_t)(64 * 128 + 65) * sizeof(float2);   // 66056
    const size_t sm_fus  = (size_t)(128 * 196 + 2 * 96 * 104) * 4 + 65 * 8; // 180744

    cudaFuncSetAttribute(k_fwd_w, cudaFuncAttributeMaxDynamicSharedMemorySize, (int)sm_fftw);
    cudaFuncSetAttribute(k_fused, cudaFuncAttributeMaxDynamicSharedMemorySize, (int)sm_fus);
    cudaFuncSetAttribute(k_inv_w, cudaFuncAttributeMaxDynamicSharedMemorySize, (int)sm_fftw);

    k_init_tw<<<1, 128>>>();
    k_fwd_w<<<dim3(6, 128, 8), 512, sm_fftw>>>(x);
    k_fused<<<dim3(8, 65, 8), 512, sm_fus>>>(w1, b1, w2, b2);
    k_inv_w<<<dim3(6, 128, 8), 512, sm_fftw>>>(x, out);
}

// round 7
// speedup vs baseline: 3.4067x; 1.2999x over previous
#include <cuda_runtime.h>
#include <cuda_bf16.h>
#include <math.h>

#define BB 8
#define HH 128
#define WW 128
#define CC 768
#define NB 8
#define BS 96
#define WF 65
#define LAMBDA 0.01f

// Frequency-domain scratch (bf16 transport): [b][wf][h][c]
__device__ __nv_bfloat162 g_F[(size_t)BB * WF * HH * CC];
// Twiddles: g_tw[k] = exp(-2*pi*i*k/128), k=0..64
__device__ float2 g_tw[65];

__device__ __forceinline__ float2 cmul(float2 a, float2 b) {
    return make_float2(a.x * b.x - a.y * b.y, a.x * b.y + a.y * b.x);
}

// pack two floats to bf16x2 word: lo = second operand, hi = first
__device__ __forceinline__ unsigned bf2(float hi, float lo) {
    unsigned r;
    asm("cvt.rn.bf16x2.f32 %0, %1, %2;" : "=r"(r) : "f"(hi), "f"(lo));
    return r;
}

__device__ __forceinline__ void mma16(float c[4], unsigned a0, unsigned a1,
                                      unsigned a2, unsigned a3,
                                      unsigned b0, unsigned b1) {
    asm volatile(
        "mma.sync.aligned.m16n8k16.row.col.f32.bf16.bf16.f32 "
        "{%0,%1,%2,%3}, {%4,%5,%6,%7}, {%8,%9}, {%0,%1,%2,%3};"
        : "+f"(c[0]), "+f"(c[1]), "+f"(c[2]), "+f"(c[3])
        : "r"(a0), "r"(a1), "r"(a2), "r"(a3), "r"(b0), "r"(b1));
}

__device__ __forceinline__ float sshrink(float v) {
    return v > LAMBDA ? v - LAMBDA : (v < -LAMBDA ? v + LAMBDA : 0.f);
}

__global__ void k_init_tw() {
    int i = threadIdx.x;
    if (i < 65) {
        double a = -2.0 * 3.14159265358979323846264338327950288 * (double)i / 128.0;
        g_tw[i] = make_float2((float)cos(a), (float)sin(a));
    }
}

// Radix-2^2: two DIT radix-2 stages fused in registers.
__device__ __forceinline__ void bf4(float2& x0, float2& x1, float2& x2,
                                    float2& x3, float2 w1, float2 w2,
                                    float2 w3) {
    float2 t1 = cmul(x1, w1), t3 = cmul(x3, w1);
    float2 y0 = make_float2(x0.x + t1.x, x0.y + t1.y);
    float2 y1 = make_float2(x0.x - t1.x, x0.y - t1.y);
    float2 y2 = make_float2(x2.x + t3.x, x2.y + t3.y);
    float2 y3 = make_float2(x2.x - t3.x, x2.y - t3.y);
    float2 u2 = cmul(y2, w2), u3 = cmul(y3, w3);
    x0 = make_float2(y0.x + u2.x, y0.y + u2.y);
    x2 = make_float2(y0.x - u2.x, y0.y - u2.y);
    x1 = make_float2(y1.x + u3.x, y1.y + u3.y);
    x3 = make_float2(y1.x - u3.x, y1.y - u3.y);
}

// ---------------------------------------------------------------------------
// Pass 1: real FFT length 128 along W (pack-in-pairs). 64-pt FFT, 3 radix-2^2
// passes. Tile [64][128 c]. Outputs stored as bf16x2.
// ---------------------------------------------------------------------------
__global__ __launch_bounds__(512, 2) void k_fwd_w(const float* __restrict__ x) {
    extern __shared__ float2 sm2[];
    float2* sz = sm2;               // [64][128]
    float2* stw = sm2 + 64 * 128;   // [65]
    const int t = threadIdx.x;
    if (t < 65) stw[t] = g_tw[t];
    const int cl = t & 127, q = t >> 7;
    const int b = blockIdx.z, h = blockIdx.y;
    const int c = blockIdx.x * 128 + cl;
    const float* xp = x + ((size_t)(b * HH + h) * WW) * CC + c;

#pragma unroll
    for (int mm = 0; mm < 16; mm++) {
        int m = q * 16 + mm;
        float re = xp[(size_t)(2 * m) * CC];
        float im = xp[(size_t)(2 * m + 1) * CC];
        sz[(__brev((unsigned)m) >> 26) * 128 + cl] = make_float2(re, im);
    }
    __syncthreads();

#pragma unroll
    for (int s = 0; s < 6; s += 2) {
        int hf = 1 << s;
#pragma unroll
        for (int r = 0; r < 4; r++) {
            int j = q * 4 + r;
            int k = j & (hf - 1);
            int i0 = ((j >> s) << (s + 2)) + k;
            float2 w1 = stw[k << (6 - s)];
            float2 w2 = stw[k << (5 - s)];
            float2 w3 = stw[(k + hf) << (5 - s)];
            float2 x0 = sz[i0 * 128 + cl];
            float2 x1 = sz[(i0 + hf) * 128 + cl];
            float2 x2 = sz[(i0 + 2 * hf) * 128 + cl];
            float2 x3 = sz[(i0 + 3 * hf) * 128 + cl];
            bf4(x0, x1, x2, x3, w1, w2, w3);
            sz[i0 * 128 + cl] = x0;
            sz[(i0 + hf) * 128 + cl] = x1;
            sz[(i0 + 2 * hf) * 128 + cl] = x2;
            sz[(i0 + 3 * hf) * 128 + cl] = x3;
        }
        __syncthreads();
    }

    size_t base = ((size_t)b * WF * HH + h) * CC + c;
    const size_t ws = (size_t)HH * CC;
#pragma unroll
    for (int jj = 0; jj < 8; jj++) {
        int idx = q * 8 + jj;
        if (idx == 0) {
            float2 Z0 = sz[cl];
            g_F[base] = __float22bfloat162_rn(make_float2(Z0.x + Z0.y, 0.f));
            g_F[base + 64 * ws] = __float22bfloat162_rn(make_float2(Z0.x - Z0.y, 0.f));
            float2 Z32 = sz[32 * 128 + cl];
            g_F[base + 32 * ws] = __float22bfloat162_rn(make_float2(Z32.x, -Z32.y));
        } else {
            int k = idx;  // 1..31
            float2 Zk = sz[k * 128 + cl];
            float2 Zm = sz[(64 - k) * 128 + cl];
            float2 E = make_float2(0.5f * (Zk.x + Zm.x), 0.5f * (Zk.y - Zm.y));
            float2 D = make_float2(0.5f * (Zk.x - Zm.x), 0.5f * (Zk.y + Zm.y));
            float2 O = make_float2(D.y, -D.x);
            float2 p = cmul(stw[k], O);
            g_F[base + (size_t)k * ws] =
                __float22bfloat162_rn(make_float2(E.x + p.x, E.y + p.y));
            float2 Ec = make_float2(E.x, -E.y);
            float2 Oc = make_float2(O.x, -O.y);
            float2 qv = cmul(stw[64 - k], Oc);
            g_F[base + (size_t)(64 - k) * ws] =
                __float22bfloat162_rn(make_float2(Ec.x + qv.x, Ec.y + qv.y));
        }
    }
}

// ---------------------------------------------------------------------------
// Fused pass: FFT-H fwd + complex MLP (bf16 mma m16n8k16) + FFT-H inv.
// smem: tile float2 [128][98] (100 KB, reused as bf16 A/O matrix, word
// stride 196) | 4 weight arrays bf16 [96 o][104 i] (word stride 52) | tw.
// ---------------------------------------------------------------------------
__global__ __launch_bounds__(512, 1) void k_fused(const float* __restrict__ w1,
                                                  const float* __restrict__ b1,
                                                  const float* __restrict__ w2,
                                                  const float* __restrict__ b2) {
    extern __shared__ unsigned smu[];
    unsigned* sBIG = smu;                         // [128][196] words
    unsigned* sW1r = smu + 128 * 196;             // [96][52] words (bf16x2)
    unsigned* sW1i = sW1r + 96 * 52;
    unsigned* sW2r = sW1i + 96 * 52;
    unsigned* sW2i = sW2r + 96 * 52;
    float2* stw = (float2*)(sW2i + 96 * 52);      // [65]
    float2* tz = (float2*)sBIG;                   // tile view, row stride 98

    const int t = threadIdx.x;
    const int lane = t & 31, warp = t >> 5;
    if (t < 65) stw[t] = g_tw[t];
    const int n = blockIdx.x, wf = blockIdx.y, b = blockIdx.z;
    const size_t base = ((size_t)(b * WF + wf) * HH) * CC + n * BS;

    // Load tile (bit-reversed rows for DIT), bf16 -> f32
    for (int i = t; i < 128 * 96; i += 512) {
        int h = i / 96, col = i - h * 96;
        tz[(__brev((unsigned)h) >> 25) * 98 + col] =
            __bfloat1622float2(g_F[base + (size_t)h * CC + col]);
    }
    // Stage W1 and W2 transposed ([o][i]) as bf16
    {
        const float* w1r = w1 + n * BS * BS;
        const float* w1i = w1 + NB * BS * BS + n * BS * BS;
        const float* w2r = w2 + n * BS * BS;
        const float* w2i = w2 + NB * BS * BS + n * BS * BS;
        __nv_bfloat16* h1r = (__nv_bfloat16*)sW1r;
        __nv_bfloat16* h1i = (__nv_bfloat16*)sW1i;
        __nv_bfloat16* h2r = (__nv_bfloat16*)sW2r;
        __nv_bfloat16* h2i = (__nv_bfloat16*)sW2i;
        for (int idx = t; idx < 9216; idx += 512) {
            int i = idx / 96, o = idx - i * 96;   // i = input(k), o = output
            int ha = o * 104 + i;
            h1r[ha] = __float2bfloat16_rn(w1r[idx]);
            h1i[ha] = __float2bfloat16_rn(w1i[idx]);
            h2r[ha] = __float2bfloat16_rn(w2r[idx]);
            h2i[ha] = __float2bfloat16_rn(w2i[idx]);
        }
    }
    __syncthreads();

    // Work maps
    int j4v[6], c4v[6];
#pragma unroll
    for (int r = 0; r < 6; r++) {
        int idx = r * 512 + t;
        j4v[r] = idx / 96;
        c4v[r] = idx - j4v[r] * 96;
    }
    int jv[12], colv[12];
#pragma unroll
    for (int r = 0; r < 12; r++) {
        int idx = r * 512 + t;
        jv[r] = idx / 96;
        colv[r] = idx - jv[r] * 96;
    }

    // ---------------- forward FFT over h ----------------
#pragma unroll
    for (int s = 0; s < 6; s += 2) {
        int hf = 1 << s;
#pragma unroll
        for (int r = 0; r < 6; r++) {
            int j = j4v[r], col = c4v[r];
            int k = j & (hf - 1);
            int i0 = ((j >> s) << (s + 2)) + k;
            float2 w1v = stw[k << (6 - s)];
            float2 w2v = stw[k << (5 - s)];
            float2 w3v = stw[(k + hf) << (5 - s)];
            float2 x0 = tz[i0 * 98 + col];
            float2 x1 = tz[(i0 + hf) * 98 + col];
            float2 x2 = tz[(i0 + 2 * hf) * 98 + col];
            float2 x3 = tz[(i0 + 3 * hf) * 98 + col];
            bf4(x0, x1, x2, x3, w1v, w2v, w3v);
            tz[i0 * 98 + col] = x0;
            tz[(i0 + hf) * 98 + col] = x1;
            tz[(i0 + 2 * hf) * 98 + col] = x2;
            tz[(i0 + 3 * hf) * 98 + col] = x3;
        }
        __syncthreads();
    }
    {
#pragma unroll
        for (int r = 0; r < 12; r++) {
            int j = jv[r], col = colv[r];
            float2 w = stw[j];
            float2 a = tz[j * 98 + col];
            float2 bb = tz[(j + 64) * 98 + col];
            float2 bw = cmul(bb, w);
            tz[j * 98 + col] = make_float2(a.x + bw.x, a.y + bw.y);
            tz[(j + 64) * 98 + col] = make_float2(a.x - bw.x, a.y - bw.y);
        }
        __syncthreads();
    }

    // ---- deinterleave tile -> bf16 A (x 1/128), in place, per-row by warp --
    // A layout: row word stride 196; real k halves 0..95 (words 0..47),
    // imag k halves 96..191 (words 48..95).
    {
        const float s128 = 0.0078125f;
#pragma unroll
        for (int rr = 0; rr < 8; rr++) {
            int row = warp * 8 + rr;
            float4 q0 = *(float4*)&tz[row * 98 + 2 * lane];        // cols 2l,2l+1
            float4 q1 = make_float4(0.f, 0.f, 0.f, 0.f);
            if (lane < 16)
                q1 = *(float4*)&tz[row * 98 + 2 * (lane + 32)];
            __syncwarp();
            unsigned* Ar = sBIG + row * 196;
            Ar[lane] = bf2(q0.z * s128, q0.x * s128);              // real pair
            Ar[48 + lane] = bf2(q0.w * s128, q0.y * s128);         // imag pair
            if (lane < 16) {
                Ar[lane + 32] = bf2(q1.z * s128, q1.x * s128);
                Ar[48 + lane + 32] = bf2(q1.w * s128, q1.y * s128);
            }
            __syncwarp();
        }
    }
    __syncthreads();

    // ---------------- MLP ----------------
    const int mgrp = warp & 3, ngrp = warp >> 2;
    const int nh = ngrp >> 1;             // 0: real outputs, 1: imag outputs
    const int jbase = (ngrp & 1) * 6;     // first n-tile within the half
    const int g = lane >> 2, tig = lane & 3;
    const int arow = mgrp * 32 + g;

    float acc[2][6][4];

    // ===== layer 1 =====
    {
        const float* bp = (nh == 0) ? (b1 + n * BS) : (b1 + NB * BS + n * BS);
#pragma unroll
        for (int j = 0; j < 6; j++) {
            int cih = (jbase + j) * 8 + 2 * tig;
            float bv0 = bp[cih], bv1 = bp[cih + 1];
#pragma unroll
            for (int mt = 0; mt < 2; mt++) {
                acc[mt][j][0] = bv0; acc[mt][j][1] = bv1;
                acc[mt][j][2] = bv0; acc[mt][j][3] = bv1;
            }
        }
        const unsigned* Blo = (nh == 0) ? sW1r : sW1i;
        const unsigned* Bhi = (nh == 0) ? sW1i : sW1r;
        const unsigned sgnHi = (nh == 0) ? 0x80008000u : 0u;
        const int colw = (jbase * 8 + g) * 52 + tig;
#pragma unroll 1
        for (int kc = 0; kc < 12; kc++) {
            const unsigned* Ain = sBIG + kc * 8;
            unsigned a0 = Ain[arow * 196 + tig];
            unsigned a1 = Ain[(arow + 8) * 196 + tig];
            unsigned a2 = Ain[arow * 196 + tig + 4];
            unsigned a3 = Ain[(arow + 8) * 196 + tig + 4];
            unsigned a4 = Ain[(arow + 16) * 196 + tig];
            unsigned a5 = Ain[(arow + 24) * 196 + tig];
            unsigned a6 = Ain[(arow + 16) * 196 + tig + 4];
            unsigned a7 = Ain[(arow + 24) * 196 + tig + 4];
            unsigned sgn = (kc < 6) ? 0u : sgnHi;
            const unsigned* Bt = ((kc < 6) ? (Blo + kc * 8) : (Bhi + (kc - 6) * 8)) + colw;
#pragma unroll
            for (int j = 0; j < 6; j++) {
                unsigned b0 = Bt[j * 416] ^ sgn;
                unsigned b1v = Bt[j * 416 + 4] ^ sgn;
                mma16(acc[0][j], a0, a1, a2, a3, b0, b1v);
                mma16(acc[1][j], a4, a5, a6, a7, b0, b1v);
            }
        }
    }
    __syncthreads();  // all A reads done

    // write relu(O) over A (packed bf16x2)
#pragma unroll
    for (int j = 0; j < 6; j++) {
        int wcol = nh * 48 + (jbase + j) * 4 + tig;
#pragma unroll
        for (int mt = 0; mt < 2; mt++) {
            int r0 = arow + 16 * mt;
            sBIG[r0 * 196 + wcol] =
                bf2(fmaxf(acc[mt][j][1], 0.f), fmaxf(acc[mt][j][0], 0.f));
            sBIG[(r0 + 8) * 196 + wcol] =
                bf2(fmaxf(acc[mt][j][3], 0.f), fmaxf(acc[mt][j][2], 0.f));
        }
    }
    __syncthreads();

    // ===== layer 2 =====
    {
        const float* bp = (nh == 0) ? (b2 + n * BS) : (b2 + NB * BS + n * BS);
#pragma unroll
        for (int j = 0; j < 6; j++) {
            int cih = (jbase + j) * 8 + 2 * tig;
            float bv0 = bp[cih], bv1 = bp[cih + 1];
#pragma unroll
            for (int mt = 0; mt < 2; mt++) {
                acc[mt][j][0] = bv0; acc[mt][j][1] = bv1;
                acc[mt][j][2] = bv0; acc[mt][j][3] = bv1;
            }
        }
        const unsigned* Blo = (nh == 0) ? sW2r : sW2i;
        const unsigned* Bhi = (nh == 0) ? sW2i : sW2r;
        const unsigned sgnHi = (nh == 0) ? 0x80008000u : 0u;
        const int colw = (jbase * 8 + g) * 52 + tig;
#pragma unroll 1
        for (int kc = 0; kc < 12; kc++) {
            const unsigned* Ain = sBIG + kc * 8;
            unsigned a0 = Ain[arow * 196 + tig];
            unsigned a1 = Ain[(arow + 8) * 196 + tig];
            unsigned a2 = Ain[arow * 196 + tig + 4];
            unsigned a3 = Ain[(arow + 8) * 196 + tig + 4];
            unsigned a4 = Ain[(arow + 16) * 196 + tig];
            unsigned a5 = Ain[(arow + 24) * 196 + tig];
            unsigned a6 = Ain[(arow + 16) * 196 + tig + 4];
            unsigned a7 = Ain[(arow + 24) * 196 + tig + 4];
            unsigned sgn = (kc < 6) ? 0u : sgnHi;
            const unsigned* Bt = ((kc < 6) ? (Blo + kc * 8) : (Bhi + (kc - 6) * 8)) + colw;
#pragma unroll
            for (int j = 0; j < 6; j++) {
                unsigned b0 = Bt[j * 416] ^ sgn;
                unsigned b1v = Bt[j * 416 + 4] ^ sgn;
                mma16(acc[0][j], a0, a1, a2, a3, b0, b1v);
                mma16(acc[1][j], a4, a5, a6, a7, b0, b1v);
            }
        }
    }
    __syncthreads();  // all O reads done

    // softshrink -> float2 tile (bit-reversed rows) for inverse FFT
    {
        float* Tf = (float*)sBIG;
#pragma unroll
        for (int j = 0; j < 6; j++) {
            int ch = (jbase + j) * 8 + 2 * tig;
#pragma unroll
            for (int mt = 0; mt < 2; mt++) {
                int r0 = arow + 16 * mt, r1 = r0 + 8;
                int br0 = __brev((unsigned)r0) >> 25;
                int br1 = __brev((unsigned)r1) >> 25;
                Tf[br0 * 196 + 2 * ch + nh] = sshrink(acc[mt][j][0]);
                Tf[br0 * 196 + 2 * (ch + 1) + nh] = sshrink(acc[mt][j][1]);
                Tf[br1 * 196 + 2 * ch + nh] = sshrink(acc[mt][j][2]);
                Tf[br1 * 196 + 2 * (ch + 1) + nh] = sshrink(acc[mt][j][3]);
            }
        }
    }
    __syncthreads();

    // ---------------- inverse FFT over h (conj twiddles) ----------------
#pragma unroll
    for (int s = 0; s < 6; s += 2) {
        int hf = 1 << s;
#pragma unroll
        for (int r = 0; r < 6; r++) {
            int j = j4v[r], col = c4v[r];
            int k = j & (hf - 1);
            int i0 = ((j >> s) << (s + 2)) + k;
            float2 w1v = stw[k << (6 - s)]; w1v.y = -w1v.y;
            float2 w2v = stw[k << (5 - s)]; w2v.y = -w2v.y;
            float2 w3v = stw[(k + hf) << (5 - s)]; w3v.y = -w3v.y;
            float2 x0 = tz[i0 * 98 + col];
            float2 x1 = tz[(i0 + hf) * 98 + col];
            float2 x2 = tz[(i0 + 2 * hf) * 98 + col];
            float2 x3 = tz[(i0 + 3 * hf) * 98 + col];
            bf4(x0, x1, x2, x3, w1v, w2v, w3v);
            tz[i0 * 98 + col] = x0;
            tz[(i0 + hf) * 98 + col] = x1;
            tz[(i0 + 2 * hf) * 98 + col] = x2;
            tz[(i0 + 3 * hf) * 98 + col] = x3;
        }
        __syncthreads();
    }
    {
#pragma unroll
        for (int r = 0; r < 12; r++) {
            int j = jv[r], col = colv[r];
            float2 w = stw[j]; w.y = -w.y;
            float2 a = tz[j * 98 + col];
            float2 bb = tz[(j + 64) * 98 + col];
            float2 bw = cmul(bb, w);
            tz[j * 98 + col] = make_float2(a.x + bw.x, a.y + bw.y);
            tz[(j + 64) * 98 + col] = make_float2(a.x - bw.x, a.y - bw.y);
        }
        __syncthreads();
    }

    // Store back (f32 -> bf16x2)
    for (int i = t; i < 128 * 96; i += 512) {
        int h = i / 96, col = i - h * 96;
        g_F[base + (size_t)h * CC + col] = __float22bfloat162_rn(tz[h * 98 + col]);
    }
}

// ---------------------------------------------------------------------------
// Pass 5: inverse real FFT length 128 along W + 1/128 scale + residual add.
// C2R semantics: imag of DC & Nyquist ignored.
// ---------------------------------------------------------------------------
__global__ __launch_bounds__(512, 2) void k_inv_w(const float* __restrict__ x,
                                                  float* __restrict__ out) {
    extern __shared__ float2 sm2[];
    float2* sz = sm2;               // [64][128]
    float2* stw = sm2 + 64 * 128;   // [65]
    const int t = threadIdx.x;
    if (t < 65) stw[t] = g_tw[t];
    __syncthreads();
    const int cl = t & 127, q = t >> 7;
    const int b = blockIdx.z, h = blockIdx.y;
    const int c = blockIdx.x * 128 + cl;
    size_t base = ((size_t)b * WF * HH + h) * CC + c;
    const size_t ws = (size_t)HH * CC;

#pragma unroll
    for (int jj = 0; jj < 8; jj++) {
        int idx = q * 8 + jj;
        if (idx == 0) {
            float2 X0 = __bfloat1622float2(g_F[base]);
            float2 X64 = __bfloat1622float2(g_F[base + 64 * ws]);
            sz[cl] = make_float2(X0.x + X64.x, X0.x - X64.x);  // imag dropped
            float2 X32 = __bfloat1622float2(g_F[base + 32 * ws]);
            sz[1 * 128 + cl] = make_float2(2.f * X32.x, -2.f * X32.y);
        } else {
            int k = idx;  // 1..31
            float2 Xk = __bfloat1622float2(g_F[base + (size_t)k * ws]);
            float2 Xm = __bfloat1622float2(g_F[base + (size_t)(64 - k) * ws]);
            float2 A = make_float2(Xk.x + Xm.x, Xk.y - Xm.y);
            float2 D = make_float2(Xk.x - Xm.x, Xk.y + Xm.y);
            float2 wc = make_float2(stw[k].x, -stw[k].y);
            float2 tv = cmul(wc, D);
            sz[(__brev((unsigned)k) >> 26) * 128 + cl] =
                make_float2(A.x - tv.y, A.y + tv.x);
            float2 A2 = make_float2(Xm.x + Xk.x, Xm.y - Xk.y);
            float2 D2 = make_float2(Xm.x - Xk.x, Xm.y + Xk.y);
            float2 wc2 = make_float2(stw[64 - k].x, -stw[64 - k].y);
            float2 t2 = cmul(wc2, D2);
            sz[(__brev((unsigned)(64 - k)) >> 26) * 128 + cl] =
                make_float2(A2.x - t2.y, A2.y + t2.x);
        }
    }
    __syncthreads();

#pragma unroll
    for (int s = 0; s < 6; s += 2) {
        int hf = 1 << s;
#pragma unroll
        for (int r = 0; r < 4; r++) {
            int j = q * 4 + r;
            int k = j & (hf - 1);
            int i0 = ((j >> s) << (s + 2)) + k;
            float2 w1 = stw[k << (6 - s)]; w1.y = -w1.y;
            float2 w2 = stw[k << (5 - s)]; w2.y = -w2.y;
            float2 w3 = stw[(k + hf) << (5 - s)]; w3.y = -w3.y;
            float2 x0 = sz[i0 * 128 + cl];
            float2 x1 = sz[(i0 + hf) * 128 + cl];
            float2 x2 = sz[(i0 + 2 * hf) * 128 + cl];
            float2 x3 = sz[(i0 + 3 * hf) * 128 + cl];
            bf4(x0, x1, x2, x3, w1, w2, w3);
            sz[i0 * 128 + cl] = x0;
            sz[(i0 + hf) * 128 + cl] = x1;
            sz[(i0 + 2 * hf) * 128 + cl] = x2;
            sz[(i0 + 3 * hf) * 128 + cl] = x3;
        }
        __syncthreads();
    }

    const size_t xbase = ((size_t)(b * HH + h) * WW) * CC + c;
#pragma unroll
    for (int mm = 0; mm < 16; mm++) {
        int m = q * 16 + mm;
        float2 z = sz[m * 128 + cl];
        size_t i0 = xbase + (size_t)(2 * m) * CC;
        size_t i1 = xbase + (size_t)(2 * m + 1) * CC;
        out[i0] = z.x * (1.f / 128.f) + x[i0];
        out[i1] = z.y * (1.f / 128.f) + x[i1];
    }
}

// ---------------------------------------------------------------------------
extern "C" void kernel_launch(void* const* d_in, const int* in_sizes, int n_in,
                              void* d_out, int out_size) {
    const float* x  = (const float*)d_in[0];
    const float* w1 = (const float*)d_in[1];
    const float* b1 = (const float*)d_in[2];
    const float* w2 = (const float*)d_in[3];
    const float* b2 = (const float*)d_in[4];
    float* out = (float*)d_out;

    const size_t sm_fftw = (size_t)(64 * 128 + 65) * sizeof(float2);   // 66056
    const size_t sm_fus  = (size_t)(128 * 196 + 4 * 96 * 52) * 4 + 65 * 8; // ~181 KB

    cudaFuncSetAttribute(k_fwd_w, cudaFuncAttributeMaxDynamicSharedMemorySize, (int)sm_fftw);
    cudaFuncSetAttribute(k_fused, cudaFuncAttributeMaxDynamicSharedMemorySize, (int)sm_fus);
    cudaFuncSetAttribute(k_inv_w, cudaFuncAttributeMaxDynamicSharedMemorySize, (int)sm_fftw);

    k_init_tw<<<1, 128>>>();
    k_fwd_w<<<dim3(6, 128, 8), 512, sm_fftw>>>(x);
    k_fused<<<dim3(8, 65, 8), 512, sm_fus>>>(w1, b1, w2, b2);
    k_inv_w<<<dim3(6, 128, 8), 512, sm_fftw>>>(x, out);
}

// round 8
// speedup vs baseline: 3.5667x; 1.0470x over previous
#include <cuda_runtime.h>
#include <cuda_bf16.h>
#include <math.h>

#define BB 8
#define HH 128
#define WW 128
#define CC 768
#define NB 8
#define BS 96
#define WF 65
#define LAMBDA 0.01f

// Frequency-domain scratch (bf16 transport): [b][wf][h][c]
__device__ __nv_bfloat162 g_F[(size_t)BB * WF * HH * CC];
// Twiddles: g_tw[k] = exp(-2*pi*i*k/128), k=0..64
__device__ float2 g_tw[65];

__device__ __forceinline__ float2 cmul(float2 a, float2 b) {
    return make_float2(a.x * b.x - a.y * b.y, a.x * b.y + a.y * b.x);
}

// pack two floats to bf16x2 word
__device__ __forceinline__ unsigned bf2(float hi, float lo) {
    unsigned r;
    asm("cvt.rn.bf16x2.f32 %0, %1, %2;" : "=r"(r) : "f"(hi), "f"(lo));
    return r;
}

__device__ __forceinline__ void mma16(float c[4], unsigned a0, unsigned a1,
                                      unsigned a2, unsigned a3,
                                      unsigned b0, unsigned b1) {
    asm volatile(
        "mma.sync.aligned.m16n8k16.row.col.f32.bf16.bf16.f32 "
        "{%0,%1,%2,%3}, {%4,%5,%6,%7}, {%8,%9}, {%0,%1,%2,%3};"
        : "+f"(c[0]), "+f"(c[1]), "+f"(c[2]), "+f"(c[3])
        : "r"(a0), "r"(a1), "r"(a2), "r"(a3), "r"(b0), "r"(b1));
}

__device__ __forceinline__ float sshrink(float v) {
    return v > LAMBDA ? v - LAMBDA : (v < -LAMBDA ? v + LAMBDA : 0.f);
}

__global__ void k_init_tw() {
    int i = threadIdx.x;
    if (i < 65) {
        double a = -2.0 * 3.14159265358979323846264338327950288 * (double)i / 128.0;
        g_tw[i] = make_float2((float)cos(a), (float)sin(a));
    }
}

// Radix-2^2: two DIT radix-2 stages fused in registers.
__device__ __forceinline__ void bf4(float2& x0, float2& x1, float2& x2,
                                    float2& x3, float2 w1, float2 w2,
                                    float2 w3) {
    float2 t1 = cmul(x1, w1), t3 = cmul(x3, w1);
    float2 y0 = make_float2(x0.x + t1.x, x0.y + t1.y);
    float2 y1 = make_float2(x0.x - t1.x, x0.y - t1.y);
    float2 y2 = make_float2(x2.x + t3.x, x2.y + t3.y);
    float2 y3 = make_float2(x2.x - t3.x, x2.y - t3.y);
    float2 u2 = cmul(y2, w2), u3 = cmul(y3, w3);
    x0 = make_float2(y0.x + u2.x, y0.y + u2.y);
    x2 = make_float2(y0.x - u2.x, y0.y - u2.y);
    x1 = make_float2(y1.x + u3.x, y1.y + u3.y);
    x3 = make_float2(y1.x - u3.x, y1.y - u3.y);
}

// Radix-2^3: three DIT radix-2 stages (s, s+1, s+2) fused in registers.
// w[0] = tw stage s; w[1],w[2] = tw stage s+1; w[3..6] = tw stage s+2.
__device__ __forceinline__ void bf8(float2 x[8], const float2 w[7]) {
    bf4(x[0], x[1], x[2], x[3], w[0], w[1], w[2]);
    bf4(x[4], x[5], x[6], x[7], w[0], w[1], w[2]);
#pragma unroll
    for (int q = 0; q < 4; q++) {
        float2 u = cmul(x[q + 4], w[3 + q]);
        float2 a = x[q];
        x[q] = make_float2(a.x + u.x, a.y + u.y);
        x[q + 4] = make_float2(a.x - u.x, a.y - u.y);
    }
}

// ---------------------------------------------------------------------------
// Pass 1: real FFT length 128 along W (pack-in-pairs). 64-pt FFT with TWO
// radix-8 passes. Tile [64][128 c]. Outputs stored as bf16x2.
// ---------------------------------------------------------------------------
__global__ __launch_bounds__(512, 2) void k_fwd_w(const float* __restrict__ x) {
    extern __shared__ float2 sm2[];
    float2* sz = sm2;               // [64][128]
    float2* stw = sm2 + 64 * 128;   // [65]
    const int t = threadIdx.x;
    if (t < 65) stw[t] = g_tw[t];
    const int cl = t & 127, q = t >> 7;
    const int b = blockIdx.z, h = blockIdx.y;
    const int c = blockIdx.x * 128 + cl;
    const float* xp = x + ((size_t)(b * HH + h) * WW) * CC + c;

#pragma unroll
    for (int mm = 0; mm < 16; mm++) {
        int m = q * 16 + mm;
        float re = xp[(size_t)(2 * m) * CC];
        float im = xp[(size_t)(2 * m + 1) * CC];
        sz[(__brev((unsigned)m) >> 26) * 128 + cl] = make_float2(re, im);
    }
    __syncthreads();

#pragma unroll
    for (int s = 0; s <= 3; s += 3) {
        int hf = 1 << s;
#pragma unroll
        for (int rr = 0; rr < 2; rr++) {
            int j = q * 2 + rr;
            int k = j & (hf - 1);
            int i0 = ((j >> s) << (s + 3)) + k;
            float2 w[7];
            w[0] = stw[k << (6 - s)];
            w[1] = stw[k << (5 - s)];
            w[2] = stw[(k + hf) << (5 - s)];
#pragma unroll
            for (int qq = 0; qq < 4; qq++) w[3 + qq] = stw[(k + qq * hf) << (4 - s)];
            float2 xv[8];
#pragma unroll
            for (int m = 0; m < 8; m++) xv[m] = sz[(i0 + m * hf) * 128 + cl];
            bf8(xv, w);
#pragma unroll
            for (int m = 0; m < 8; m++) sz[(i0 + m * hf) * 128 + cl] = xv[m];
        }
        __syncthreads();
    }

    size_t base = ((size_t)b * WF * HH + h) * CC + c;
    const size_t ws = (size_t)HH * CC;
#pragma unroll
    for (int jj = 0; jj < 8; jj++) {
        int idx = q * 8 + jj;
        if (idx == 0) {
            float2 Z0 = sz[cl];
            g_F[base] = __float22bfloat162_rn(make_float2(Z0.x + Z0.y, 0.f));
            g_F[base + 64 * ws] = __float22bfloat162_rn(make_float2(Z0.x - Z0.y, 0.f));
            float2 Z32 = sz[32 * 128 + cl];
            g_F[base + 32 * ws] = __float22bfloat162_rn(make_float2(Z32.x, -Z32.y));
        } else {
            int k = idx;  // 1..31
            float2 Zk = sz[k * 128 + cl];
            float2 Zm = sz[(64 - k) * 128 + cl];
            float2 E = make_float2(0.5f * (Zk.x + Zm.x), 0.5f * (Zk.y - Zm.y));
            float2 D = make_float2(0.5f * (Zk.x - Zm.x), 0.5f * (Zk.y + Zm.y));
            float2 O = make_float2(D.y, -D.x);
            float2 p = cmul(stw[k], O);
            g_F[base + (size_t)k * ws] =
                __float22bfloat162_rn(make_float2(E.x + p.x, E.y + p.y));
            float2 Ec = make_float2(E.x, -E.y);
            float2 Oc = make_float2(O.x, -O.y);
            float2 qv = cmul(stw[64 - k], Oc);
            g_F[base + (size_t)(64 - k) * ws] =
                __float22bfloat162_rn(make_float2(Ec.x + qv.x, Ec.y + qv.y));
        }
    }
}

// ---------------------------------------------------------------------------
// Fused pass: FFT-H fwd + complex MLP (bf16 mma m16n8k16) + FFT-H inv.
// 128-pt FFTs: 2 radix-8 passes + 1 radix-2 pass per direction.
// ---------------------------------------------------------------------------
__global__ __launch_bounds__(512, 1) void k_fused(const float* __restrict__ w1,
                                                  const float* __restrict__ b1,
                                                  const float* __restrict__ w2,
                                                  const float* __restrict__ b2) {
    extern __shared__ unsigned smu[];
    unsigned* sBIG = smu;                         // [128][196] words
    unsigned* sW1r = smu + 128 * 196;             // [96][52] words (bf16x2)
    unsigned* sW1i = sW1r + 96 * 52;
    unsigned* sW2r = sW1i + 96 * 52;
    unsigned* sW2i = sW2r + 96 * 52;
    float2* stw = (float2*)(sW2i + 96 * 52);      // [65]
    float2* tz = (float2*)sBIG;                   // tile view, row stride 98

    const int t = threadIdx.x;
    const int lane = t & 31, warp = t >> 5;
    if (t < 65) stw[t] = g_tw[t];
    const int n = blockIdx.x, wf = blockIdx.y, b = blockIdx.z;
    const size_t base = ((size_t)(b * WF + wf) * HH) * CC + n * BS;

    // Load tile (bit-reversed rows for DIT), bf16 -> f32
    for (int i = t; i < 128 * 96; i += 512) {
        int h = i / 96, col = i - h * 96;
        tz[(__brev((unsigned)h) >> 25) * 98 + col] =
            __bfloat1622float2(g_F[base + (size_t)h * CC + col]);
    }
    // Stage W1 and W2 transposed ([o][i]) as bf16
    {
        const float* w1r = w1 + n * BS * BS;
        const float* w1i = w1 + NB * BS * BS + n * BS * BS;
        const float* w2r = w2 + n * BS * BS;
        const float* w2i = w2 + NB * BS * BS + n * BS * BS;
        __nv_bfloat16* h1r = (__nv_bfloat16*)sW1r;
        __nv_bfloat16* h1i = (__nv_bfloat16*)sW1i;
        __nv_bfloat16* h2r = (__nv_bfloat16*)sW2r;
        __nv_bfloat16* h2i = (__nv_bfloat16*)sW2i;
        for (int idx = t; idx < 9216; idx += 512) {
            int i = idx / 96, o = idx - i * 96;   // i = input(k), o = output
            int ha = o * 104 + i;
            h1r[ha] = __float2bfloat16_rn(w1r[idx]);
            h1i[ha] = __float2bfloat16_rn(w1i[idx]);
            h2r[ha] = __float2bfloat16_rn(w2r[idx]);
            h2i[ha] = __float2bfloat16_rn(w2i[idx]);
        }
    }
    __syncthreads();

    // Work maps: radix-8 passes: 16 groups x 96 cols = 1536 -> 3/thread
    int j8v[3], c8v[3];
#pragma unroll
    for (int r = 0; r < 3; r++) {
        int idx = r * 512 + t;
        j8v[r] = idx / 96;
        c8v[r] = idx - j8v[r] * 96;
    }
    // final radix-2 stage: 64 butterflies x 96 cols = 6144 -> 12/thread
    int jv[12], colv[12];
#pragma unroll
    for (int r = 0; r < 12; r++) {
        int idx = r * 512 + t;
        jv[r] = idx / 96;
        colv[r] = idx - jv[r] * 96;
    }

    // ---------------- forward FFT over h ----------------
#pragma unroll
    for (int s = 0; s <= 3; s += 3) {
        int hf = 1 << s;
#pragma unroll
        for (int r = 0; r < 3; r++) {
            int j = j8v[r], col = c8v[r];
            int k = j & (hf - 1);
            int i0 = ((j >> s) << (s + 3)) + k;
            float2 w[7];
            w[0] = stw[k << (6 - s)];
            w[1] = stw[k << (5 - s)];
            w[2] = stw[(k + hf) << (5 - s)];
#pragma unroll
            for (int qq = 0; qq < 4; qq++) w[3 + qq] = stw[(k + qq * hf) << (4 - s)];
            float2 xv[8];
#pragma unroll
            for (int m = 0; m < 8; m++) xv[m] = tz[(i0 + m * hf) * 98 + col];
            bf8(xv, w);
#pragma unroll
            for (int m = 0; m < 8; m++) tz[(i0 + m * hf) * 98 + col] = xv[m];
        }
        __syncthreads();
    }
    // final radix-2 stage (s=6, half=64)
    {
#pragma unroll
        for (int r = 0; r < 12; r++) {
            int j = jv[r], col = colv[r];
            float2 w = stw[j];
            float2 a = tz[j * 98 + col];
            float2 bb = tz[(j + 64) * 98 + col];
            float2 bw = cmul(bb, w);
            tz[j * 98 + col] = make_float2(a.x + bw.x, a.y + bw.y);
            tz[(j + 64) * 98 + col] = make_float2(a.x - bw.x, a.y - bw.y);
        }
        __syncthreads();
    }

    // ---- deinterleave tile -> bf16 A (x 1/128), in place, per-row by warp --
    {
        const float s128 = 0.0078125f;
#pragma unroll
        for (int rr = 0; rr < 8; rr++) {
            int row = warp * 8 + rr;
            float4 q0 = *(float4*)&tz[row * 98 + 2 * lane];
            float4 q1 = make_float4(0.f, 0.f, 0.f, 0.f);
            if (lane < 16)
                q1 = *(float4*)&tz[row * 98 + 2 * (lane + 32)];
            __syncwarp();
            unsigned* Ar = sBIG + row * 196;
            Ar[lane] = bf2(q0.z * s128, q0.x * s128);
            Ar[48 + lane] = bf2(q0.w * s128, q0.y * s128);
            if (lane < 16) {
                Ar[lane + 32] = bf2(q1.z * s128, q1.x * s128);
                Ar[48 + lane + 32] = bf2(q1.w * s128, q1.y * s128);
            }
            __syncwarp();
        }
    }
    __syncthreads();

    // ---------------- MLP ----------------
    const int mgrp = warp & 3, ngrp = warp >> 2;
    const int nh = ngrp >> 1;
    const int jbase = (ngrp & 1) * 6;
    const int g = lane >> 2, tig = lane & 3;
    const int arow = mgrp * 32 + g;

    float acc[2][6][4];

    // ===== layer 1 =====
    {
        const float* bp = (nh == 0) ? (b1 + n * BS) : (b1 + NB * BS + n * BS);
#pragma unroll
        for (int j = 0; j < 6; j++) {
            int cih = (jbase + j) * 8 + 2 * tig;
            float bv0 = bp[cih], bv1 = bp[cih + 1];
#pragma unroll
            for (int mt = 0; mt < 2; mt++) {
                acc[mt][j][0] = bv0; acc[mt][j][1] = bv1;
                acc[mt][j][2] = bv0; acc[mt][j][3] = bv1;
            }
        }
        const unsigned* Blo = (nh == 0) ? sW1r : sW1i;
        const unsigned* Bhi = (nh == 0) ? sW1i : sW1r;
        const unsigned sgnHi = (nh == 0) ? 0x80008000u : 0u;
        const int colw = (jbase * 8 + g) * 52 + tig;
#pragma unroll 1
        for (int kc = 0; kc < 12; kc++) {
            const unsigned* Ain = sBIG + kc * 8;
            unsigned a0 = Ain[arow * 196 + tig];
            unsigned a1 = Ain[(arow + 8) * 196 + tig];
            unsigned a2 = Ain[arow * 196 + tig + 4];
            unsigned a3 = Ain[(arow + 8) * 196 + tig + 4];
            unsigned a4 = Ain[(arow + 16) * 196 + tig];
            unsigned a5 = Ain[(arow + 24) * 196 + tig];
            unsigned a6 = Ain[(arow + 16) * 196 + tig + 4];
            unsigned a7 = Ain[(arow + 24) * 196 + tig + 4];
            unsigned sgn = (kc < 6) ? 0u : sgnHi;
            const unsigned* Bt = ((kc < 6) ? (Blo + kc * 8) : (Bhi + (kc - 6) * 8)) + colw;
#pragma unroll
            for (int j = 0; j < 6; j++) {
                unsigned b0 = Bt[j * 416] ^ sgn;
                unsigned b1v = Bt[j * 416 + 4] ^ sgn;
                mma16(acc[0][j], a0, a1, a2, a3, b0, b1v);
                mma16(acc[1][j], a4, a5, a6, a7, b0, b1v);
            }
        }
    }
    __syncthreads();  // all A reads done

    // write relu(O) over A (packed bf16x2)
#pragma unroll
    for (int j = 0; j < 6; j++) {
        int wcol = nh * 48 + (jbase + j) * 4 + tig;
#pragma unroll
        for (int mt = 0; mt < 2; mt++) {
            int r0 = arow + 16 * mt;
            sBIG[r0 * 196 + wcol] =
                bf2(fmaxf(acc[mt][j][1], 0.f), fmaxf(acc[mt][j][0], 0.f));
            sBIG[(r0 + 8) * 196 + wcol] =
                bf2(fmaxf(acc[mt][j][3], 0.f), fmaxf(acc[mt][j][2], 0.f));
        }
    }
    __syncthreads();

    // ===== layer 2 =====
    {
        const float* bp = (nh == 0) ? (b2 + n * BS) : (b2 + NB * BS + n * BS);
#pragma unroll
        for (int j = 0; j < 6; j++) {
            int cih = (jbase + j) * 8 + 2 * tig;
            float bv0 = bp[cih], bv1 = bp[cih + 1];
#pragma unroll
            for (int mt = 0; mt < 2; mt++) {
                acc[mt][j][0] = bv0; acc[mt][j][1] = bv1;
                acc[mt][j][2] = bv0; acc[mt][j][3] = bv1;
            }
        }
        const unsigned* Blo = (nh == 0) ? sW2r : sW2i;
        const unsigned* Bhi = (nh == 0) ? sW2i : sW2r;
        const unsigned sgnHi = (nh == 0) ? 0x80008000u : 0u;
        const int colw = (jbase * 8 + g) * 52 + tig;
#pragma unroll 1
        for (int kc = 0; kc < 12; kc++) {
            const unsigned* Ain = sBIG + kc * 8;
            unsigned a0 = Ain[arow * 196 + tig];
            unsigned a1 = Ain[(arow + 8) * 196 + tig];
            unsigned a2 = Ain[arow * 196 + tig + 4];
            unsigned a3 = Ain[(arow + 8) * 196 + tig + 4];
            unsigned a4 = Ain[(arow + 16) * 196 + tig];
            unsigned a5 = Ain[(arow + 24) * 196 + tig];
            unsigned a6 = Ain[(arow + 16) * 196 + tig + 4];
            unsigned a7 = Ain[(arow + 24) * 196 + tig + 4];
            unsigned sgn = (kc < 6) ? 0u : sgnHi;
            const unsigned* Bt = ((kc < 6) ? (Blo + kc * 8) : (Bhi + (kc - 6) * 8)) + colw;
#pragma unroll
            for (int j = 0; j < 6; j++) {
                unsigned b0 = Bt[j * 416] ^ sgn;
                unsigned b1v = Bt[j * 416 + 4] ^ sgn;
                mma16(acc[0][j], a0, a1, a2, a3, b0, b1v);
                mma16(acc[1][j], a4, a5, a6, a7, b0, b1v);
            }
        }
    }
    __syncthreads();  // all O reads done

    // softshrink -> float2 tile (bit-reversed rows) for inverse FFT
    {
        float* Tf = (float*)sBIG;
#pragma unroll
        for (int j = 0; j < 6; j++) {
            int ch = (jbase + j) * 8 + 2 * tig;
#pragma unroll
            for (int mt = 0; mt < 2; mt++) {
                int r0 = arow + 16 * mt, r1 = r0 + 8;
                int br0 = __brev((unsigned)r0) >> 25;
                int br1 = __brev((unsigned)r1) >> 25;
                Tf[br0 * 196 + 2 * ch + nh] = sshrink(acc[mt][j][0]);
                Tf[br0 * 196 + 2 * (ch + 1) + nh] = sshrink(acc[mt][j][1]);
                Tf[br1 * 196 + 2 * ch + nh] = sshrink(acc[mt][j][2]);
                Tf[br1 * 196 + 2 * (ch + 1) + nh] = sshrink(acc[mt][j][3]);
            }
        }
    }
    __syncthreads();

    // ---------------- inverse FFT over h (conj twiddles) ----------------
#pragma unroll
    for (int s = 0; s <= 3; s += 3) {
        int hf = 1 << s;
#pragma unroll
        for (int r = 0; r < 3; r++) {
            int j = j8v[r], col = c8v[r];
            int k = j & (hf - 1);
            int i0 = ((j >> s) << (s + 3)) + k;
            float2 w[7];
            w[0] = stw[k << (6 - s)];
            w[1] = stw[k << (5 - s)];
            w[2] = stw[(k + hf) << (5 - s)];
#pragma unroll
            for (int qq = 0; qq < 4; qq++) w[3 + qq] = stw[(k + qq * hf) << (4 - s)];
#pragma unroll
            for (int m = 0; m < 7; m++) w[m].y = -w[m].y;
            float2 xv[8];
#pragma unroll
            for (int m = 0; m < 8; m++) xv[m] = tz[(i0 + m * hf) * 98 + col];
            bf8(xv, w);
#pragma unroll
            for (int m = 0; m < 8; m++) tz[(i0 + m * hf) * 98 + col] = xv[m];
        }
        __syncthreads();
    }
    {
#pragma unroll
        for (int r = 0; r < 12; r++) {
            int j = jv[r], col = colv[r];
            float2 w = stw[j]; w.y = -w.y;
            float2 a = tz[j * 98 + col];
            float2 bb = tz[(j + 64) * 98 + col];
            float2 bw = cmul(bb, w);
            tz[j * 98 + col] = make_float2(a.x + bw.x, a.y + bw.y);
            tz[(j + 64) * 98 + col] = make_float2(a.x - bw.x, a.y - bw.y);
        }
        __syncthreads();
    }

    // Store back (f32 -> bf16x2)
    for (int i = t; i < 128 * 96; i += 512) {
        int h = i / 96, col = i - h * 96;
        g_F[base + (size_t)h * CC + col] = __float22bfloat162_rn(tz[h * 98 + col]);
    }
}

// ---------------------------------------------------------------------------
// Pass 5: inverse real FFT length 128 along W + 1/128 scale + residual add.
// 64-pt inverse FFT with TWO radix-8 passes (conj twiddles).
// C2R semantics: imag of DC & Nyquist ignored.
// ---------------------------------------------------------------------------
__global__ __launch_bounds__(512, 2) void k_inv_w(const float* __restrict__ x,
                                                  float* __restrict__ out) {
    extern __shared__ float2 sm2[];
    float2* sz = sm2;               // [64][128]
    float2* stw = sm2 + 64 * 128;   // [65]
    const int t = threadIdx.x;
    if (t < 65) stw[t] = g_tw[t];
    __syncthreads();
    const int cl = t & 127, q = t >> 7;
    const int b = blockIdx.z, h = blockIdx.y;
    const int c = blockIdx.x * 128 + cl;
    size_t base = ((size_t)b * WF * HH + h) * CC + c;
    const size_t ws = (size_t)HH * CC;

#pragma unroll
    for (int jj = 0; jj < 8; jj++) {
        int idx = q * 8 + jj;
        if (idx == 0) {
            float2 X0 = __bfloat1622float2(g_F[base]);
            float2 X64 = __bfloat1622float2(g_F[base + 64 * ws]);
            sz[cl] = make_float2(X0.x + X64.x, X0.x - X64.x);  // imag dropped
            float2 X32 = __bfloat1622float2(g_F[base + 32 * ws]);
            sz[1 * 128 + cl] = make_float2(2.f * X32.x, -2.f * X32.y);
        } else {
            int k = idx;  // 1..31
            float2 Xk = __bfloat1622float2(g_F[base + (size_t)k * ws]);
            float2 Xm = __bfloat1622float2(g_F[base + (size_t)(64 - k) * ws]);
            float2 A = make_float2(Xk.x + Xm.x, Xk.y - Xm.y);
            float2 D = make_float2(Xk.x - Xm.x, Xk.y + Xm.y);
            float2 wc = make_float2(stw[k].x, -stw[k].y);
            float2 tv = cmul(wc, D);
            sz[(__brev((unsigned)k) >> 26) * 128 + cl] =
                make_float2(A.x - tv.y, A.y + tv.x);
            float2 A2 = make_float2(Xm.x + Xk.x, Xm.y - Xk.y);
            float2 D2 = make_float2(Xm.x - Xk.x, Xm.y + Xk.y);
            float2 wc2 = make_float2(stw[64 - k].x, -stw[64 - k].y);
            float2 t2 = cmul(wc2, D2);
            sz[(__brev((unsigned)(64 - k)) >> 26) * 128 + cl] =
                make_float2(A2.x - t2.y, A2.y + t2.x);
        }
    }
    __syncthreads();

#pragma unroll
    for (int s = 0; s <= 3; s += 3) {
        int hf = 1 << s;
#pragma unroll
        for (int rr = 0; rr < 2; rr++) {
            int j = q * 2 + rr;
            int k = j & (hf - 1);
            int i0 = ((j >> s) << (s + 3)) + k;
            float2 w[7];
            w[0] = stw[k << (6 - s)];
            w[1] = stw[k << (5 - s)];
            w[2] = stw[(k + hf) << (5 - s)];
#pragma unroll
            for (int qq = 0; qq < 4; qq++) w[3 + qq] = stw[(k + qq * hf) << (4 - s)];
#pragma unroll
            for (int m = 0; m < 7; m++) w[m].y = -w[m].y;
            float2 xv[8];
#pragma unroll
            for (int m = 0; m < 8; m++) xv[m] = sz[(i0 + m * hf) * 128 + cl];
            bf8(xv, w);
#pragma unroll
            for (int m = 0; m < 8; m++) sz[(i0 + m * hf) * 128 + cl] = xv[m];
        }
        __syncthreads();
    }

    const size_t xbase = ((size_t)(b * HH + h) * WW) * CC + c;
#pragma unroll
    for (int mm = 0; mm < 16; mm++) {
        int m = q * 16 + mm;
        float2 z = sz[m * 128 + cl];
        size_t i0 = xbase + (size_t)(2 * m) * CC;
        size_t i1 = xbase + (size_t)(2 * m + 1) * CC;
        out[i0] = z.x * (1.f / 128.f) + x[i0];
        out[i1] = z.y * (1.f / 128.f) + x[i1];
    }
}

// ---------------------------------------------------------------------------
extern "C" void kernel_launch(void* const* d_in, const int* in_sizes, int n_in,
                              void* d_out, int out_size) {
    const float* x  = (const float*)d_in[0];
    const float* w1 = (const float*)d_in[1];
    const float* b1 = (const float*)d_in[2];
    const float* w2 = (const float*)d_in[3];
    const float* b2 = (const float*)d_in[4];
    float* out = (float*)d_out;

    const size_t sm_fftw = (size_t)(64 * 128 + 65) * sizeof(float2);   // 66056
    const size_t sm_fus  = (size_t)(128 * 196 + 4 * 96 * 52) * 4 + 65 * 8; // ~181 KB

    cudaFuncSetAttribute(k_fwd_w, cudaFuncAttributeMaxDynamicSharedMemorySize, (int)sm_fftw);
    cudaFuncSetAttribute(k_fused, cudaFuncAttributeMaxDynamicSharedMemorySize, (int)sm_fus);
    cudaFuncSetAttribute(k_inv_w, cudaFuncAttributeMaxDynamicSharedMemorySize, (int)sm_fftw);

    k_init_tw<<<1, 128>>>();
    k_fwd_w<<<dim3(6, 128, 8), 512, sm_fftw>>>(x);
    k_fused<<<dim3(8, 65, 8), 512, sm_fus>>>(w1, b1, w2, b2);
    k_inv_w<<<dim3(6, 128, 8), 512, sm_fftw>>>(x, out);
}

// round 9
// speedup vs baseline: 3.7845x; 1.0610x over previous
#include <cuda_runtime.h>
#include <cuda_bf16.h>
#include <math.h>

#define BB 8
#define HH 128
#define WW 128
#define CC 768
#define NB 8
#define BS 96
#define WF 65
#define LAMBDA 0.01f

#define C4F 0.70710678118654752440f
#define C8F 0.92387953251128675613f
#define S8F 0.38268343236508977173f

// Frequency-domain scratch (bf16 transport): [b][wf][h][c]
__device__ __nv_bfloat162 g_F[(size_t)BB * WF * HH * CC];
// Twiddles: g_tw[k] = exp(-2*pi*i*k/128), k=0..64
__device__ float2 g_tw[65];

__device__ __forceinline__ float2 cmul(float2 a, float2 b) {
    return make_float2(a.x * b.x - a.y * b.y, a.x * b.y + a.y * b.x);
}

// pack two floats to bf16x2 word
__device__ __forceinline__ unsigned bf2(float hi, float lo) {
    unsigned r;
    asm("cvt.rn.bf16x2.f32 %0, %1, %2;" : "=r"(r) : "f"(hi), "f"(lo));
    return r;
}

__device__ __forceinline__ void mma16(float c[4], unsigned a0, unsigned a1,
                                      unsigned a2, unsigned a3,
                                      unsigned b0, unsigned b1) {
    asm volatile(
        "mma.sync.aligned.m16n8k16.row.col.f32.bf16.bf16.f32 "
        "{%0,%1,%2,%3}, {%4,%5,%6,%7}, {%8,%9}, {%0,%1,%2,%3};"
        : "+f"(c[0]), "+f"(c[1]), "+f"(c[2]), "+f"(c[3])
        : "r"(a0), "r"(a1), "r"(a2), "r"(a3), "r"(b0), "r"(b1));
}

__device__ __forceinline__ void ldsm4(unsigned& r0, unsigned& r1,
                                      unsigned& r2, unsigned& r3,
                                      unsigned addr) {
    asm volatile(
        "ldmatrix.sync.aligned.m8n8.x4.shared.b16 {%0,%1,%2,%3}, [%4];"
        : "=r"(r0), "=r"(r1), "=r"(r2), "=r"(r3)
        : "r"(addr));
}

__device__ __forceinline__ float sshrink(float v) {
    return v > LAMBDA ? v - LAMBDA : (v < -LAMBDA ? v + LAMBDA : 0.f);
}

__global__ void k_init_tw() {
    int i = threadIdx.x;
    if (i < 65) {
        double a = -2.0 * 3.14159265358979323846264338327950288 * (double)i / 128.0;
        g_tw[i] = make_float2((float)cos(a), (float)sin(a));
    }
}

// ----- register butterflies -----
// ∓i * v : forward (INV=false) uses e^{-i...} so -i rotation.
template <bool INV>
__device__ __forceinline__ float2 rot90(float2 v) {
    return INV ? make_float2(-v.y, v.x) : make_float2(v.y, -v.x);
}

// Radix-2^2, k=0 (trivial twiddles)
template <bool INV>
__device__ __forceinline__ void bf4_0(float2& x0, float2& x1, float2& x2,
                                      float2& x3) {
    float2 y0 = make_float2(x0.x + x1.x, x0.y + x1.y);
    float2 y1 = make_float2(x0.x - x1.x, x0.y - x1.y);
    float2 y2 = make_float2(x2.x + x3.x, x2.y + x3.y);
    float2 y3 = make_float2(x2.x - x3.x, x2.y - x3.y);
    float2 u3 = rot90<INV>(y3);
    x0 = make_float2(y0.x + y2.x, y0.y + y2.y);
    x2 = make_float2(y0.x - y2.x, y0.y - y2.y);
    x1 = make_float2(y1.x + u3.x, y1.y + u3.y);
    x3 = make_float2(y1.x - u3.x, y1.y - u3.y);
}

// Radix-2^3, k=0 (hardcoded 8th-root twiddles)
template <bool INV>
__device__ __forceinline__ void bf8_0(float2* x) {
    bf4_0<INV>(x[0], x[1], x[2], x[3]);
    bf4_0<INV>(x[4], x[5], x[6], x[7]);
    const float I = INV ? 1.f : -1.f;
    const float2 t1 = make_float2(C4F, I * C4F);
    const float2 t3 = make_float2(-C4F, I * C4F);
    {
        float2 a = x[0], u = x[4];
        x[0] = make_float2(a.x + u.x, a.y + u.y);
        x[4] = make_float2(a.x - u.x, a.y - u.y);
    }
    {
        float2 a = x[1], u = cmul(x[5], t1);
        x[1] = make_float2(a.x + u.x, a.y + u.y);
        x[5] = make_float2(a.x - u.x, a.y - u.y);
    }
    {
        float2 a = x[2], u = rot90<INV>(x[6]);
        x[2] = make_float2(a.x + u.x, a.y + u.y);
        x[6] = make_float2(a.x - u.x, a.y - u.y);
    }
    {
        float2 a = x[3], u = cmul(x[7], t3);
        x[3] = make_float2(a.x + u.x, a.y + u.y);
        x[7] = make_float2(a.x - u.x, a.y - u.y);
    }
}

// Radix-2^4 (stages with k=0): 16-point DIT block, hardcoded twiddles.
template <bool INV>
__device__ __forceinline__ void bf16pt(float2* x) {
    bf8_0<INV>(x);
    bf8_0<INV>(x + 8);
    const float I = INV ? 1.f : -1.f;
    const float2 w1 = make_float2(C8F, I * S8F);
    const float2 w2 = make_float2(C4F, I * C4F);
    const float2 w3 = make_float2(S8F, I * C8F);
    const float2 w5 = make_float2(-S8F, I * C8F);
    const float2 w6 = make_float2(-C4F, I * C4F);
    const float2 w7 = make_float2(-C8F, I * S8F);
#pragma unroll
    for (int m = 0; m < 8; m++) {
        float2 u;
        if (m == 0) u = x[8];
        else if (m == 1) u = cmul(x[9], w1);
        else if (m == 2) u = cmul(x[10], w2);
        else if (m == 3) u = cmul(x[11], w3);
        else if (m == 4) u = rot90<INV>(x[12]);
        else if (m == 5) u = cmul(x[13], w5);
        else if (m == 6) u = cmul(x[14], w6);
        else u = cmul(x[15], w7);
        float2 a = x[m];
        x[m] = make_float2(a.x + u.x, a.y + u.y);
        x[m + 8] = make_float2(a.x - u.x, a.y - u.y);
    }
}

// Generic radix-2^3 with provided twiddles (w[0]; w[1],w[2]; w[3..6]).
__device__ __forceinline__ void bf8(float2 x[8], const float2 w[7]) {
    float2 t1 = cmul(x[1], w[0]), t3 = cmul(x[3], w[0]);
    float2 y0 = make_float2(x[0].x + t1.x, x[0].y + t1.y);
    float2 y1 = make_float2(x[0].x - t1.x, x[0].y - t1.y);
    float2 y2 = make_float2(x[2].x + t3.x, x[2].y + t3.y);
    float2 y3 = make_float2(x[2].x - t3.x, x[2].y - t3.y);
    float2 u2 = cmul(y2, w[1]), u3 = cmul(y3, w[2]);
    x[0] = make_float2(y0.x + u2.x, y0.y + u2.y);
    x[2] = make_float2(y0.x - u2.x, y0.y - u2.y);
    x[1] = make_float2(y1.x + u3.x, y1.y + u3.y);
    x[3] = make_float2(y1.x - u3.x, y1.y - u3.y);
    float2 t5 = cmul(x[5], w[0]), t7 = cmul(x[7], w[0]);
    float2 z0 = make_float2(x[4].x + t5.x, x[4].y + t5.y);
    float2 z1 = make_float2(x[4].x - t5.x, x[4].y - t5.y);
    float2 z2 = make_float2(x[6].x + t7.x, x[6].y + t7.y);
    float2 z3 = make_float2(x[6].x - t7.x, x[6].y - t7.y);
    float2 v2 = cmul(z2, w[1]), v3 = cmul(z3, w[2]);
    x[4] = make_float2(z0.x + v2.x, z0.y + v2.y);
    x[6] = make_float2(z0.x - v2.x, z0.y - v2.y);
    x[5] = make_float2(z1.x + v3.x, z1.y + v3.y);
    x[7] = make_float2(z1.x - v3.x, z1.y - v3.y);
#pragma unroll
    for (int q = 0; q < 4; q++) {
        float2 u = cmul(x[q + 4], w[3 + q]);
        float2 a = x[q];
        x[q] = make_float2(a.x + u.x, a.y + u.y);
        x[q + 4] = make_float2(a.x - u.x, a.y - u.y);
    }
}

// ---------------------------------------------------------------------------
// Pass 1: real FFT length 128 along W (pack-in-pairs). 64-pt FFT with TWO
// radix-8 passes. Tile [64][128 c]. Outputs stored as bf16x2.
// ---------------------------------------------------------------------------
__global__ __launch_bounds__(512, 2) void k_fwd_w(const float* __restrict__ x) {
    extern __shared__ float2 sm2[];
    float2* sz = sm2;               // [64][128]
    float2* stw = sm2 + 64 * 128;   // [65]
    const int t = threadIdx.x;
    if (t < 65) stw[t] = g_tw[t];
    const int cl = t & 127, q = t >> 7;
    const int b = blockIdx.z, h = blockIdx.y;
    const int c = blockIdx.x * 128 + cl;
    const float* xp = x + ((size_t)(b * HH + h) * WW) * CC + c;

#pragma unroll
    for (int mm = 0; mm < 16; mm++) {
        int m = q * 16 + mm;
        float re = xp[(size_t)(2 * m) * CC];
        float im = xp[(size_t)(2 * m + 1) * CC];
        sz[(__brev((unsigned)m) >> 26) * 128 + cl] = make_float2(re, im);
    }
    __syncthreads();

#pragma unroll
    for (int s = 0; s <= 3; s += 3) {
        int hf = 1 << s;
#pragma unroll
        for (int rr = 0; rr < 2; rr++) {
            int j = q * 2 + rr;
            int k = j & (hf - 1);
            int i0 = ((j >> s) << (s + 3)) + k;
            float2 w[7];
            w[0] = stw[k << (6 - s)];
            w[1] = stw[k << (5 - s)];
            w[2] = stw[(k + hf) << (5 - s)];
#pragma unroll
            for (int qq = 0; qq < 4; qq++) w[3 + qq] = stw[(k + qq * hf) << (4 - s)];
            float2 xv[8];
#pragma unroll
            for (int m = 0; m < 8; m++) xv[m] = sz[(i0 + m * hf) * 128 + cl];
            bf8(xv, w);
#pragma unroll
            for (int m = 0; m < 8; m++) sz[(i0 + m * hf) * 128 + cl] = xv[m];
        }
        __syncthreads();
    }

    size_t base = ((size_t)b * WF * HH + h) * CC + c;
    const size_t ws = (size_t)HH * CC;
#pragma unroll
    for (int jj = 0; jj < 8; jj++) {
        int idx = q * 8 + jj;
        if (idx == 0) {
            float2 Z0 = sz[cl];
            g_F[base] = __float22bfloat162_rn(make_float2(Z0.x + Z0.y, 0.f));
            g_F[base + 64 * ws] = __float22bfloat162_rn(make_float2(Z0.x - Z0.y, 0.f));
            float2 Z32 = sz[32 * 128 + cl];
            g_F[base + 32 * ws] = __float22bfloat162_rn(make_float2(Z32.x, -Z32.y));
        } else {
            int k = idx;  // 1..31
            float2 Zk = sz[k * 128 + cl];
            float2 Zm = sz[(64 - k) * 128 + cl];
            float2 E = make_float2(0.5f * (Zk.x + Zm.x), 0.5f * (Zk.y - Zm.y));
            float2 D = make_float2(0.5f * (Zk.x - Zm.x), 0.5f * (Zk.y + Zm.y));
            float2 O = make_float2(D.y, -D.x);
            float2 p = cmul(stw[k], O);
            g_F[base + (size_t)k * ws] =
                __float22bfloat162_rn(make_float2(E.x + p.x, E.y + p.y));
            float2 Ec = make_float2(E.x, -E.y);
            float2 Oc = make_float2(O.x, -O.y);
            float2 qv = cmul(stw[64 - k], Oc);
            g_F[base + (size_t)(64 - k) * ws] =
                __float22bfloat162_rn(make_float2(Ec.x + qv.x, Ec.y + qv.y));
        }
    }
}

// ---------------------------------------------------------------------------
// Fused pass: FFT-H fwd + complex MLP (bf16 mma + ldmatrix) + FFT-H inv.
// 128-pt FFTs: 1 radix-16 pass (k=0, hardcoded twiddles) + 1 radix-8 pass.
// ---------------------------------------------------------------------------
__global__ __launch_bounds__(512, 1) void k_fused(const float* __restrict__ w1,
                                                  const float* __restrict__ b1,
                                                  const float* __restrict__ w2,
                                                  const float* __restrict__ b2) {
    extern __shared__ unsigned smu[];
    unsigned* sBIG = smu;                         // [128][196] words
    unsigned* sW1r = smu + 128 * 196;             // [96][52] words (bf16x2)
    unsigned* sW1i = sW1r + 96 * 52;
    unsigned* sW2r = sW1i + 96 * 52;
    unsigned* sW2i = sW2r + 96 * 52;
    float2* stw = (float2*)(sW2i + 96 * 52);      // [65]
    float2* tz = (float2*)sBIG;                   // tile view, row stride 98

    const int t = threadIdx.x;
    const int lane = t & 31, warp = t >> 5;
    if (t < 65) stw[t] = g_tw[t];
    const int n = blockIdx.x, wf = blockIdx.y, b = blockIdx.z;
    const size_t base = ((size_t)(b * WF + wf) * HH) * CC + n * BS;

    // Load tile (bit-reversed rows for DIT), bf16 -> f32
    for (int i = t; i < 128 * 96; i += 512) {
        int h = i / 96, col = i - h * 96;
        tz[(__brev((unsigned)h) >> 25) * 98 + col] =
            __bfloat1622float2(g_F[base + (size_t)h * CC + col]);
    }
    // Stage W1 and W2 transposed ([o][i]) as bf16
    {
        const float* w1r = w1 + n * BS * BS;
        const float* w1i = w1 + NB * BS * BS + n * BS * BS;
        const float* w2r = w2 + n * BS * BS;
        const float* w2i = w2 + NB * BS * BS + n * BS * BS;
        __nv_bfloat16* h1r = (__nv_bfloat16*)sW1r;
        __nv_bfloat16* h1i = (__nv_bfloat16*)sW1i;
        __nv_bfloat16* h2r = (__nv_bfloat16*)sW2r;
        __nv_bfloat16* h2i = (__nv_bfloat16*)sW2i;
        for (int idx = t; idx < 9216; idx += 512) {
            int i = idx / 96, o = idx - i * 96;   // i = input(k), o = output
            int ha = o * 104 + i;
            h1r[ha] = __float2bfloat16_rn(w1r[idx]);
            h1i[ha] = __float2bfloat16_rn(w1i[idx]);
            h2r[ha] = __float2bfloat16_rn(w2r[idx]);
            h2i[ha] = __float2bfloat16_rn(w2i[idx]);
        }
    }
    __syncthreads();

    // radix-8 (stages 4-6) work map: 16 groups x 96 cols = 1536 -> 3/thread
    int j8v[3], c8v[3];
#pragma unroll
    for (int r = 0; r < 3; r++) {
        int idx = r * 512 + t;
        j8v[r] = idx / 96;
        c8v[r] = idx - j8v[r] * 96;
    }

    // ---------------- forward FFT over h ----------------
    // pass 1: radix-16 (stages 0-3, k=0). 8 groups x 96 cols = 768 items.
#pragma unroll
    for (int rep = 0; rep < 2; rep++) {
        if (rep == 0 || t < 256) {
            int idx = rep * 512 + t;
            int j = idx / 96, col = idx - j * 96;
            float2* p = tz + (j * 16) * 98 + col;
            float2 xv[16];
#pragma unroll
            for (int m = 0; m < 16; m++) xv[m] = p[m * 98];
            bf16pt<false>(xv);
#pragma unroll
            for (int m = 0; m < 16; m++) p[m * 98] = xv[m];
        }
    }
    __syncthreads();
    // pass 2: radix-8 (stages 4-6), hf=16, k=j
    {
#pragma unroll
        for (int r = 0; r < 3; r++) {
            int j = j8v[r], col = c8v[r];
            float2 w[7];
            w[0] = stw[j << 2];
            w[1] = stw[j << 1];
            w[2] = stw[(j + 16) << 1];
#pragma unroll
            for (int qq = 0; qq < 4; qq++) w[3 + qq] = stw[j + qq * 16];
            float2* p = tz + j * 98 + col;
            float2 xv[8];
#pragma unroll
            for (int m = 0; m < 8; m++) xv[m] = p[(m * 16) * 98];
            bf8(xv, w);
#pragma unroll
            for (int m = 0; m < 8; m++) p[(m * 16) * 98] = xv[m];
        }
        __syncthreads();
    }

    // ---- deinterleave tile -> bf16 A (x 1/128), in place, per-row by warp --
    {
        const float s128 = 0.0078125f;
#pragma unroll
        for (int rr = 0; rr < 8; rr++) {
            int row = warp * 8 + rr;
            float4 q0 = *(float4*)&tz[row * 98 + 2 * lane];
            float4 q1 = make_float4(0.f, 0.f, 0.f, 0.f);
            if (lane < 16)
                q1 = *(float4*)&tz[row * 98 + 2 * (lane + 32)];
            __syncwarp();
            unsigned* Ar = sBIG + row * 196;
            Ar[lane] = bf2(q0.z * s128, q0.x * s128);
            Ar[48 + lane] = bf2(q0.w * s128, q0.y * s128);
            if (lane < 16) {
                Ar[lane + 32] = bf2(q1.z * s128, q1.x * s128);
                Ar[48 + lane + 32] = bf2(q1.w * s128, q1.y * s128);
            }
            __syncwarp();
        }
    }
    __syncthreads();

    // ---------------- MLP ----------------
    const int mgrp = warp & 3, ngrp = warp >> 2;
    const int nh = ngrp >> 1;
    const int jbase = (ngrp & 1) * 6;
    const int g = lane >> 2, tig = lane & 3;
    const int arow = mgrp * 32 + g;

    // ldmatrix lane addressing
    const unsigned sbigAddr = (unsigned)__cvta_generic_to_shared(sBIG);
    const int matq = lane >> 3;
    const unsigned aBase0 = sbigAddr +
        (unsigned)(((mgrp * 32 + (lane & 7) + (matq & 1) * 8) * 196 +
                    (matq >> 1) * 4) * 4);
    const unsigned aBase1 = aBase0 + 16u * 196u * 4u;
    const unsigned bOff0 = (unsigned)((((jbase * 8 + (matq >> 1) * 8 +
                                         (lane & 7)) * 52) + (matq & 1) * 4) * 4);
    const unsigned pStep = 16u * 52u * 4u;
    const unsigned w1lo = (unsigned)__cvta_generic_to_shared((nh == 0) ? sW1r : sW1i);
    const unsigned w1hi = (unsigned)__cvta_generic_to_shared((nh == 0) ? sW1i : sW1r);
    const unsigned w2lo = (unsigned)__cvta_generic_to_shared((nh == 0) ? sW2r : sW2i);
    const unsigned w2hi = (unsigned)__cvta_generic_to_shared((nh == 0) ? sW2i : sW2r);
    const unsigned sgnHi = (nh == 0) ? 0x80008000u : 0u;

    float acc[2][6][4];

    // ===== layer 1 =====
    {
        const float* bp = (nh == 0) ? (b1 + n * BS) : (b1 + NB * BS + n * BS);
#pragma unroll
        for (int j = 0; j < 6; j++) {
            int cih = (jbase + j) * 8 + 2 * tig;
            float bv0 = bp[cih], bv1 = bp[cih + 1];
#pragma unroll
            for (int mt = 0; mt < 2; mt++) {
                acc[mt][j][0] = bv0; acc[mt][j][1] = bv1;
                acc[mt][j][2] = bv0; acc[mt][j][3] = bv1;
            }
        }
#pragma unroll 1
        for (int kc = 0; kc < 12; kc++) {
            unsigned a0, a1, a2, a3, a4, a5, a6, a7;
            ldsm4(a0, a1, a2, a3, aBase0 + kc * 32);
            ldsm4(a4, a5, a6, a7, aBase1 + kc * 32);
            unsigned sgn = (kc < 6) ? 0u : sgnHi;
            unsigned wA = ((kc < 6) ? w1lo + kc * 32 : w1hi + (kc - 6) * 32) + bOff0;
            unsigned br[12];
#pragma unroll
            for (int p = 0; p < 3; p++) {
                unsigned r0, r1, r2, r3;
                ldsm4(r0, r1, r2, r3, wA + p * pStep);
                br[4 * p] = r0 ^ sgn;
                br[4 * p + 1] = r1 ^ sgn;
                br[4 * p + 2] = r2 ^ sgn;
                br[4 * p + 3] = r3 ^ sgn;
            }
#pragma unroll
            for (int j = 0; j < 6; j++) {
                mma16(acc[0][j], a0, a1, a2, a3, br[2 * j], br[2 * j + 1]);
                mma16(acc[1][j], a4, a5, a6, a7, br[2 * j], br[2 * j + 1]);
            }
        }
    }
    __syncthreads();  // all A reads done

    // write relu(O) over A (packed bf16x2)
#pragma unroll
    for (int j = 0; j < 6; j++) {
        int wcol = nh * 48 + (jbase + j) * 4 + tig;
#pragma unroll
        for (int mt = 0; mt < 2; mt++) {
            int r0 = arow + 16 * mt;
            sBIG[r0 * 196 + wcol] =
                bf2(fmaxf(acc[mt][j][1], 0.f), fmaxf(acc[mt][j][0], 0.f));
            sBIG[(r0 + 8) * 196 + wcol] =
                bf2(fmaxf(acc[mt][j][3], 0.f), fmaxf(acc[mt][j][2], 0.f));
        }
    }
    __syncthreads();

    // ===== layer 2 =====
    {
        const float* bp = (nh == 0) ? (b2 + n * BS) : (b2 + NB * BS + n * BS);
#pragma unroll
        for (int j = 0; j < 6; j++) {
            int cih = (jbase + j) * 8 + 2 * tig;
            float bv0 = bp[cih], bv1 = bp[cih + 1];
#pragma unroll
            for (int mt = 0; mt < 2; mt++) {
                acc[mt][j][0] = bv0; acc[mt][j][1] = bv1;
                acc[mt][j][2] = bv0; acc[mt][j][3] = bv1;
            }
        }
#pragma unroll 1
        for (int kc = 0; kc < 12; kc++) {
            unsigned a0, a1, a2, a3, a4, a5, a6, a7;
            ldsm4(a0, a1, a2, a3, aBase0 + kc * 32);
            ldsm4(a4, a5, a6, a7, aBase1 + kc * 32);
            unsigned sgn = (kc < 6) ? 0u : sgnHi;
            unsigned wA = ((kc < 6) ? w2lo + kc * 32 : w2hi + (kc - 6) * 32) + bOff0;
            unsigned br[12];
#pragma unroll
            for (int p = 0; p < 3; p++) {
                unsigned r0, r1, r2, r3;
                ldsm4(r0, r1, r2, r3, wA + p * pStep);
                br[4 * p] = r0 ^ sgn;
                br[4 * p + 1] = r1 ^ sgn;
                br[4 * p + 2] = r2 ^ sgn;
                br[4 * p + 3] = r3 ^ sgn;
            }
#pragma unroll
            for (int j = 0; j < 6; j++) {
                mma16(acc[0][j], a0, a1, a2, a3, br[2 * j], br[2 * j + 1]);
                mma16(acc[1][j], a4, a5, a6, a7, br[2 * j], br[2 * j + 1]);
            }
        }
    }
    __syncthreads();  // all O reads done

    // softshrink -> float2 tile (bit-reversed rows) for inverse FFT
    {
        float* Tf = (float*)sBIG;
#pragma unroll
        for (int j = 0; j < 6; j++) {
            int ch = (jbase + j) * 8 + 2 * tig;
#pragma unroll
            for (int mt = 0; mt < 2; mt++) {
                int r0 = arow + 16 * mt, r1 = r0 + 8;
                int br0 = __brev((unsigned)r0) >> 25;
                int br1 = __brev((unsigned)r1) >> 25;
                Tf[br0 * 196 + 2 * ch + nh] = sshrink(acc[mt][j][0]);
                Tf[br0 * 196 + 2 * (ch + 1) + nh] = sshrink(acc[mt][j][1]);
                Tf[br1 * 196 + 2 * ch + nh] = sshrink(acc[mt][j][2]);
                Tf[br1 * 196 + 2 * (ch + 1) + nh] = sshrink(acc[mt][j][3]);
            }
        }
    }
    __syncthreads();

    // ---------------- inverse FFT over h (conj twiddles) ----------------
#pragma unroll
    for (int rep = 0; rep < 2; rep++) {
        if (rep == 0 || t < 256) {
            int idx = rep * 512 + t;
            int j = idx / 96, col = idx - j * 96;
            float2* p = tz + (j * 16) * 98 + col;
            float2 xv[16];
#pragma unroll
            for (int m = 0; m < 16; m++) xv[m] = p[m * 98];
            bf16pt<true>(xv);
#pragma unroll
            for (int m = 0; m < 16; m++) p[m * 98] = xv[m];
        }
    }
    __syncthreads();
    {
#pragma unroll
        for (int r = 0; r < 3; r++) {
            int j = j8v[r], col = c8v[r];
            float2 w[7];
            w[0] = stw[j << 2];
            w[1] = stw[j << 1];
            w[2] = stw[(j + 16) << 1];
#pragma unroll
            for (int qq = 0; qq < 4; qq++) w[3 + qq] = stw[j + qq * 16];
#pragma unroll
            for (int m = 0; m < 7; m++) w[m].y = -w[m].y;
            float2* p = tz + j * 98 + col;
            float2 xv[8];
#pragma unroll
            for (int m = 0; m < 8; m++) xv[m] = p[(m * 16) * 98];
            bf8(xv, w);
#pragma unroll
            for (int m = 0; m < 8; m++) p[(m * 16) * 98] = xv[m];
        }
        __syncthreads();
    }

    // Store back (f32 -> bf16x2)
    for (int i = t; i < 128 * 96; i += 512) {
        int h = i / 96, col = i - h * 96;
        g_F[base + (size_t)h * CC + col] = __float22bfloat162_rn(tz[h * 98 + col]);
    }
}

// ---------------------------------------------------------------------------
// Pass 5: inverse real FFT length 128 along W + 1/128 scale + residual add.
// 64-pt inverse FFT with TWO radix-8 passes (conj twiddles).
// C2R semantics: imag of DC & Nyquist ignored.
// ---------------------------------------------------------------------------
__global__ __launch_bounds__(512, 2) void k_inv_w(const float* __restrict__ x,
                                                  float* __restrict__ out) {
    extern __shared__ float2 sm2[];
    float2* sz = sm2;               // [64][128]
    float2* stw = sm2 + 64 * 128;   // [65]
    const int t = threadIdx.x;
    if (t < 65) stw[t] = g_tw[t];
    __syncthreads();
    const int cl = t & 127, q = t >> 7;
    const int b = blockIdx.z, h = blockIdx.y;
    const int c = blockIdx.x * 128 + cl;
    size_t base = ((size_t)b * WF * HH + h) * CC + c;
    const size_t ws = (size_t)HH * CC;

#pragma unroll
    for (int jj = 0; jj < 8; jj++) {
        int idx = q * 8 + jj;
        if (idx == 0) {
            float2 X0 = __bfloat1622float2(g_F[base]);
            float2 X64 = __bfloat1622float2(g_F[base + 64 * ws]);
            sz[cl] = make_float2(X0.x + X64.x, X0.x - X64.x);  // imag dropped
            float2 X32 = __bfloat1622float2(g_F[base + 32 * ws]);
            sz[1 * 128 + cl] = make_float2(2.f * X32.x, -2.f * X32.y);
        } else {
            int k = idx;  // 1..31
            float2 Xk = __bfloat1622float2(g_F[base + (size_t)k * ws]);
            float2 Xm = __bfloat1622float2(g_F[base + (size_t)(64 - k) * ws]);
            float2 A = make_float2(Xk.x + Xm.x, Xk.y - Xm.y);
            float2 D = make_float2(Xk.x - Xm.x, Xk.y + Xm.y);
            float2 wc = make_float2(stw[k].x, -stw[k].y);
            float2 tv = cmul(wc, D);
            sz[(__brev((unsigned)k) >> 26) * 128 + cl] =
                make_float2(A.x - tv.y, A.y + tv.x);
            float2 A2 = make_float2(Xm.x + Xk.x, Xm.y - Xk.y);
            float2 D2 = make_float2(Xm.x - Xk.x, Xm.y + Xk.y);
            float2 wc2 = make_float2(stw[64 - k].x, -stw[64 - k].y);
            float2 t2 = cmul(wc2, D2);
            sz[(__brev((unsigned)(64 - k)) >> 26) * 128 + cl] =
                make_float2(A2.x - t2.y, A2.y + t2.x);
        }
    }
    __syncthreads();

#pragma unroll
    for (int s = 0; s <= 3; s += 3) {
        int hf = 1 << s;
#pragma unroll
        for (int rr = 0; rr < 2; rr++) {
            int j = q * 2 + rr;
            int k = j & (hf - 1);
            int i0 = ((j >> s) << (s + 3)) + k;
            float2 w[7];
            w[0] = stw[k << (6 - s)];
            w[1] = stw[k << (5 - s)];
            w[2] = stw[(k + hf) << (5 - s)];
#pragma unroll
            for (int qq = 0; qq < 4; qq++) w[3 + qq] = stw[(k + qq * hf) << (4 - s)];
#pragma unroll
            for (int m = 0; m < 7; m++) w[m].y = -w[m].y;
            float2 xv[8];
#pragma unroll
            for (int m = 0; m < 8; m++) xv[m] = sz[(i0 + m * hf) * 128 + cl];
            bf8(xv, w);
#pragma unroll
            for (int m = 0; m < 8; m++) sz[(i0 + m * hf) * 128 + cl] = xv[m];
        }
        __syncthreads();
    }

    const size_t xbase = ((size_t)(b * HH + h) * WW) * CC + c;
#pragma unroll
    for (int mm = 0; mm < 16; mm++) {
        int m = q * 16 + mm;
        float2 z = sz[m * 128 + cl];
        size_t i0 = xbase + (size_t)(2 * m) * CC;
        size_t i1 = xbase + (size_t)(2 * m + 1) * CC;
        out[i0] = z.x * (1.f / 128.f) + x[i0];
        out[i1] = z.y * (1.f / 128.f) + x[i1];
    }
}

// ---------------------------------------------------------------------------
extern "C" void kernel_launch(void* const* d_in, const int* in_sizes, int n_in,
                              void* d_out, int out_size) {
    const float* x  = (const float*)d_in[0];
    const float* w1 = (const float*)d_in[1];
    const float* b1 = (const float*)d_in[2];
    const float* w2 = (const float*)d_in[3];
    const float* b2 = (const float*)d_in[4];
    float* out = (float*)d_out;

    const size_t sm_fftw = (size_t)(64 * 128 + 65) * sizeof(float2);   // 66056
    const size_t sm_fus  = (size_t)(128 * 196 + 4 * 96 * 52) * 4 + 65 * 8; // ~181 KB

    cudaFuncSetAttribute(k_fwd_w, cudaFuncAttributeMaxDynamicSharedMemorySize, (int)sm_fftw);
    cudaFuncSetAttribute(k_fused, cudaFuncAttributeMaxDynamicSharedMemorySize, (int)sm_fus);
    cudaFuncSetAttribute(k_inv_w, cudaFuncAttributeMaxDynamicSharedMemorySize, (int)sm_fftw);

    k_init_tw<<<1, 128>>>();
    k_fwd_w<<<dim3(6, 128, 8), 512, sm_fftw>>>(x);
    k_fused<<<dim3(8, 65, 8), 512, sm_fus>>>(w1, b1, w2, b2);
    k_inv_w<<<dim3(6, 128, 8), 512, sm_fftw>>>(x, out);
}

// round 11
// speedup vs baseline: 4.4282x; 1.1701x over previous
#include <cuda_runtime.h>
#include <cuda_bf16.h>
#include <math.h>

#define BB 8
#define HH 128
#define WW 128
#define CC 768
#define NB 8
#define BS 96
#define WF 65
#define LAMBDA 0.01f

#define C4F 0.70710678118654752440f
#define C8F 0.92387953251128675613f
#define S8F 0.38268343236508977173f

// Frequency-domain scratch (bf16 transport): [b][wf][h][c]
__device__ __nv_bfloat162 g_F[(size_t)BB * WF * HH * CC];
// Twiddles: g_tw[k] = exp(-2*pi*i*k/128), k=0..64
__device__ float2 g_tw[65];

__device__ __forceinline__ float2 cmul(float2 a, float2 b) {
    return make_float2(a.x * b.x - a.y * b.y, a.x * b.y + a.y * b.x);
}

// pack two floats to bf16x2 word
__device__ __forceinline__ unsigned bf2(float hi, float lo) {
    unsigned r;
    asm("cvt.rn.bf16x2.f32 %0, %1, %2;" : "=r"(r) : "f"(hi), "f"(lo));
    return r;
}

__device__ __forceinline__ void mma16(float c[4], unsigned a0, unsigned a1,
                                      unsigned a2, unsigned a3,
                                      unsigned b0, unsigned b1) {
    asm volatile(
        "mma.sync.aligned.m16n8k16.row.col.f32.bf16.bf16.f32 "
        "{%0,%1,%2,%3}, {%4,%5,%6,%7}, {%8,%9}, {%0,%1,%2,%3};"
        : "+f"(c[0]), "+f"(c[1]), "+f"(c[2]), "+f"(c[3])
        : "r"(a0), "r"(a1), "r"(a2), "r"(a3), "r"(b0), "r"(b1));
}

__device__ __forceinline__ void ldsm4(unsigned& r0, unsigned& r1,
                                      unsigned& r2, unsigned& r3,
                                      unsigned addr) {
    asm volatile(
        "ldmatrix.sync.aligned.m8n8.x4.shared.b16 {%0,%1,%2,%3}, [%4];"
        : "=r"(r0), "=r"(r1), "=r"(r2), "=r"(r3)
        : "r"(addr));
}

__device__ __forceinline__ float sshrink(float v) {
    return v > LAMBDA ? v - LAMBDA : (v < -LAMBDA ? v + LAMBDA : 0.f);
}

__global__ void k_init_tw() {
    int i = threadIdx.x;
    if (i < 65) {
        double a = -2.0 * 3.14159265358979323846264338327950288 * (double)i / 128.0;
        g_tw[i] = make_float2((float)cos(a), (float)sin(a));
    }
}

// ----- register butterflies -----
template <bool INV>
__device__ __forceinline__ float2 rot90(float2 v) {
    return INV ? make_float2(-v.y, v.x) : make_float2(v.y, -v.x);
}

template <bool INV>
__device__ __forceinline__ void bf4_0(float2& x0, float2& x1, float2& x2,
                                      float2& x3) {
    float2 y0 = make_float2(x0.x + x1.x, x0.y + x1.y);
    float2 y1 = make_float2(x0.x - x1.x, x0.y - x1.y);
    float2 y2 = make_float2(x2.x + x3.x, x2.y + x3.y);
    float2 y3 = make_float2(x2.x - x3.x, x2.y - x3.y);
    float2 u3 = rot90<INV>(y3);
    x0 = make_float2(y0.x + y2.x, y0.y + y2.y);
    x2 = make_float2(y0.x - y2.x, y0.y - y2.y);
    x1 = make_float2(y1.x + u3.x, y1.y + u3.y);
    x3 = make_float2(y1.x - u3.x, y1.y - u3.y);
}

template <bool INV>
__device__ __forceinline__ void bf8_0(float2* x) {
    bf4_0<INV>(x[0], x[1], x[2], x[3]);
    bf4_0<INV>(x[4], x[5], x[6], x[7]);
    const float I = INV ? 1.f : -1.f;
    const float2 t1 = make_float2(C4F, I * C4F);
    const float2 t3 = make_float2(-C4F, I * C4F);
    { float2 a = x[0], u = x[4];
      x[0] = make_float2(a.x + u.x, a.y + u.y);
      x[4] = make_float2(a.x - u.x, a.y - u.y); }
    { float2 a = x[1], u = cmul(x[5], t1);
      x[1] = make_float2(a.x + u.x, a.y + u.y);
      x[5] = make_float2(a.x - u.x, a.y - u.y); }
    { float2 a = x[2], u = rot90<INV>(x[6]);
      x[2] = make_float2(a.x + u.x, a.y + u.y);
      x[6] = make_float2(a.x - u.x, a.y - u.y); }
    { float2 a = x[3], u = cmul(x[7], t3);
      x[3] = make_float2(a.x + u.x, a.y + u.y);
      x[7] = make_float2(a.x - u.x, a.y - u.y); }
}

template <bool INV>
__device__ __forceinline__ void bf16pt(float2* x) {
    bf8_0<INV>(x);
    bf8_0<INV>(x + 8);
    const float I = INV ? 1.f : -1.f;
    const float2 w1 = make_float2(C8F, I * S8F);
    const float2 w2 = make_float2(C4F, I * C4F);
    const float2 w3 = make_float2(S8F, I * C8F);
    const float2 w5 = make_float2(-S8F, I * C8F);
    const float2 w6 = make_float2(-C4F, I * C4F);
    const float2 w7 = make_float2(-C8F, I * S8F);
#pragma unroll
    for (int m = 0; m < 8; m++) {
        float2 u;
        if (m == 0) u = x[8];
        else if (m == 1) u = cmul(x[9], w1);
        else if (m == 2) u = cmul(x[10], w2);
        else if (m == 3) u = cmul(x[11], w3);
        else if (m == 4) u = rot90<INV>(x[12]);
        else if (m == 5) u = cmul(x[13], w5);
        else if (m == 6) u = cmul(x[14], w6);
        else u = cmul(x[15], w7);
        float2 a = x[m];
        x[m] = make_float2(a.x + u.x, a.y + u.y);
        x[m + 8] = make_float2(a.x - u.x, a.y - u.y);
    }
}

// Generic radix-2^3 with provided twiddles (w[0]; w[1],w[2]; w[3..6]).
__device__ __forceinline__ void bf8(float2 x[8], const float2 w[7]) {
    float2 t1 = cmul(x[1], w[0]), t3 = cmul(x[3], w[0]);
    float2 y0 = make_float2(x[0].x + t1.x, x[0].y + t1.y);
    float2 y1 = make_float2(x[0].x - t1.x, x[0].y - t1.y);
    float2 y2 = make_float2(x[2].x + t3.x, x[2].y + t3.y);
    float2 y3 = make_float2(x[2].x - t3.x, x[2].y - t3.y);
    float2 u2 = cmul(y2, w[1]), u3 = cmul(y3, w[2]);
    x[0] = make_float2(y0.x + u2.x, y0.y + u2.y);
    x[2] = make_float2(y0.x - u2.x, y0.y - u2.y);
    x[1] = make_float2(y1.x + u3.x, y1.y + u3.y);
    x[3] = make_float2(y1.x - u3.x, y1.y - u3.y);
    float2 t5 = cmul(x[5], w[0]), t7 = cmul(x[7], w[0]);
    float2 z0 = make_float2(x[4].x + t5.x, x[4].y + t5.y);
    float2 z1 = make_float2(x[4].x - t5.x, x[4].y - t5.y);
    float2 z2 = make_float2(x[6].x + t7.x, x[6].y + t7.y);
    float2 z3 = make_float2(x[6].x - t7.x, x[6].y - t7.y);
    float2 v2 = cmul(z2, w[1]), v3 = cmul(z3, w[2]);
    x[4] = make_float2(z0.x + v2.x, z0.y + v2.y);
    x[6] = make_float2(z0.x - v2.x, z0.y - v2.y);
    x[5] = make_float2(z1.x + v3.x, z1.y + v3.y);
    x[7] = make_float2(z1.x - v3.x, z1.y - v3.y);
#pragma unroll
    for (int q = 0; q < 4; q++) {
        float2 u = cmul(x[q + 4], w[3 + q]);
        float2 a = x[q];
        x[q] = make_float2(a.x + u.x, a.y + u.y);
        x[q + 4] = make_float2(a.x - u.x, a.y - u.y);
    }
}

// ---------------------------------------------------------------------------
// Pass 1: real FFT length 128 along W (pack-in-pairs), 2 radix-8 passes.
// ---------------------------------------------------------------------------
__global__ __launch_bounds__(512, 2) void k_fwd_w(const float* __restrict__ x) {
    extern __shared__ float2 sm2[];
    float2* sz = sm2;               // [64][128]
    float2* stw = sm2 + 64 * 128;   // [65]
    const int t = threadIdx.x;
    if (t < 65) stw[t] = g_tw[t];
    const int cl = t & 127, q = t >> 7;
    const int b = blockIdx.z, h = blockIdx.y;
    const int c = blockIdx.x * 128 + cl;
    const float* xp = x + ((size_t)(b * HH + h) * WW) * CC + c;

#pragma unroll
    for (int mm = 0; mm < 16; mm++) {
        int m = q * 16 + mm;
        float re = xp[(size_t)(2 * m) * CC];
        float im = xp[(size_t)(2 * m + 1) * CC];
        sz[(__brev((unsigned)m) >> 26) * 128 + cl] = make_float2(re, im);
    }
    __syncthreads();

#pragma unroll
    for (int s = 0; s <= 3; s += 3) {
        int hf = 1 << s;
#pragma unroll
        for (int rr = 0; rr < 2; rr++) {
            int j = q * 2 + rr;
            int k = j & (hf - 1);
            int i0 = ((j >> s) << (s + 3)) + k;
            float2 w[7];
            w[0] = stw[k << (6 - s)];
            w[1] = stw[k << (5 - s)];
            w[2] = stw[(k + hf) << (5 - s)];
#pragma unroll
            for (int qq = 0; qq < 4; qq++) w[3 + qq] = stw[(k + qq * hf) << (4 - s)];
            float2 xv[8];
#pragma unroll
            for (int m = 0; m < 8; m++) xv[m] = sz[(i0 + m * hf) * 128 + cl];
            bf8(xv, w);
#pragma unroll
            for (int m = 0; m < 8; m++) sz[(i0 + m * hf) * 128 + cl] = xv[m];
        }
        __syncthreads();
    }

    size_t base = ((size_t)b * WF * HH + h) * CC + c;
    const size_t ws = (size_t)HH * CC;
#pragma unroll
    for (int jj = 0; jj < 8; jj++) {
        int idx = q * 8 + jj;
        if (idx == 0) {
            float2 Z0 = sz[cl];
            g_F[base] = __float22bfloat162_rn(make_float2(Z0.x + Z0.y, 0.f));
            g_F[base + 64 * ws] = __float22bfloat162_rn(make_float2(Z0.x - Z0.y, 0.f));
            float2 Z32 = sz[32 * 128 + cl];
            g_F[base + 32 * ws] = __float22bfloat162_rn(make_float2(Z32.x, -Z32.y));
        } else {
            int k = idx;  // 1..31
            float2 Zk = sz[k * 128 + cl];
            float2 Zm = sz[(64 - k) * 128 + cl];
            float2 E = make_float2(0.5f * (Zk.x + Zm.x), 0.5f * (Zk.y - Zm.y));
            float2 D = make_float2(0.5f * (Zk.x - Zm.x), 0.5f * (Zk.y + Zm.y));
            float2 O = make_float2(D.y, -D.x);
            float2 p = cmul(stw[k], O);
            g_F[base + (size_t)k * ws] =
                __float22bfloat162_rn(make_float2(E.x + p.x, E.y + p.y));
            float2 Ec = make_float2(E.x, -E.y);
            float2 Oc = make_float2(O.x, -O.y);
            float2 qv = cmul(stw[64 - k], Oc);
            g_F[base + (size_t)(64 - k) * ws] =
                __float22bfloat162_rn(make_float2(Ec.x + qv.x, Ec.y + qv.y));
        }
    }
}

// ---------------------------------------------------------------------------
// Fused pass: FFT-H fwd + complex MLP (bf16 mma + ldmatrix) + FFT-H inv.
// Forward pass-1 gathers straight from g_F (bit-reversal is an involution);
// inverse pass-2 scatters straight to g_F. Tile lives only between passes.
// ---------------------------------------------------------------------------
__global__ __launch_bounds__(512, 1) void k_fused(const float* __restrict__ w1,
                                                  const float* __restrict__ b1,
                                                  const float* __restrict__ w2,
                                                  const float* __restrict__ b2) {
    extern __shared__ unsigned smu[];
    unsigned* sBIG = smu;                         // [128][196] words
    unsigned* sW1r = smu + 128 * 196;             // [96][52] words (bf16x2)
    unsigned* sW1i = sW1r + 96 * 52;
    unsigned* sW2r = sW1i + 96 * 52;
    unsigned* sW2i = sW2r + 96 * 52;
    float2* stw = (float2*)(sW2i + 96 * 52);      // [65]
    float2* tz = (float2*)sBIG;                   // tile view, row stride 98

    const int t = threadIdx.x;
    const int lane = t & 31, warp = t >> 5;
    if (t < 65) stw[t] = g_tw[t];
    const int n = blockIdx.x, wf = blockIdx.y, b = blockIdx.z;
    const size_t base = ((size_t)(b * WF + wf) * HH) * CC + n * BS;

    // Stage W1 and W2 transposed ([o][i]) as bf16
    {
        const float* w1r = w1 + n * BS * BS;
        const float* w1i = w1 + NB * BS * BS + n * BS * BS;
        const float* w2r = w2 + n * BS * BS;
        const float* w2i = w2 + NB * BS * BS + n * BS * BS;
        __nv_bfloat16* h1r = (__nv_bfloat16*)sW1r;
        __nv_bfloat16* h1i = (__nv_bfloat16*)sW1i;
        __nv_bfloat16* h2r = (__nv_bfloat16*)sW2r;
        __nv_bfloat16* h2i = (__nv_bfloat16*)sW2i;
        for (int idx = t; idx < 9216; idx += 512) {
            int i = idx / 96, o = idx - i * 96;   // i = input(k), o = output
            int ha = o * 104 + i;
            h1r[ha] = __float2bfloat16_rn(w1r[idx]);
            h1i[ha] = __float2bfloat16_rn(w1i[idx]);
            h2r[ha] = __float2bfloat16_rn(w2r[idx]);
            h2i[ha] = __float2bfloat16_rn(w2i[idx]);
        }
    }

    // radix-8 (stages 4-6) work map: 16 groups x 96 cols = 1536 -> 3/thread
    int j8v[3], c8v[3];
#pragma unroll
    for (int r = 0; r < 3; r++) {
        int idx = r * 512 + t;
        j8v[r] = idx / 96;
        c8v[r] = idx - j8v[r] * 96;
    }

    // ---------------- forward FFT over h ----------------
    // pass 1: radix-16 (stages 0-3, k=0), gathering directly from g_F.
    // tile[row] holds g_F[brev7(row)]; brev7 is an involution.
#pragma unroll
    for (int rep = 0; rep < 2; rep++) {
        if (rep == 0 || t < 256) {
            int idx = rep * 512 + t;
            int j = idx / 96, col = idx - j * 96;
            float2 xv[16];
#pragma unroll
            for (int m = 0; m < 16; m++) {
                int h = __brev((unsigned)(j * 16 + m)) >> 25;
                xv[m] = __bfloat1622float2(g_F[base + (size_t)h * CC + col]);
            }
            bf16pt<false>(xv);
            float2* p = tz + (j * 16) * 98 + col;
#pragma unroll
            for (int m = 0; m < 16; m++) p[m * 98] = xv[m];
        }
    }
    __syncthreads();  // also covers weight staging + stw
    // pass 2: radix-8 (stages 4-6), hf=16, k=j
    {
#pragma unroll
        for (int r = 0; r < 3; r++) {
            int j = j8v[r], col = c8v[r];
            float2 w[7];
            w[0] = stw[j << 2];
            w[1] = stw[j << 1];
            w[2] = stw[(j + 16) << 1];
#pragma unroll
            for (int qq = 0; qq < 4; qq++) w[3 + qq] = stw[j + qq * 16];
            float2* p = tz + j * 98 + col;
            float2 xv[8];
#pragma unroll
            for (int m = 0; m < 8; m++) xv[m] = p[(m * 16) * 98];
            bf8(xv, w);
#pragma unroll
            for (int m = 0; m < 8; m++) p[(m * 16) * 98] = xv[m];
        }
        __syncthreads();
    }

    // ---- deinterleave tile -> bf16 A (x 1/128), in place, per-row by warp --
    {
        const float s128 = 0.0078125f;
#pragma unroll
        for (int rr = 0; rr < 8; rr++) {
            int row = warp * 8 + rr;
            float4 q0 = *(float4*)&tz[row * 98 + 2 * lane];
            float4 q1 = make_float4(0.f, 0.f, 0.f, 0.f);
            if (lane < 16)
                q1 = *(float4*)&tz[row * 98 + 2 * (lane + 32)];
            __syncwarp();
            unsigned* Ar = sBIG + row * 196;
            Ar[lane] = bf2(q0.z * s128, q0.x * s128);
            Ar[48 + lane] = bf2(q0.w * s128, q0.y * s128);
            if (lane < 16) {
                Ar[lane + 32] = bf2(q1.z * s128, q1.x * s128);
                Ar[48 + lane + 32] = bf2(q1.w * s128, q1.y * s128);
            }
            __syncwarp();
        }
    }
    __syncthreads();

    // ---------------- MLP ----------------
    const int mgrp = warp & 3, ngrp = warp >> 2;
    const int nh = ngrp >> 1;
    const int jbase = (ngrp & 1) * 6;
    const int g = lane >> 2, tig = lane & 3;
    const int arow = mgrp * 32 + g;

    const unsigned sbigAddr = (unsigned)__cvta_generic_to_shared(sBIG);
    const int matq = lane >> 3;
    const unsigned aBase0 = sbigAddr +
        (unsigned)(((mgrp * 32 + (lane & 7) + (matq & 1) * 8) * 196 +
                    (matq >> 1) * 4) * 4);
    const unsigned aBase1 = aBase0 + 16u * 196u * 4u;
    const unsigned bOff0 = (unsigned)((((jbase * 8 + (matq >> 1) * 8 +
                                         (lane & 7)) * 52) + (matq & 1) * 4) * 4);
    const unsigned pStep = 16u * 52u * 4u;
    const unsigned w1lo = (unsigned)__cvta_generic_to_shared((nh == 0) ? sW1r : sW1i);
    const unsigned w1hi = (unsigned)__cvta_generic_to_shared((nh == 0) ? sW1i : sW1r);
    const unsigned w2lo = (unsigned)__cvta_generic_to_shared((nh == 0) ? sW2r : sW2i);
    const unsigned w2hi = (unsigned)__cvta_generic_to_shared((nh == 0) ? sW2i : sW2r);
    const unsigned sgnHi = (nh == 0) ? 0x80008000u : 0u;

    float acc[2][6][4];

    // ===== layer 1 =====
    {
        const float* bp = (nh == 0) ? (b1 + n * BS) : (b1 + NB * BS + n * BS);
#pragma unroll
        for (int j = 0; j < 6; j++) {
            int cih = (jbase + j) * 8 + 2 * tig;
            float bv0 = bp[cih], bv1 = bp[cih + 1];
#pragma unroll
            for (int mt = 0; mt < 2; mt++) {
                acc[mt][j][0] = bv0; acc[mt][j][1] = bv1;
                acc[mt][j][2] = bv0; acc[mt][j][3] = bv1;
            }
        }
#pragma unroll 2
        for (int kc = 0; kc < 12; kc++) {
            unsigned a0, a1, a2, a3, a4, a5, a6, a7;
            ldsm4(a0, a1, a2, a3, aBase0 + kc * 32);
            ldsm4(a4, a5, a6, a7, aBase1 + kc * 32);
            unsigned sgn = (kc < 6) ? 0u : sgnHi;
            unsigned wA = ((kc < 6) ? w1lo + kc * 32 : w1hi + (kc - 6) * 32) + bOff0;
            unsigned br[12];
#pragma unroll
            for (int p = 0; p < 3; p++) {
                unsigned r0, r1, r2, r3;
                ldsm4(r0, r1, r2, r3, wA + p * pStep);
                br[4 * p] = r0 ^ sgn;
                br[4 * p + 1] = r1 ^ sgn;
                br[4 * p + 2] = r2 ^ sgn;
                br[4 * p + 3] = r3 ^ sgn;
            }
#pragma unroll
            for (int j = 0; j < 6; j++) {
                mma16(acc[0][j], a0, a1, a2, a3, br[2 * j], br[2 * j + 1]);
                mma16(acc[1][j], a4, a5, a6, a7, br[2 * j], br[2 * j + 1]);
            }
        }
    }
    __syncthreads();  // all A reads done

    // write relu(O) over A (packed bf16x2)
#pragma unroll
    for (int j = 0; j < 6; j++) {
        int wcol = nh * 48 + (jbase + j) * 4 + tig;
#pragma unroll
        for (int mt = 0; mt < 2; mt++) {
            int r0 = arow + 16 * mt;
            sBIG[r0 * 196 + wcol] =
                bf2(fmaxf(acc[mt][j][1], 0.f), fmaxf(acc[mt][j][0], 0.f));
            sBIG[(r0 + 8) * 196 + wcol] =
                bf2(fmaxf(acc[mt][j][3], 0.f), fmaxf(acc[mt][j][2], 0.f));
        }
    }
    __syncthreads();

    // ===== layer 2 =====
    {
        const float* bp = (nh == 0) ? (b2 + n * BS) : (b2 + NB * BS + n * BS);
#pragma unroll
        for (int j = 0; j < 6; j++) {
            int cih = (jbase + j) * 8 + 2 * tig;
            float bv0 = bp[cih], bv1 = bp[cih + 1];
#pragma unroll
            for (int mt = 0; mt < 2; mt++) {
                acc[mt][j][0] = bv0; acc[mt][j][1] = bv1;
                acc[mt][j][2] = bv0; acc[mt][j][3] = bv1;
            }
        }
#pragma unroll 2
        for (int kc = 0; kc < 12; kc++) {
            unsigned a0, a1, a2, a3, a4, a5, a6, a7;
            ldsm4(a0, a1, a2, a3, aBase0 + kc * 32);
            ldsm4(a4, a5, a6, a7, aBase1 + kc * 32);
            unsigned sgn = (kc < 6) ? 0u : sgnHi;
            unsigned wA = ((kc < 6) ? w2lo + kc * 32 : w2hi + (kc - 6) * 32) + bOff0;
            unsigned br[12];
#pragma unroll
            for (int p = 0; p < 3; p++) {
                unsigned r0, r1, r2, r3;
                ldsm4(r0, r1, r2, r3, wA + p * pStep);
                br[4 * p] = r0 ^ sgn;
                br[4 * p + 1] = r1 ^ sgn;
                br[4 * p + 2] = r2 ^ sgn;
                br[4 * p + 3] = r3 ^ sgn;
            }
#pragma unroll
            for (int j = 0; j < 6; j++) {
                mma16(acc[0][j], a0, a1, a2, a3, br[2 * j], br[2 * j + 1]);
                mma16(acc[1][j], a4, a5, a6, a7, br[2 * j], br[2 * j + 1]);
            }
        }
    }
    __syncthreads();  // all O reads done

    // softshrink -> float2 tile (bit-reversed rows) for inverse FFT
    {
        float* Tf = (float*)sBIG;
#pragma unroll
        for (int j = 0; j < 6; j++) {
            int ch = (jbase + j) * 8 + 2 * tig;
#pragma unroll
            for (int mt = 0; mt < 2; mt++) {
                int r0 = arow + 16 * mt, r1 = r0 + 8;
                int br0 = __brev((unsigned)r0) >> 25;
                int br1 = __brev((unsigned)r1) >> 25;
                Tf[br0 * 196 + 2 * ch + nh] = sshrink(acc[mt][j][0]);
                Tf[br0 * 196 + 2 * (ch + 1) + nh] = sshrink(acc[mt][j][1]);
                Tf[br1 * 196 + 2 * ch + nh] = sshrink(acc[mt][j][2]);
                Tf[br1 * 196 + 2 * (ch + 1) + nh] = sshrink(acc[mt][j][3]);
            }
        }
    }
    __syncthreads();

    // ---------------- inverse FFT over h (conj twiddles) ----------------
#pragma unroll
    for (int rep = 0; rep < 2; rep++) {
        if (rep == 0 || t < 256) {
            int idx = rep * 512 + t;
            int j = idx / 96, col = idx - j * 96;
            float2* p = tz + (j * 16) * 98 + col;
            float2 xv[16];
#pragma unroll
            for (int m = 0; m < 16; m++) xv[m] = p[m * 98];
            bf16pt<true>(xv);
#pragma unroll
            for (int m = 0; m < 16; m++) p[m * 98] = xv[m];
        }
    }
    __syncthreads();
    // pass 2: radix-8, scatter results directly to g_F
    {
#pragma unroll
        for (int r = 0; r < 3; r++) {
            int j = j8v[r], col = c8v[r];
            float2 w[7];
            w[0] = stw[j << 2];
            w[1] = stw[j << 1];
            w[2] = stw[(j + 16) << 1];
#pragma unroll
            for (int qq = 0; qq < 4; qq++) w[3 + qq] = stw[j + qq * 16];
#pragma unroll
            for (int m = 0; m < 7; m++) w[m].y = -w[m].y;
            float2* p = tz + j * 98 + col;
            float2 xv[8];
#pragma unroll
            for (int m = 0; m < 8; m++) xv[m] = p[(m * 16) * 98];
            bf8(xv, w);
#pragma unroll
            for (int m = 0; m < 8; m++)
                g_F[base + (size_t)(j + m * 16) * CC + col] =
                    __float22bfloat162_rn(xv[m]);
        }
    }
}

// ---------------------------------------------------------------------------
// Pass 5: inverse real FFT length 128 along W + 1/128 scale + residual add.
// 64-pt inverse FFT with TWO radix-8 passes (conj twiddles).
// C2R semantics: imag of DC & Nyquist ignored.
// ---------------------------------------------------------------------------
__global__ __launch_bounds__(512, 2) void k_inv_w(const float* __restrict__ x,
                                                  float* __restrict__ out) {
    extern __shared__ float2 sm2[];
    float2* sz = sm2;               // [64][128]
    float2* stw = sm2 + 64 * 128;   // [65]
    const int t = threadIdx.x;
    if (t < 65) stw[t] = g_tw[t];
    __syncthreads();
    const int cl = t & 127, q = t >> 7;
    const int b = blockIdx.z, h = blockIdx.y;
    const int c = blockIdx.x * 128 + cl;
    size_t base = ((size_t)b * WF * HH + h) * CC + c;
    const size_t ws = (size_t)HH * CC;

#pragma unroll
    for (int jj = 0; jj < 8; jj++) {
        int idx = q * 8 + jj;
        if (idx == 0) {
            float2 X0 = __bfloat1622float2(g_F[base]);
            float2 X64 = __bfloat1622float2(g_F[base + 64 * ws]);
            sz[cl] = make_float2(X0.x + X64.x, X0.x - X64.x);  // imag dropped
            float2 X32 = __bfloat1622float2(g_F[base + 32 * ws]);
            sz[1 * 128 + cl] = make_float2(2.f * X32.x, -2.f * X32.y);
        } else {
            int k = idx;  // 1..31
            float2 Xk = __bfloat1622float2(g_F[base + (size_t)k * ws]);
            float2 Xm = __bfloat1622float2(g_F[base + (size_t)(64 - k) * ws]);
            float2 A = make_float2(Xk.x + Xm.x, Xk.y - Xm.y);
            float2 D = make_float2(Xk.x - Xm.x, Xk.y + Xm.y);
            float2 wc = make_float2(stw[k].x, -stw[k].y);
            float2 tv = cmul(wc, D);
            sz[(__brev((unsigned)k) >> 26) * 128 + cl] =
                make_float2(A.x - tv.y, A.y + tv.x);
            float2 A2 = make_float2(Xm.x + Xk.x, Xm.y - Xk.y);
            float2 D2 = make_float2(Xm.x - Xk.x, Xm.y + Xk.y);
            float2 wc2 = make_float2(stw[64 - k].x, -stw[64 - k].y);
            float2 t2 = cmul(wc2, D2);
            sz[(__brev((unsigned)(64 - k)) >> 26) * 128 + cl] =
                make_float2(A2.x - t2.y, A2.y + t2.x);
        }
    }
    __syncthreads();

#pragma unroll
    for (int s = 0; s <= 3; s += 3) {
        int hf = 1 << s;
#pragma unroll
        for (int rr = 0; rr < 2; rr++) {
            int j = q * 2 + rr;
            int k = j & (hf - 1);
            int i0 = ((j >> s) << (s + 3)) + k;
            float2 w[7];
            w[0] = stw[k << (6 - s)];
            w[1] = stw[k << (5 - s)];
            w[2] = stw[(k + hf) << (5 - s)];
#pragma unroll
            for (int qq = 0; qq < 4; qq++) w[3 + qq] = stw[(k + qq * hf) << (4 - s)];
#pragma unroll
            for (int m = 0; m < 7; m++) w[m].y = -w[m].y;
            float2 xv[8];
#pragma unroll
            for (int m = 0; m < 8; m++) xv[m] = sz[(i0 + m * hf) * 128 + cl];
            bf8(xv, w);
#pragma unroll
            for (int m = 0; m < 8; m++) sz[(i0 + m * hf) * 128 + cl] = xv[m];
        }
        __syncthreads();
    }

    const size_t xbase = ((size_t)(b * HH + h) * WW) * CC + c;
#pragma unroll
    for (int mm = 0; mm < 16; mm++) {
        int m = q * 16 + mm;
        float2 z = sz[m * 128 + cl];
        size_t i0 = xbase + (size_t)(2 * m) * CC;
        size_t i1 = xbase + (size_t)(2 * m + 1) * CC;
        out[i0] = z.x * (1.f / 128.f) + x[i0];
        out[i1] = z.y * (1.f / 128.f) + x[i1];
    }
}

// ---------------------------------------------------------------------------
extern "C" void kernel_launch(void* const* d_in, const int* in_sizes, int n_in,
                              void* d_out, int out_size) {
    const float* x  = (const float*)d_in[0];
    const float* w1 = (const float*)d_in[1];
    const float* b1 = (const float*)d_in[2];
    const float* w2 = (const float*)d_in[3];
    const float* b2 = (const float*)d_in[4];
    float* out = (float*)d_out;

    const size_t sm_fftw = (size_t)(64 * 128 + 65) * sizeof(float2);   // 66056
    const size_t sm_fus  = (size_t)(128 * 196 + 4 * 96 * 52) * 4 + 65 * 8; // ~181 KB

    cudaFuncSetAttribute(k_fwd_w, cudaFuncAttributeMaxDynamicSharedMemorySize, (int)sm_fftw);
    cudaFuncSetAttribute(k_fused, cudaFuncAttributeMaxDynamicSharedMemorySize, (int)sm_fus);
    cudaFuncSetAttribute(k_inv_w, cudaFuncAttributeMaxDynamicSharedMemorySize, (int)sm_fftw);

    k_init_tw<<<1, 128>>>();
    k_fwd_w<<<dim3(6, 128, 8), 512, sm_fftw>>>(x);
    k_fused<<<dim3(8, 65, 8), 512, sm_fus>>>(w1, b1, w2, b2);
    k_inv_w<<<dim3(6, 128, 8), 512, sm_fftw>>>(x, out);
}

// round 12
// speedup vs baseline: 4.4772x; 1.0111x over previous
#include <cuda_runtime.h>
#include <cuda_bf16.h>
#include <math.h>

#define BB 8
#define HH 128
#define WW 128
#define CC 768
#define NB 8
#define BS 96
#define WF 65
#define LAMBDA 0.01f

#define C4F 0.70710678118654752440f
#define C8F 0.92387953251128675613f
#define S8F 0.38268343236508977173f

// Frequency-domain scratch (bf16 transport): [b][wf][h][c]
__device__ __nv_bfloat162 g_F[(size_t)BB * WF * HH * CC];
// Twiddles: g_tw[k] = exp(-2*pi*i*k/128), k=0..64
__device__ float2 g_tw[65];

__device__ __forceinline__ float2 cmul(float2 a, float2 b) {
    return make_float2(a.x * b.x - a.y * b.y, a.x * b.y + a.y * b.x);
}

// pack two floats to bf16x2 word
__device__ __forceinline__ unsigned bf2(float hi, float lo) {
    unsigned r;
    asm("cvt.rn.bf16x2.f32 %0, %1, %2;" : "=r"(r) : "f"(hi), "f"(lo));
    return r;
}

__device__ __forceinline__ void mma16(float c[4], unsigned a0, unsigned a1,
                                      unsigned a2, unsigned a3,
                                      unsigned b0, unsigned b1) {
    asm volatile(
        "mma.sync.aligned.m16n8k16.row.col.f32.bf16.bf16.f32 "
        "{%0,%1,%2,%3}, {%4,%5,%6,%7}, {%8,%9}, {%0,%1,%2,%3};"
        : "+f"(c[0]), "+f"(c[1]), "+f"(c[2]), "+f"(c[3])
        : "r"(a0), "r"(a1), "r"(a2), "r"(a3), "r"(b0), "r"(b1));
}

__device__ __forceinline__ void ldsm4(unsigned& r0, unsigned& r1,
                                      unsigned& r2, unsigned& r3,
                                      unsigned addr) {
    asm volatile(
        "ldmatrix.sync.aligned.m8n8.x4.shared.b16 {%0,%1,%2,%3}, [%4];"
        : "=r"(r0), "=r"(r1), "=r"(r2), "=r"(r3)
        : "r"(addr));
}

__device__ __forceinline__ float sshrink(float v) {
    return v > LAMBDA ? v - LAMBDA : (v < -LAMBDA ? v + LAMBDA : 0.f);
}

__global__ void k_init_tw() {
    int i = threadIdx.x;
    if (i < 65) {
        double a = -2.0 * 3.14159265358979323846264338327950288 * (double)i / 128.0;
        g_tw[i] = make_float2((float)cos(a), (float)sin(a));
    }
}

// ----- register butterflies -----
template <bool INV>
__device__ __forceinline__ float2 rot90(float2 v) {
    return INV ? make_float2(-v.y, v.x) : make_float2(v.y, -v.x);
}

template <bool INV>
__device__ __forceinline__ void bf4_0(float2& x0, float2& x1, float2& x2,
                                      float2& x3) {
    float2 y0 = make_float2(x0.x + x1.x, x0.y + x1.y);
    float2 y1 = make_float2(x0.x - x1.x, x0.y - x1.y);
    float2 y2 = make_float2(x2.x + x3.x, x2.y + x3.y);
    float2 y3 = make_float2(x2.x - x3.x, x2.y - x3.y);
    float2 u3 = rot90<INV>(y3);
    x0 = make_float2(y0.x + y2.x, y0.y + y2.y);
    x2 = make_float2(y0.x - y2.x, y0.y - y2.y);
    x1 = make_float2(y1.x + u3.x, y1.y + u3.y);
    x3 = make_float2(y1.x - u3.x, y1.y - u3.y);
}

template <bool INV>
__device__ __forceinline__ void bf8_0(float2* x) {
    bf4_0<INV>(x[0], x[1], x[2], x[3]);
    bf4_0<INV>(x[4], x[5], x[6], x[7]);
    const float I = INV ? 1.f : -1.f;
    const float2 t1 = make_float2(C4F, I * C4F);
    const float2 t3 = make_float2(-C4F, I * C4F);
    { float2 a = x[0], u = x[4];
      x[0] = make_float2(a.x + u.x, a.y + u.y);
      x[4] = make_float2(a.x - u.x, a.y - u.y); }
    { float2 a = x[1], u = cmul(x[5], t1);
      x[1] = make_float2(a.x + u.x, a.y + u.y);
      x[5] = make_float2(a.x - u.x, a.y - u.y); }
    { float2 a = x[2], u = rot90<INV>(x[6]);
      x[2] = make_float2(a.x + u.x, a.y + u.y);
      x[6] = make_float2(a.x - u.x, a.y - u.y); }
    { float2 a = x[3], u = cmul(x[7], t3);
      x[3] = make_float2(a.x + u.x, a.y + u.y);
      x[7] = make_float2(a.x - u.x, a.y - u.y); }
}

template <bool INV>
__device__ __forceinline__ void bf16pt(float2* x) {
    bf8_0<INV>(x);
    bf8_0<INV>(x + 8);
    const float I = INV ? 1.f : -1.f;
    const float2 w1 = make_float2(C8F, I * S8F);
    const float2 w2 = make_float2(C4F, I * C4F);
    const float2 w3 = make_float2(S8F, I * C8F);
    const float2 w5 = make_float2(-S8F, I * C8F);
    const float2 w6 = make_float2(-C4F, I * C4F);
    const float2 w7 = make_float2(-C8F, I * S8F);
#pragma unroll
    for (int m = 0; m < 8; m++) {
        float2 u;
        if (m == 0) u = x[8];
        else if (m == 1) u = cmul(x[9], w1);
        else if (m == 2) u = cmul(x[10], w2);
        else if (m == 3) u = cmul(x[11], w3);
        else if (m == 4) u = rot90<INV>(x[12]);
        else if (m == 5) u = cmul(x[13], w5);
        else if (m == 6) u = cmul(x[14], w6);
        else u = cmul(x[15], w7);
        float2 a = x[m];
        x[m] = make_float2(a.x + u.x, a.y + u.y);
        x[m + 8] = make_float2(a.x - u.x, a.y - u.y);
    }
}

// Generic radix-2^3 with provided twiddles (w[0]; w[1],w[2]; w[3..6]).
__device__ __forceinline__ void bf8(float2 x[8], const float2 w[7]) {
    float2 t1 = cmul(x[1], w[0]), t3 = cmul(x[3], w[0]);
    float2 y0 = make_float2(x[0].x + t1.x, x[0].y + t1.y);
    float2 y1 = make_float2(x[0].x - t1.x, x[0].y - t1.y);
    float2 y2 = make_float2(x[2].x + t3.x, x[2].y + t3.y);
    float2 y3 = make_float2(x[2].x - t3.x, x[2].y - t3.y);
    float2 u2 = cmul(y2, w[1]), u3 = cmul(y3, w[2]);
    x[0] = make_float2(y0.x + u2.x, y0.y + u2.y);
    x[2] = make_float2(y0.x - u2.x, y0.y - u2.y);
    x[1] = make_float2(y1.x + u3.x, y1.y + u3.y);
    x[3] = make_float2(y1.x - u3.x, y1.y - u3.y);
    float2 t5 = cmul(x[5], w[0]), t7 = cmul(x[7], w[0]);
    float2 z0 = make_float2(x[4].x + t5.x, x[4].y + t5.y);
    float2 z1 = make_float2(x[4].x - t5.x, x[4].y - t5.y);
    float2 z2 = make_float2(x[6].x + t7.x, x[6].y + t7.y);
    float2 z3 = make_float2(x[6].x - t7.x, x[6].y - t7.y);
    float2 v2 = cmul(z2, w[1]), v3 = cmul(z3, w[2]);
    x[4] = make_float2(z0.x + v2.x, z0.y + v2.y);
    x[6] = make_float2(z0.x - v2.x, z0.y - v2.y);
    x[5] = make_float2(z1.x + v3.x, z1.y + v3.y);
    x[7] = make_float2(z1.x - v3.x, z1.y - v3.y);
#pragma unroll
    for (int q = 0; q < 4; q++) {
        float2 u = cmul(x[q + 4], w[3 + q]);
        float2 a = x[q];
        x[q] = make_float2(a.x + u.x, a.y + u.y);
        x[q + 4] = make_float2(a.x - u.x, a.y - u.y);
    }
}

// ---------------------------------------------------------------------------
// Pass 1: real FFT length 128 along W (pack-in-pairs), 2 radix-8 passes.
// Pass-1 gathers bit-reversed packed inputs directly from x (k=0 -> bf8_0).
// ---------------------------------------------------------------------------
__global__ __launch_bounds__(512, 2) void k_fwd_w(const float* __restrict__ x) {
    extern __shared__ float2 sm2[];
    float2* sz = sm2;               // [64][128]
    float2* stw = sm2 + 64 * 128;   // [65]
    const int t = threadIdx.x;
    if (t < 65) stw[t] = g_tw[t];
    const int cl = t & 127, q = t >> 7;
    const int b = blockIdx.z, h = blockIdx.y;
    const int c = blockIdx.x * 128 + cl;
    const float* xp = x + ((size_t)(b * HH + h) * WW) * CC + c;

    // pass 1: s=0 (k=0), gather from gmem with bit-reversed packed indices
#pragma unroll
    for (int rr = 0; rr < 2; rr++) {
        int j = q * 2 + rr;
        float2 xv[8];
#pragma unroll
        for (int m = 0; m < 8; m++) {
            int mm = __brev((unsigned)(j * 8 + m)) >> 26;
            xv[m] = make_float2(xp[(size_t)(2 * mm) * CC],
                                xp[(size_t)(2 * mm + 1) * CC]);
        }
        bf8_0<false>(xv);
#pragma unroll
        for (int m = 0; m < 8; m++) sz[(j * 8 + m) * 128 + cl] = xv[m];
    }
    __syncthreads();  // covers stw staging too

    // pass 2: s=3, hf=8, k=j
#pragma unroll
    for (int rr = 0; rr < 2; rr++) {
        int j = q * 2 + rr;
        float2 w[7];
        w[0] = stw[j << 3];
        w[1] = stw[j << 2];
        w[2] = stw[(j + 8) << 2];
#pragma unroll
        for (int qq = 0; qq < 4; qq++) w[3 + qq] = stw[(j + qq * 8) << 1];
        float2 xv[8];
#pragma unroll
        for (int m = 0; m < 8; m++) xv[m] = sz[(j + m * 8) * 128 + cl];
        bf8(xv, w);
#pragma unroll
        for (int m = 0; m < 8; m++) sz[(j + m * 8) * 128 + cl] = xv[m];
    }
    __syncthreads();

    size_t base = ((size_t)b * WF * HH + h) * CC + c;
    const size_t ws = (size_t)HH * CC;
#pragma unroll
    for (int jj = 0; jj < 8; jj++) {
        int idx = q * 8 + jj;
        if (idx == 0) {
            float2 Z0 = sz[cl];
            g_F[base] = __float22bfloat162_rn(make_float2(Z0.x + Z0.y, 0.f));
            g_F[base + 64 * ws] = __float22bfloat162_rn(make_float2(Z0.x - Z0.y, 0.f));
            float2 Z32 = sz[32 * 128 + cl];
            g_F[base + 32 * ws] = __float22bfloat162_rn(make_float2(Z32.x, -Z32.y));
        } else {
            int k = idx;  // 1..31
            float2 Zk = sz[k * 128 + cl];
            float2 Zm = sz[(64 - k) * 128 + cl];
            float2 E = make_float2(0.5f * (Zk.x + Zm.x), 0.5f * (Zk.y - Zm.y));
            float2 D = make_float2(0.5f * (Zk.x - Zm.x), 0.5f * (Zk.y + Zm.y));
            float2 O = make_float2(D.y, -D.x);
            float2 p = cmul(stw[k], O);
            g_F[base + (size_t)k * ws] =
                __float22bfloat162_rn(make_float2(E.x + p.x, E.y + p.y));
            float2 Ec = make_float2(E.x, -E.y);
            float2 Oc = make_float2(O.x, -O.y);
            float2 qv = cmul(stw[64 - k], Oc);
            g_F[base + (size_t)(64 - k) * ws] =
                __float22bfloat162_rn(make_float2(Ec.x + qv.x, Ec.y + qv.y));
        }
    }
}

// ---------------------------------------------------------------------------
// Fused pass: FFT-H fwd + complex MLP (bf16 mma + ldmatrix) + FFT-H inv.
// ---------------------------------------------------------------------------
__global__ __launch_bounds__(512, 1) void k_fused(const float* __restrict__ w1,
                                                  const float* __restrict__ b1,
                                                  const float* __restrict__ w2,
                                                  const float* __restrict__ b2) {
    extern __shared__ unsigned smu[];
    unsigned* sBIG = smu;                         // [128][196] words
    unsigned* sW1r = smu + 128 * 196;             // [96][52] words (bf16x2)
    unsigned* sW1i = sW1r + 96 * 52;
    unsigned* sW2r = sW1i + 96 * 52;
    unsigned* sW2i = sW2r + 96 * 52;
    float2* stw = (float2*)(sW2i + 96 * 52);      // [65]
    float2* tz = (float2*)sBIG;                   // tile view, row stride 98

    const int t = threadIdx.x;
    const int lane = t & 31, warp = t >> 5;
    if (t < 65) stw[t] = g_tw[t];
    const int n = blockIdx.x, wf = blockIdx.y, b = blockIdx.z;
    const size_t base = ((size_t)(b * WF + wf) * HH) * CC + n * BS;

    // Stage W1 and W2 transposed ([o][i]) as bf16
    {
        const float* w1r = w1 + n * BS * BS;
        const float* w1i = w1 + NB * BS * BS + n * BS * BS;
        const float* w2r = w2 + n * BS * BS;
        const float* w2i = w2 + NB * BS * BS + n * BS * BS;
        __nv_bfloat16* h1r = (__nv_bfloat16*)sW1r;
        __nv_bfloat16* h1i = (__nv_bfloat16*)sW1i;
        __nv_bfloat16* h2r = (__nv_bfloat16*)sW2r;
        __nv_bfloat16* h2i = (__nv_bfloat16*)sW2i;
        for (int idx = t; idx < 9216; idx += 512) {
            int i = idx / 96, o = idx - i * 96;   // i = input(k), o = output
            int ha = o * 104 + i;
            h1r[ha] = __float2bfloat16_rn(w1r[idx]);
            h1i[ha] = __float2bfloat16_rn(w1i[idx]);
            h2r[ha] = __float2bfloat16_rn(w2r[idx]);
            h2i[ha] = __float2bfloat16_rn(w2i[idx]);
        }
    }

    // radix-8 (stages 4-6) work map: 16 groups x 96 cols = 1536 -> 3/thread
    int j8v[3], c8v[3];
#pragma unroll
    for (int r = 0; r < 3; r++) {
        int idx = r * 512 + t;
        j8v[r] = idx / 96;
        c8v[r] = idx - j8v[r] * 96;
    }

    // ---------------- forward FFT over h ----------------
    // pass 1: radix-16 (stages 0-3, k=0), gathering directly from g_F.
#pragma unroll
    for (int rep = 0; rep < 2; rep++) {
        if (rep == 0 || t < 256) {
            int idx = rep * 512 + t;
            int j = idx / 96, col = idx - j * 96;
            float2 xv[16];
#pragma unroll
            for (int m = 0; m < 16; m++) {
                int h = __brev((unsigned)(j * 16 + m)) >> 25;
                xv[m] = __bfloat1622float2(g_F[base + (size_t)h * CC + col]);
            }
            bf16pt<false>(xv);
            float2* p = tz + (j * 16) * 98 + col;
#pragma unroll
            for (int m = 0; m < 16; m++) p[m * 98] = xv[m];
        }
    }
    __syncthreads();  // also covers weight staging + stw
    // pass 2: radix-8 (stages 4-6), hf=16, k=j
    {
#pragma unroll
        for (int r = 0; r < 3; r++) {
            int j = j8v[r], col = c8v[r];
            float2 w[7];
            w[0] = stw[j << 2];
            w[1] = stw[j << 1];
            w[2] = stw[(j + 16) << 1];
#pragma unroll
            for (int qq = 0; qq < 4; qq++) w[3 + qq] = stw[j + qq * 16];
            float2* p = tz + j * 98 + col;
            float2 xv[8];
#pragma unroll
            for (int m = 0; m < 8; m++) xv[m] = p[(m * 16) * 98];
            bf8(xv, w);
#pragma unroll
            for (int m = 0; m < 8; m++) p[(m * 16) * 98] = xv[m];
        }
        __syncthreads();
    }

    // ---- deinterleave tile -> bf16 A (x 1/128), in place, per-row by warp --
    {
        const float s128 = 0.0078125f;
#pragma unroll
        for (int rr = 0; rr < 8; rr++) {
            int row = warp * 8 + rr;
            float4 q0 = *(float4*)&tz[row * 98 + 2 * lane];
            float4 q1 = make_float4(0.f, 0.f, 0.f, 0.f);
            if (lane < 16)
                q1 = *(float4*)&tz[row * 98 + 2 * (lane + 32)];
            __syncwarp();
            unsigned* Ar = sBIG + row * 196;
            Ar[lane] = bf2(q0.z * s128, q0.x * s128);
            Ar[48 + lane] = bf2(q0.w * s128, q0.y * s128);
            if (lane < 16) {
                Ar[lane + 32] = bf2(q1.z * s128, q1.x * s128);
                Ar[48 + lane + 32] = bf2(q1.w * s128, q1.y * s128);
            }
            __syncwarp();
        }
    }
    __syncthreads();

    // ---------------- MLP ----------------
    const int mgrp = warp & 3, ngrp = warp >> 2;
    const int nh = ngrp >> 1;
    const int jbase = (ngrp & 1) * 6;
    const int g = lane >> 2, tig = lane & 3;
    const int arow = mgrp * 32 + g;

    const unsigned sbigAddr = (unsigned)__cvta_generic_to_shared(sBIG);
    const int matq = lane >> 3;
    const unsigned aBase0 = sbigAddr +
        (unsigned)(((mgrp * 32 + (lane & 7) + (matq & 1) * 8) * 196 +
                    (matq >> 1) * 4) * 4);
    const unsigned aBase1 = aBase0 + 16u * 196u * 4u;
    const unsigned bOff0 = (unsigned)((((jbase * 8 + (matq >> 1) * 8 +
                                         (lane & 7)) * 52) + (matq & 1) * 4) * 4);
    const unsigned pStep = 16u * 52u * 4u;
    const unsigned w1lo = (unsigned)__cvta_generic_to_shared((nh == 0) ? sW1r : sW1i);
    const unsigned w1hi = (unsigned)__cvta_generic_to_shared((nh == 0) ? sW1i : sW1r);
    const unsigned w2lo = (unsigned)__cvta_generic_to_shared((nh == 0) ? sW2r : sW2i);
    const unsigned w2hi = (unsigned)__cvta_generic_to_shared((nh == 0) ? sW2i : sW2r);
    const unsigned sgnHi = (nh == 0) ? 0x80008000u : 0u;

    float acc[2][6][4];

    // ===== layer 1 =====
    {
        const float* bp = (nh == 0) ? (b1 + n * BS) : (b1 + NB * BS + n * BS);
#pragma unroll
        for (int j = 0; j < 6; j++) {
            int cih = (jbase + j) * 8 + 2 * tig;
            float bv0 = bp[cih], bv1 = bp[cih + 1];
#pragma unroll
            for (int mt = 0; mt < 2; mt++) {
                acc[mt][j][0] = bv0; acc[mt][j][1] = bv1;
                acc[mt][j][2] = bv0; acc[mt][j][3] = bv1;
            }
        }
#pragma unroll 2
        for (int kc = 0; kc < 12; kc++) {
            unsigned a0, a1, a2, a3, a4, a5, a6, a7;
            ldsm4(a0, a1, a2, a3, aBase0 + kc * 32);
            ldsm4(a4, a5, a6, a7, aBase1 + kc * 32);
            unsigned sgn = (kc < 6) ? 0u : sgnHi;
            unsigned wA = ((kc < 6) ? w1lo + kc * 32 : w1hi + (kc - 6) * 32) + bOff0;
            unsigned br[12];
#pragma unroll
            for (int p = 0; p < 3; p++) {
                unsigned r0, r1, r2, r3;
                ldsm4(r0, r1, r2, r3, wA + p * pStep);
                br[4 * p] = r0 ^ sgn;
                br[4 * p + 1] = r1 ^ sgn;
                br[4 * p + 2] = r2 ^ sgn;
                br[4 * p + 3] = r3 ^ sgn;
            }
#pragma unroll
            for (int j = 0; j < 6; j++) {
                mma16(acc[0][j], a0, a1, a2, a3, br[2 * j], br[2 * j + 1]);
                mma16(acc[1][j], a4, a5, a6, a7, br[2 * j], br[2 * j + 1]);
            }
        }
    }
    __syncthreads();  // all A reads done

    // write relu(O) over A (packed bf16x2)
#pragma unroll
    for (int j = 0; j < 6; j++) {
        int wcol = nh * 48 + (jbase + j) * 4 + tig;
#pragma unroll
        for (int mt = 0; mt < 2; mt++) {
            int r0 = arow + 16 * mt;
            sBIG[r0 * 196 + wcol] =
                bf2(fmaxf(acc[mt][j][1], 0.f), fmaxf(acc[mt][j][0], 0.f));
            sBIG[(r0 + 8) * 196 + wcol] =
                bf2(fmaxf(acc[mt][j][3], 0.f), fmaxf(acc[mt][j][2], 0.f));
        }
    }
    __syncthreads();

    // ===== layer 2 =====
    {
        const float* bp = (nh == 0) ? (b2 + n * BS) : (b2 + NB * BS + n * BS);
#pragma unroll
        for (int j = 0; j < 6; j++) {
            int cih = (jbase + j) * 8 + 2 * tig;
            float bv0 = bp[cih], bv1 = bp[cih + 1];
#pragma unroll
            for (int mt = 0; mt < 2; mt++) {
                acc[mt][j][0] = bv0; acc[mt][j][1] = bv1;
                acc[mt][j][2] = bv0; acc[mt][j][3] = bv1;
            }
        }
#pragma unroll 2
        for (int kc = 0; kc < 12; kc++) {
            unsigned a0, a1, a2, a3, a4, a5, a6, a7;
            ldsm4(a0, a1, a2, a3, aBase0 + kc * 32);
            ldsm4(a4, a5, a6, a7, aBase1 + kc * 32);
            unsigned sgn = (kc < 6) ? 0u : sgnHi;
            unsigned wA = ((kc < 6) ? w2lo + kc * 32 : w2hi + (kc - 6) * 32) + bOff0;
            unsigned br[12];
#pragma unroll
            for (int p = 0; p < 3; p++) {
                unsigned r0, r1, r2, r3;
                ldsm4(r0, r1, r2, r3, wA + p * pStep);
                br[4 * p] = r0 ^ sgn;
                br[4 * p + 1] = r1 ^ sgn;
                br[4 * p + 2] = r2 ^ sgn;
                br[4 * p + 3] = r3 ^ sgn;
            }
#pragma unroll
            for (int j = 0; j < 6; j++) {
                mma16(acc[0][j], a0, a1, a2, a3, br[2 * j], br[2 * j + 1]);
                mma16(acc[1][j], a4, a5, a6, a7, br[2 * j], br[2 * j + 1]);
            }
        }
    }
    __syncthreads();  // all O reads done

    // softshrink -> float2 tile (bit-reversed rows) for inverse FFT
    {
        float* Tf = (float*)sBIG;
#pragma unroll
        for (int j = 0; j < 6; j++) {
            int ch = (jbase + j) * 8 + 2 * tig;
#pragma unroll
            for (int mt = 0; mt < 2; mt++) {
                int r0 = arow + 16 * mt, r1 = r0 + 8;
                int br0 = __brev((unsigned)r0) >> 25;
                int br1 = __brev((unsigned)r1) >> 25;
                Tf[br0 * 196 + 2 * ch + nh] = sshrink(acc[mt][j][0]);
                Tf[br0 * 196 + 2 * (ch + 1) + nh] = sshrink(acc[mt][j][1]);
                Tf[br1 * 196 + 2 * ch + nh] = sshrink(acc[mt][j][2]);
                Tf[br1 * 196 + 2 * (ch + 1) + nh] = sshrink(acc[mt][j][3]);
            }
        }
    }
    __syncthreads();

    // ---------------- inverse FFT over h (conj twiddles) ----------------
#pragma unroll
    for (int rep = 0; rep < 2; rep++) {
        if (rep == 0 || t < 256) {
            int idx = rep * 512 + t;
            int j = idx / 96, col = idx - j * 96;
            float2* p = tz + (j * 16) * 98 + col;
            float2 xv[16];
#pragma unroll
            for (int m = 0; m < 16; m++) xv[m] = p[m * 98];
            bf16pt<true>(xv);
#pragma unroll
            for (int m = 0; m < 16; m++) p[m * 98] = xv[m];
        }
    }
    __syncthreads();
    // pass 2: radix-8, scatter results directly to g_F
    {
#pragma unroll
        for (int r = 0; r < 3; r++) {
            int j = j8v[r], col = c8v[r];
            float2 w[7];
            w[0] = stw[j << 2];
            w[1] = stw[j << 1];
            w[2] = stw[(j + 16) << 1];
#pragma unroll
            for (int qq = 0; qq < 4; qq++) w[3 + qq] = stw[j + qq * 16];
#pragma unroll
            for (int m = 0; m < 7; m++) w[m].y = -w[m].y;
            float2* p = tz + j * 98 + col;
            float2 xv[8];
#pragma unroll
            for (int m = 0; m < 8; m++) xv[m] = p[(m * 16) * 98];
            bf8(xv, w);
#pragma unroll
            for (int m = 0; m < 8; m++)
                g_F[base + (size_t)(j + m * 16) * CC + col] =
                    __float22bfloat162_rn(xv[m]);
        }
    }
}

// ---------------------------------------------------------------------------
// Pass 5: inverse real FFT length 128 along W + 1/128 scale + residual add.
// Pass-1 computes the C2R untangle on the fly, gathering straight from g_F
// (k=0 stage -> bf8_0<true>). C2R: imag of DC & Nyquist ignored.
// ---------------------------------------------------------------------------
__global__ __launch_bounds__(512, 2) void k_inv_w(const float* __restrict__ x,
                                                  float* __restrict__ out) {
    extern __shared__ float2 sm2[];
    float2* sz = sm2;               // [64][128]
    float2* stw = sm2 + 64 * 128;   // [65]
    const int t = threadIdx.x;
    if (t < 65) stw[t] = g_tw[t];
    __syncthreads();
    const int cl = t & 127, q = t >> 7;
    const int b = blockIdx.z, h = blockIdx.y;
    const int c = blockIdx.x * 128 + cl;
    size_t base = ((size_t)b * WF * HH + h) * CC + c;
    const size_t ws = (size_t)HH * CC;

    // pass 1: s=0 (k=0), rows j*8+m hold Zc[brev6(row)] computed on the fly
#pragma unroll
    for (int rr = 0; rr < 2; rr++) {
        int j = q * 2 + rr;
        float2 xv[8];
#pragma unroll
        for (int m = 0; m < 8; m++) {
            int k = __brev((unsigned)(j * 8 + m)) >> 26;
            if (k == 0) {
                float2 X0 = __bfloat1622float2(g_F[base]);
                float2 X64 = __bfloat1622float2(g_F[base + 64 * ws]);
                xv[m] = make_float2(X0.x + X64.x, X0.x - X64.x);  // imag dropped
            } else if (k == 32) {
                float2 X32 = __bfloat1622float2(g_F[base + 32 * ws]);
                xv[m] = make_float2(2.f * X32.x, -2.f * X32.y);
            } else {
                float2 Xk = __bfloat1622float2(g_F[base + (size_t)k * ws]);
                float2 Xm = __bfloat1622float2(g_F[base + (size_t)(64 - k) * ws]);
                float2 A = make_float2(Xk.x + Xm.x, Xk.y - Xm.y);
                float2 D = make_float2(Xk.x - Xm.x, Xk.y + Xm.y);
                float2 wc = make_float2(stw[k].x, -stw[k].y);
                float2 tv = cmul(wc, D);
                xv[m] = make_float2(A.x - tv.y, A.y + tv.x);
            }
        }
        bf8_0<true>(xv);
#pragma unroll
        for (int m = 0; m < 8; m++) sz[(j * 8 + m) * 128 + cl] = xv[m];
    }
    __syncthreads();

    // pass 2: s=3, hf=8, k=j (conj twiddles)
#pragma unroll
    for (int rr = 0; rr < 2; rr++) {
        int j = q * 2 + rr;
        float2 w[7];
        w[0] = stw[j << 3];
        w[1] = stw[j << 2];
        w[2] = stw[(j + 8) << 2];
#pragma unroll
        for (int qq = 0; qq < 4; qq++) w[3 + qq] = stw[(j + qq * 8) << 1];
#pragma unroll
        for (int m = 0; m < 7; m++) w[m].y = -w[m].y;
        float2 xv[8];
#pragma unroll
        for (int m = 0; m < 8; m++) xv[m] = sz[(j + m * 8) * 128 + cl];
        bf8(xv, w);
#pragma unroll
        for (int m = 0; m < 8; m++) sz[(j + m * 8) * 128 + cl] = xv[m];
    }
    __syncthreads();

    const size_t xbase = ((size_t)(b * HH + h) * WW) * CC + c;
#pragma unroll
    for (int mm = 0; mm < 16; mm++) {
        int m = q * 16 + mm;
        float2 z = sz[m * 128 + cl];
        size_t i0 = xbase + (size_t)(2 * m) * CC;
        size_t i1 = xbase + (size_t)(2 * m + 1) * CC;
        out[i0] = z.x * (1.f / 128.f) + x[i0];
        out[i1] = z.y * (1.f / 128.f) + x[i1];
    }
}

// ---------------------------------------------------------------------------
extern "C" void kernel_launch(void* const* d_in, const int* in_sizes, int n_in,
                              void* d_out, int out_size) {
    const float* x  = (const float*)d_in[0];
    const float* w1 = (const float*)d_in[1];
    const float* b1 = (const float*)d_in[2];
    const float* w2 = (const float*)d_in[3];
    const float* b2 = (const float*)d_in[4];
    float* out = (float*)d_out;

    const size_t sm_fftw = (size_t)(64 * 128 + 65) * sizeof(float2);   // 66056
    const size_t sm_fus  = (size_t)(128 * 196 + 4 * 96 * 52) * 4 + 65 * 8; // ~181 KB

    cudaFuncSetAttribute(k_fwd_w, cudaFuncAttributeMaxDynamicSharedMemorySize, (int)sm_fftw);
    cudaFuncSetAttribute(k_fused, cudaFuncAttributeMaxDynamicSharedMemorySize, (int)sm_fus);
    cudaFuncSetAttribute(k_inv_w, cudaFuncAttributeMaxDynamicSharedMemorySize, (int)sm_fftw);

    k_init_tw<<<1, 128>>>();
    k_fwd_w<<<dim3(6, 128, 8), 512, sm_fftw>>>(x);
    k_fused<<<dim3(8, 65, 8), 512, sm_fus>>>(w1, b1, w2, b2);
    k_inv_w<<<dim3(6, 128, 8), 512, sm_fftw>>>(x, out);
}

// round 13
// speedup vs baseline: 4.7579x; 1.0627x over previous
#include <cuda_runtime.h>
#include <cuda_bf16.h>
#include <math.h>

#define BB 8
#define HH 128
#define WW 128
#define CC 768
#define NB 8
#define BS 96
#define WF 65
#define LAMBDA 0.01f

#define C4F 0.70710678118654752440f
#define C8F 0.92387953251128675613f
#define S8F 0.38268343236508977173f

// Frequency-domain scratch (bf16 transport): [b][wf][h][c]
__device__ __nv_bfloat162 g_F[(size_t)BB * WF * HH * CC];
// Twiddles: g_tw[k] = exp(-2*pi*i*k/128), k=0..64
__device__ float2 g_tw[65];
// Pre-packed bf16x2 weight images: [n][4 mats][96 o][52 words]
__device__ __align__(16) unsigned g_Wp[(size_t)NB * 4 * 96 * 52];

__device__ __forceinline__ float2 cmul(float2 a, float2 b) {
    return make_float2(a.x * b.x - a.y * b.y, a.x * b.y + a.y * b.x);
}

// pack two floats to bf16x2 word
__device__ __forceinline__ unsigned bf2(float hi, float lo) {
    unsigned r;
    asm("cvt.rn.bf16x2.f32 %0, %1, %2;" : "=r"(r) : "f"(hi), "f"(lo));
    return r;
}

__device__ __forceinline__ void mma16(float c[4], unsigned a0, unsigned a1,
                                      unsigned a2, unsigned a3,
                                      unsigned b0, unsigned b1) {
    asm volatile(
        "mma.sync.aligned.m16n8k16.row.col.f32.bf16.bf16.f32 "
        "{%0,%1,%2,%3}, {%4,%5,%6,%7}, {%8,%9}, {%0,%1,%2,%3};"
        : "+f"(c[0]), "+f"(c[1]), "+f"(c[2]), "+f"(c[3])
        : "r"(a0), "r"(a1), "r"(a2), "r"(a3), "r"(b0), "r"(b1));
}

__device__ __forceinline__ void ldsm4(unsigned& r0, unsigned& r1,
                                      unsigned& r2, unsigned& r3,
                                      unsigned addr) {
    asm volatile(
        "ldmatrix.sync.aligned.m8n8.x4.shared.b16 {%0,%1,%2,%3}, [%4];"
        : "=r"(r0), "=r"(r1), "=r"(r2), "=r"(r3)
        : "r"(addr));
}

__device__ __forceinline__ float sshrink(float v) {
    return v > LAMBDA ? v - LAMBDA : (v < -LAMBDA ? v + LAMBDA : 0.f);
}

__global__ void k_init_tw() {
    int i = threadIdx.x;
    if (i < 65) {
        double a = -2.0 * 3.14159265358979323846264338327950288 * (double)i / 128.0;
        g_tw[i] = make_float2((float)cos(a), (float)sin(a));
    }
}

// ---------------------------------------------------------------------------
// Pre-pack weights into the exact padded smem image (bf16x2, [o][i-word]).
// mats order matches k_fused smem: 0=W1r, 1=W1i, 2=W2r, 3=W2i.
// ---------------------------------------------------------------------------
__global__ void k_pack_w(const float* __restrict__ w1,
                         const float* __restrict__ w2) {
    const int n = blockIdx.x, t = threadIdx.x;
    const float* src[4] = {w1 + n * BS * BS, w1 + NB * BS * BS + n * BS * BS,
                           w2 + n * BS * BS, w2 + NB * BS * BS + n * BS * BS};
    unsigned* dst = g_Wp + (size_t)n * 4 * 96 * 52;
    for (int idx = t; idx < 96 * 52; idx += 256) {
        int o = idx / 52, iw = idx - o * 52;
#pragma unroll
        for (int m = 0; m < 4; m++) {
            unsigned v = 0u;
            if (iw < 48) {
                int i0 = 2 * iw;
                v = bf2(src[m][(i0 + 1) * 96 + o], src[m][i0 * 96 + o]);
            }
            dst[m * 96 * 52 + idx] = v;
        }
    }
}

// ----- register butterflies -----
template <bool INV>
__device__ __forceinline__ float2 rot90(float2 v) {
    return INV ? make_float2(-v.y, v.x) : make_float2(v.y, -v.x);
}

template <bool INV>
__device__ __forceinline__ void bf4_0(float2& x0, float2& x1, float2& x2,
                                      float2& x3) {
    float2 y0 = make_float2(x0.x + x1.x, x0.y + x1.y);
    float2 y1 = make_float2(x0.x - x1.x, x0.y - x1.y);
    float2 y2 = make_float2(x2.x + x3.x, x2.y + x3.y);
    float2 y3 = make_float2(x2.x - x3.x, x2.y - x3.y);
    float2 u3 = rot90<INV>(y3);
    x0 = make_float2(y0.x + y2.x, y0.y + y2.y);
    x2 = make_float2(y0.x - y2.x, y0.y - y2.y);
    x1 = make_float2(y1.x + u3.x, y1.y + u3.y);
    x3 = make_float2(y1.x - u3.x, y1.y - u3.y);
}

template <bool INV>
__device__ __forceinline__ void bf8_0(float2* x) {
    bf4_0<INV>(x[0], x[1], x[2], x[3]);
    bf4_0<INV>(x[4], x[5], x[6], x[7]);
    const float I = INV ? 1.f : -1.f;
    const float2 t1 = make_float2(C4F, I * C4F);
    const float2 t3 = make_float2(-C4F, I * C4F);
    { float2 a = x[0], u = x[4];
      x[0] = make_float2(a.x + u.x, a.y + u.y);
      x[4] = make_float2(a.x - u.x, a.y - u.y); }
    { float2 a = x[1], u = cmul(x[5], t1);
      x[1] = make_float2(a.x + u.x, a.y + u.y);
      x[5] = make_float2(a.x - u.x, a.y - u.y); }
    { float2 a = x[2], u = rot90<INV>(x[6]);
      x[2] = make_float2(a.x + u.x, a.y + u.y);
      x[6] = make_float2(a.x - u.x, a.y - u.y); }
    { float2 a = x[3], u = cmul(x[7], t3);
      x[3] = make_float2(a.x + u.x, a.y + u.y);
      x[7] = make_float2(a.x - u.x, a.y - u.y); }
}

template <bool INV>
__device__ __forceinline__ void bf16pt(float2* x) {
    bf8_0<INV>(x);
    bf8_0<INV>(x + 8);
    const float I = INV ? 1.f : -1.f;
    const float2 w1 = make_float2(C8F, I * S8F);
    const float2 w2 = make_float2(C4F, I * C4F);
    const float2 w3 = make_float2(S8F, I * C8F);
    const float2 w5 = make_float2(-S8F, I * C8F);
    const float2 w6 = make_float2(-C4F, I * C4F);
    const float2 w7 = make_float2(-C8F, I * S8F);
#pragma unroll
    for (int m = 0; m < 8; m++) {
        float2 u;
        if (m == 0) u = x[8];
        else if (m == 1) u = cmul(x[9], w1);
        else if (m == 2) u = cmul(x[10], w2);
        else if (m == 3) u = cmul(x[11], w3);
        else if (m == 4) u = rot90<INV>(x[12]);
        else if (m == 5) u = cmul(x[13], w5);
        else if (m == 6) u = cmul(x[14], w6);
        else u = cmul(x[15], w7);
        float2 a = x[m];
        x[m] = make_float2(a.x + u.x, a.y + u.y);
        x[m + 8] = make_float2(a.x - u.x, a.y - u.y);
    }
}

// Generic radix-2^3 with provided twiddles (w[0]; w[1],w[2]; w[3..6]).
__device__ __forceinline__ void bf8(float2 x[8], const float2 w[7]) {
    float2 t1 = cmul(x[1], w[0]), t3 = cmul(x[3], w[0]);
    float2 y0 = make_float2(x[0].x + t1.x, x[0].y + t1.y);
    float2 y1 = make_float2(x[0].x - t1.x, x[0].y - t1.y);
    float2 y2 = make_float2(x[2].x + t3.x, x[2].y + t3.y);
    float2 y3 = make_float2(x[2].x - t3.x, x[2].y - t3.y);
    float2 u2 = cmul(y2, w[1]), u3 = cmul(y3, w[2]);
    x[0] = make_float2(y0.x + u2.x, y0.y + u2.y);
    x[2] = make_float2(y0.x - u2.x, y0.y - u2.y);
    x[1] = make_float2(y1.x + u3.x, y1.y + u3.y);
    x[3] = make_float2(y1.x - u3.x, y1.y - u3.y);
    float2 t5 = cmul(x[5], w[0]), t7 = cmul(x[7], w[0]);
    float2 z0 = make_float2(x[4].x + t5.x, x[4].y + t5.y);
    float2 z1 = make_float2(x[4].x - t5.x, x[4].y - t5.y);
    float2 z2 = make_float2(x[6].x + t7.x, x[6].y + t7.y);
    float2 z3 = make_float2(x[6].x - t7.x, x[6].y - t7.y);
    float2 v2 = cmul(z2, w[1]), v3 = cmul(z3, w[2]);
    x[4] = make_float2(z0.x + v2.x, z0.y + v2.y);
    x[6] = make_float2(z0.x - v2.x, z0.y - v2.y);
    x[5] = make_float2(z1.x + v3.x, z1.y + v3.y);
    x[7] = make_float2(z1.x - v3.x, z1.y - v3.y);
#pragma unroll
    for (int q = 0; q < 4; q++) {
        float2 u = cmul(x[q + 4], w[3 + q]);
        float2 a = x[q];
        x[q] = make_float2(a.x + u.x, a.y + u.y);
        x[q + 4] = make_float2(a.x - u.x, a.y - u.y);
    }
}

// ---------------------------------------------------------------------------
// Pass 1: real FFT length 128 along W (pack-in-pairs), 2 radix-8 passes.
// Pass-1 gathers bit-reversed packed inputs directly from x (k=0 -> bf8_0).
// ---------------------------------------------------------------------------
__global__ __launch_bounds__(512, 2) void k_fwd_w(const float* __restrict__ x) {
    extern __shared__ float2 sm2[];
    float2* sz = sm2;               // [64][128]
    float2* stw = sm2 + 64 * 128;   // [65]
    const int t = threadIdx.x;
    if (t < 65) stw[t] = g_tw[t];
    const int cl = t & 127, q = t >> 7;
    const int b = blockIdx.z, h = blockIdx.y;
    const int c = blockIdx.x * 128 + cl;
    const float* xp = x + ((size_t)(b * HH + h) * WW) * CC + c;

    // pass 1: s=0 (k=0), gather from gmem with bit-reversed packed indices
#pragma unroll
    for (int rr = 0; rr < 2; rr++) {
        int j = q * 2 + rr;
        float2 xv[8];
#pragma unroll
        for (int m = 0; m < 8; m++) {
            int mm = __brev((unsigned)(j * 8 + m)) >> 26;
            xv[m] = make_float2(xp[(size_t)(2 * mm) * CC],
                                xp[(size_t)(2 * mm + 1) * CC]);
        }
        bf8_0<false>(xv);
#pragma unroll
        for (int m = 0; m < 8; m++) sz[(j * 8 + m) * 128 + cl] = xv[m];
    }
    __syncthreads();  // covers stw staging too

    // pass 2: s=3, hf=8, k=j
#pragma unroll
    for (int rr = 0; rr < 2; rr++) {
        int j = q * 2 + rr;
        float2 w[7];
        w[0] = stw[j << 3];
        w[1] = stw[j << 2];
        w[2] = stw[(j + 8) << 2];
#pragma unroll
        for (int qq = 0; qq < 4; qq++) w[3 + qq] = stw[(j + qq * 8) << 1];
        float2 xv[8];
#pragma unroll
        for (int m = 0; m < 8; m++) xv[m] = sz[(j + m * 8) * 128 + cl];
        bf8(xv, w);
#pragma unroll
        for (int m = 0; m < 8; m++) sz[(j + m * 8) * 128 + cl] = xv[m];
    }
    __syncthreads();

    size_t base = ((size_t)b * WF * HH + h) * CC + c;
    const size_t ws = (size_t)HH * CC;
#pragma unroll
    for (int jj = 0; jj < 8; jj++) {
        int idx = q * 8 + jj;
        if (idx == 0) {
            float2 Z0 = sz[cl];
            g_F[base] = __float22bfloat162_rn(make_float2(Z0.x + Z0.y, 0.f));
            g_F[base + 64 * ws] = __float22bfloat162_rn(make_float2(Z0.x - Z0.y, 0.f));
            float2 Z32 = sz[32 * 128 + cl];
            g_F[base + 32 * ws] = __float22bfloat162_rn(make_float2(Z32.x, -Z32.y));
        } else {
            int k = idx;  // 1..31
            float2 Zk = sz[k * 128 + cl];
            float2 Zm = sz[(64 - k) * 128 + cl];
            float2 E = make_float2(0.5f * (Zk.x + Zm.x), 0.5f * (Zk.y - Zm.y));
            float2 D = make_float2(0.5f * (Zk.x - Zm.x), 0.5f * (Zk.y + Zm.y));
            float2 O = make_float2(D.y, -D.x);
            float2 p = cmul(stw[k], O);
            g_F[base + (size_t)k * ws] =
                __float22bfloat162_rn(make_float2(E.x + p.x, E.y + p.y));
            float2 Ec = make_float2(E.x, -E.y);
            float2 Oc = make_float2(O.x, -O.y);
            float2 qv = cmul(stw[64 - k], Oc);
            g_F[base + (size_t)(64 - k) * ws] =
                __float22bfloat162_rn(make_float2(Ec.x + qv.x, Ec.y + qv.y));
        }
    }
}

// ---------------------------------------------------------------------------
// Fused pass: FFT-H fwd + complex MLP (bf16 mma + ldmatrix) + FFT-H inv.
// Weights staged from pre-packed g_Wp with a plain uint4 memcpy.
// ---------------------------------------------------------------------------
__global__ __launch_bounds__(512, 1) void k_fused(const float* __restrict__ b1,
                                                  const float* __restrict__ b2) {
    extern __shared__ unsigned smu[];
    unsigned* sBIG = smu;                         // [128][196] words
    unsigned* sW1r = smu + 128 * 196;             // [96][52] words (bf16x2)
    unsigned* sW1i = sW1r + 96 * 52;
    unsigned* sW2r = sW1i + 96 * 52;
    unsigned* sW2i = sW2r + 96 * 52;
    float2* stw = (float2*)(sW2i + 96 * 52);      // [65]
    float2* tz = (float2*)sBIG;                   // tile view, row stride 98

    const int t = threadIdx.x;
    const int lane = t & 31, warp = t >> 5;
    if (t < 65) stw[t] = g_tw[t];
    const int n = blockIdx.x, wf = blockIdx.y, b = blockIdx.z;
    const size_t base = ((size_t)(b * WF + wf) * HH) * CC + n * BS;

    // Stage all four weight images: contiguous uint4 memcpy from g_Wp[n]
    {
        const uint4* src = (const uint4*)(g_Wp + (size_t)n * 4 * 96 * 52);
        uint4* dst = (uint4*)sW1r;
        for (int idx = t; idx < 4992; idx += 512) dst[idx] = src[idx];
    }

    // radix-8 (stages 4-6) work map: 16 groups x 96 cols = 1536 -> 3/thread
    int j8v[3], c8v[3];
#pragma unroll
    for (int r = 0; r < 3; r++) {
        int idx = r * 512 + t;
        j8v[r] = idx / 96;
        c8v[r] = idx - j8v[r] * 96;
    }

    // ---------------- forward FFT over h ----------------
    // pass 1: radix-16 (stages 0-3, k=0), gathering directly from g_F.
#pragma unroll
    for (int rep = 0; rep < 2; rep++) {
        if (rep == 0 || t < 256) {
            int idx = rep * 512 + t;
            int j = idx / 96, col = idx - j * 96;
            float2 xv[16];
#pragma unroll
            for (int m = 0; m < 16; m++) {
                int h = __brev((unsigned)(j * 16 + m)) >> 25;
                xv[m] = __bfloat1622float2(g_F[base + (size_t)h * CC + col]);
            }
            bf16pt<false>(xv);
            float2* p = tz + (j * 16) * 98 + col;
#pragma unroll
            for (int m = 0; m < 16; m++) p[m * 98] = xv[m];
        }
    }
    __syncthreads();  // also covers weight staging + stw
    // pass 2: radix-8 (stages 4-6), hf=16, k=j
    {
#pragma unroll
        for (int r = 0; r < 3; r++) {
            int j = j8v[r], col = c8v[r];
            float2 w[7];
            w[0] = stw[j << 2];
            w[1] = stw[j << 1];
            w[2] = stw[(j + 16) << 1];
#pragma unroll
            for (int qq = 0; qq < 4; qq++) w[3 + qq] = stw[j + qq * 16];
            float2* p = tz + j * 98 + col;
            float2 xv[8];
#pragma unroll
            for (int m = 0; m < 8; m++) xv[m] = p[(m * 16) * 98];
            bf8(xv, w);
#pragma unroll
            for (int m = 0; m < 8; m++) p[(m * 16) * 98] = xv[m];
        }
        __syncthreads();
    }

    // ---- deinterleave tile -> bf16 A (x 1/128), in place, per-row by warp --
    {
        const float s128 = 0.0078125f;
#pragma unroll
        for (int rr = 0; rr < 8; rr++) {
            int row = warp * 8 + rr;
            float4 q0 = *(float4*)&tz[row * 98 + 2 * lane];
            float4 q1 = make_float4(0.f, 0.f, 0.f, 0.f);
            if (lane < 16)
                q1 = *(float4*)&tz[row * 98 + 2 * (lane + 32)];
            __syncwarp();
            unsigned* Ar = sBIG + row * 196;
            Ar[lane] = bf2(q0.z * s128, q0.x * s128);
            Ar[48 + lane] = bf2(q0.w * s128, q0.y * s128);
            if (lane < 16) {
                Ar[lane + 32] = bf2(q1.z * s128, q1.x * s128);
                Ar[48 + lane + 32] = bf2(q1.w * s128, q1.y * s128);
            }
            __syncwarp();
        }
    }
    __syncthreads();

    // ---------------- MLP ----------------
    const int mgrp = warp & 3, ngrp = warp >> 2;
    const int nh = ngrp >> 1;
    const int jbase = (ngrp & 1) * 6;
    const int g = lane >> 2, tig = lane & 3;
    const int arow = mgrp * 32 + g;

    const unsigned sbigAddr = (unsigned)__cvta_generic_to_shared(sBIG);
    const int matq = lane >> 3;
    const unsigned aBase0 = sbigAddr +
        (unsigned)(((mgrp * 32 + (lane & 7) + (matq & 1) * 8) * 196 +
                    (matq >> 1) * 4) * 4);
    const unsigned aBase1 = aBase0 + 16u * 196u * 4u;
    const unsigned bOff0 = (unsigned)((((jbase * 8 + (matq >> 1) * 8 +
                                         (lane & 7)) * 52) + (matq & 1) * 4) * 4);
    const unsigned pStep = 16u * 52u * 4u;
    const unsigned w1lo = (unsigned)__cvta_generic_to_shared((nh == 0) ? sW1r : sW1i);
    const unsigned w1hi = (unsigned)__cvta_generic_to_shared((nh == 0) ? sW1i : sW1r);
    const unsigned w2lo = (unsigned)__cvta_generic_to_shared((nh == 0) ? sW2r : sW2i);
    const unsigned w2hi = (unsigned)__cvta_generic_to_shared((nh == 0) ? sW2i : sW2r);
    const unsigned sgnHi = (nh == 0) ? 0x80008000u : 0u;

    float acc[2][6][4];

    // ===== layer 1 =====
    {
        const float* bp = (nh == 0) ? (b1 + n * BS) : (b1 + NB * BS + n * BS);
#pragma unroll
        for (int j = 0; j < 6; j++) {
            int cih = (jbase + j) * 8 + 2 * tig;
            float bv0 = bp[cih], bv1 = bp[cih + 1];
#pragma unroll
            for (int mt = 0; mt < 2; mt++) {
                acc[mt][j][0] = bv0; acc[mt][j][1] = bv1;
                acc[mt][j][2] = bv0; acc[mt][j][3] = bv1;
            }
        }
#pragma unroll 2
        for (int kc = 0; kc < 12; kc++) {
            unsigned a0, a1, a2, a3, a4, a5, a6, a7;
            ldsm4(a0, a1, a2, a3, aBase0 + kc * 32);
            ldsm4(a4, a5, a6, a7, aBase1 + kc * 32);
            unsigned sgn = (kc < 6) ? 0u : sgnHi;
            unsigned wA = ((kc < 6) ? w1lo + kc * 32 : w1hi + (kc - 6) * 32) + bOff0;
            unsigned br[12];
#pragma unroll
            for (int p = 0; p < 3; p++) {
                unsigned r0, r1, r2, r3;
                ldsm4(r0, r1, r2, r3, wA + p * pStep);
                br[4 * p] = r0 ^ sgn;
                br[4 * p + 1] = r1 ^ sgn;
                br[4 * p + 2] = r2 ^ sgn;
                br[4 * p + 3] = r3 ^ sgn;
            }
#pragma unroll
            for (int j = 0; j < 6; j++) {
                mma16(acc[0][j], a0, a1, a2, a3, br[2 * j], br[2 * j + 1]);
                mma16(acc[1][j], a4, a5, a6, a7, br[2 * j], br[2 * j + 1]);
            }
        }
    }
    __syncthreads();  // all A reads done

    // write relu(O) over A (packed bf16x2)
#pragma unroll
    for (int j = 0; j < 6; j++) {
        int wcol = nh * 48 + (jbase + j) * 4 + tig;
#pragma unroll
        for (int mt = 0; mt < 2; mt++) {
            int r0 = arow + 16 * mt;
            sBIG[r0 * 196 + wcol] =
                bf2(fmaxf(acc[mt][j][1], 0.f), fmaxf(acc[mt][j][0], 0.f));
            sBIG[(r0 + 8) * 196 + wcol] =
                bf2(fmaxf(acc[mt][j][3], 0.f), fmaxf(acc[mt][j][2], 0.f));
        }
    }
    __syncthreads();

    // ===== layer 2 =====
    {
        const float* bp = (nh == 0) ? (b2 + n * BS) : (b2 + NB * BS + n * BS);
#pragma unroll
        for (int j = 0; j < 6; j++) {
            int cih = (jbase + j) * 8 + 2 * tig;
            float bv0 = bp[cih], bv1 = bp[cih + 1];
#pragma unroll
            for (int mt = 0; mt < 2; mt++) {
                acc[mt][j][0] = bv0; acc[mt][j][1] = bv1;
                acc[mt][j][2] = bv0; acc[mt][j][3] = bv1;
            }
        }
#pragma unroll 2
        for (int kc = 0; kc < 12; kc++) {
            unsigned a0, a1, a2, a3, a4, a5, a6, a7;
            ldsm4(a0, a1, a2, a3, aBase0 + kc * 32);
            ldsm4(a4, a5, a6, a7, aBase1 + kc * 32);
            unsigned sgn = (kc < 6) ? 0u : sgnHi;
            unsigned wA = ((kc < 6) ? w2lo + kc * 32 : w2hi + (kc - 6) * 32) + bOff0;
            unsigned br[12];
#pragma unroll
            for (int p = 0; p < 3; p++) {
                unsigned r0, r1, r2, r3;
                ldsm4(r0, r1, r2, r3, wA + p * pStep);
                br[4 * p] = r0 ^ sgn;
                br[4 * p + 1] = r1 ^ sgn;
                br[4 * p + 2] = r2 ^ sgn;
                br[4 * p + 3] = r3 ^ sgn;
            }
#pragma unroll
            for (int j = 0; j < 6; j++) {
                mma16(acc[0][j], a0, a1, a2, a3, br[2 * j], br[2 * j + 1]);
                mma16(acc[1][j], a4, a5, a6, a7, br[2 * j], br[2 * j + 1]);
            }
        }
    }
    __syncthreads();  // all O reads done

    // softshrink -> float2 tile (bit-reversed rows) for inverse FFT
    {
        float* Tf = (float*)sBIG;
#pragma unroll
        for (int j = 0; j < 6; j++) {
            int ch = (jbase + j) * 8 + 2 * tig;
#pragma unroll
            for (int mt = 0; mt < 2; mt++) {
                int r0 = arow + 16 * mt, r1 = r0 + 8;
                int br0 = __brev((unsigned)r0) >> 25;
                int br1 = __brev((unsigned)r1) >> 25;
                Tf[br0 * 196 + 2 * ch + nh] = sshrink(acc[mt][j][0]);
                Tf[br0 * 196 + 2 * (ch + 1) + nh] = sshrink(acc[mt][j][1]);
                Tf[br1 * 196 + 2 * ch + nh] = sshrink(acc[mt][j][2]);
                Tf[br1 * 196 + 2 * (ch + 1) + nh] = sshrink(acc[mt][j][3]);
            }
        }
    }
    __syncthreads();

    // ---------------- inverse FFT over h (conj twiddles) ----------------
#pragma unroll
    for (int rep = 0; rep < 2; rep++) {
        if (rep == 0 || t < 256) {
            int idx = rep * 512 + t;
            int j = idx / 96, col = idx - j * 96;
            float2* p = tz + (j * 16) * 98 + col;
            float2 xv[16];
#pragma unroll
            for (int m = 0; m < 16; m++) xv[m] = p[m * 98];
            bf16pt<true>(xv);
#pragma unroll
            for (int m = 0; m < 16; m++) p[m * 98] = xv[m];
        }
    }
    __syncthreads();
    // pass 2: radix-8, scatter results directly to g_F
    {
#pragma unroll
        for (int r = 0; r < 3; r++) {
            int j = j8v[r], col = c8v[r];
            float2 w[7];
            w[0] = stw[j << 2];
            w[1] = stw[j << 1];
            w[2] = stw[(j + 16) << 1];
#pragma unroll
            for (int qq = 0; qq < 4; qq++) w[3 + qq] = stw[j + qq * 16];
#pragma unroll
            for (int m = 0; m < 7; m++) w[m].y = -w[m].y;
            float2* p = tz + j * 98 + col;
            float2 xv[8];
#pragma unroll
            for (int m = 0; m < 8; m++) xv[m] = p[(m * 16) * 98];
            bf8(xv, w);
#pragma unroll
            for (int m = 0; m < 8; m++)
                g_F[base + (size_t)(j + m * 16) * CC + col] =
                    __float22bfloat162_rn(xv[m]);
        }
    }
}

// ---------------------------------------------------------------------------
// Pass 5: inverse real FFT length 128 along W + 1/128 scale + residual add.
// Staged untangle (R11 form); 2 radix-8 passes (conj twiddles).
// C2R semantics: imag of DC & Nyquist ignored.
// ---------------------------------------------------------------------------
__global__ __launch_bounds__(512, 2) void k_inv_w(const float* __restrict__ x,
                                                  float* __restrict__ out) {
    extern __shared__ float2 sm2[];
    float2* sz = sm2;               // [64][128]
    float2* stw = sm2 + 64 * 128;   // [65]
    const int t = threadIdx.x;
    if (t < 65) stw[t] = g_tw[t];
    __syncthreads();
    const int cl = t & 127, q = t >> 7;
    const int b = blockIdx.z, h = blockIdx.y;
    const int c = blockIdx.x * 128 + cl;
    size_t base = ((size_t)b * WF * HH + h) * CC + c;
    const size_t ws = (size_t)HH * CC;

#pragma unroll
    for (int jj = 0; jj < 8; jj++) {
        int idx = q * 8 + jj;
        if (idx == 0) {
            float2 X0 = __bfloat1622float2(g_F[base]);
            float2 X64 = __bfloat1622float2(g_F[base + 64 * ws]);
            sz[cl] = make_float2(X0.x + X64.x, X0.x - X64.x);  // imag dropped
            float2 X32 = __bfloat1622float2(g_F[base + 32 * ws]);
            sz[1 * 128 + cl] = make_float2(2.f * X32.x, -2.f * X32.y);
        } else {
            int k = idx;  // 1..31
            float2 Xk = __bfloat1622float2(g_F[base + (size_t)k * ws]);
            float2 Xm = __bfloat1622float2(g_F[base + (size_t)(64 - k) * ws]);
            float2 A = make_float2(Xk.x + Xm.x, Xk.y - Xm.y);
            float2 D = make_float2(Xk.x - Xm.x, Xk.y + Xm.y);
            float2 wc = make_float2(stw[k].x, -stw[k].y);
            float2 tv = cmul(wc, D);
            sz[(__brev((unsigned)k) >> 26) * 128 + cl] =
                make_float2(A.x - tv.y, A.y + tv.x);
            float2 A2 = make_float2(Xm.x + Xk.x, Xm.y - Xk.y);
            float2 D2 = make_float2(Xm.x - Xk.x, Xm.y + Xk.y);
            float2 wc2 = make_float2(stw[64 - k].x, -stw[64 - k].y);
            float2 t2 = cmul(wc2, D2);
            sz[(__brev((unsigned)(64 - k)) >> 26) * 128 + cl] =
                make_float2(A2.x - t2.y, A2.y + t2.x);
        }
    }
    __syncthreads();

#pragma unroll
    for (int s = 0; s <= 3; s += 3) {
        int hf = 1 << s;
#pragma unroll
        for (int rr = 0; rr < 2; rr++) {
            int j = q * 2 + rr;
            int k = j & (hf - 1);
            int i0 = ((j >> s) << (s + 3)) + k;
            float2 w[7];
            w[0] = stw[k << (6 - s)];
            w[1] = stw[k << (5 - s)];
            w[2] = stw[(k + hf) << (5 - s)];
#pragma unroll
            for (int qq = 0; qq < 4; qq++) w[3 + qq] = stw[(k + qq * hf) << (4 - s)];
#pragma unroll
            for (int m = 0; m < 7; m++) w[m].y = -w[m].y;
            float2 xv[8];
#pragma unroll
            for (int m = 0; m < 8; m++) xv[m] = sz[(i0 + m * hf) * 128 + cl];
            bf8(xv, w);
#pragma unroll
            for (int m = 0; m < 8; m++) sz[(i0 + m * hf) * 128 + cl] = xv[m];
        }
        __syncthreads();
    }

    const size_t xbase = ((size_t)(b * HH + h) * WW) * CC + c;
#pragma unroll
    for (int mm = 0; mm < 16; mm++) {
        int m = q * 16 + mm;
        float2 z = sz[m * 128 + cl];
        size_t i0 = xbase + (size_t)(2 * m) * CC;
        size_t i1 = xbase + (size_t)(2 * m + 1) * CC;
        out[i0] = z.x * (1.f / 128.f) + x[i0];
        out[i1] = z.y * (1.f / 128.f) + x[i1];
    }
}

// ---------------------------------------------------------------------------
extern "C" void kernel_launch(void* const* d_in, const int* in_sizes, int n_in,
                              void* d_out, int out_size) {
    const float* x  = (const float*)d_in[0];
    const float* w1 = (const float*)d_in[1];
    const float* b1 = (const float*)d_in[2];
    const float* w2 = (const float*)d_in[3];
    const float* b2 = (const float*)d_in[4];
    float* out = (float*)d_out;

    const size_t sm_fftw = (size_t)(64 * 128 + 65) * sizeof(float2);   // 66056
    const size_t sm_fus  = (size_t)(128 * 196 + 4 * 96 * 52) * 4 + 65 * 8; // ~181 KB

    cudaFuncSetAttribute(k_fwd_w, cudaFuncAttributeMaxDynamicSharedMemorySize, (int)sm_fftw);
    cudaFuncSetAttribute(k_fused, cudaFuncAttributeMaxDynamicSharedMemorySize, (int)sm_fus);
    cudaFuncSetAttribute(k_inv_w, cudaFuncAttributeMaxDynamicSharedMemorySize, (int)sm_fftw);

    k_init_tw<<<1, 128>>>();
    k_pack_w<<<NB, 256>>>(w1, w2);
    k_fwd_w<<<dim3(6, 128, 8), 512, sm_fftw>>>(x);
    k_fused<<<dim3(8, 65, 8), 512, sm_fus>>>(b1, b2);
    k_inv_w<<<dim3(6, 128, 8), 512, sm_fftw>>>(x, out);
}

// round 14
// speedup vs baseline: 4.8099x; 1.0109x over previous
#include <cuda_runtime.h>
#include <cuda_bf16.h>
#include <math.h>

#define BB 8
#define HH 128
#define WW 128
#define CC 768
#define NB 8
#define BS 96
#define WF 65
#define LAMBDA 0.01f

#define C4F 0.70710678118654752440f
#define C8F 0.92387953251128675613f
#define S8F 0.38268343236508977173f

// Frequency-domain scratch (bf16 transport): [b][wf][h][c]
__device__ __nv_bfloat162 g_F[(size_t)BB * WF * HH * CC];
// Twiddles: g_tw[k] = exp(-2*pi*i*k/128), k=0..64
__device__ float2 g_tw[65];
// Pre-packed bf16x2 weight images: [n][4 mats][96 o][52 words]
__device__ __align__(16) unsigned g_Wp[(size_t)NB * 4 * 96 * 52];

__device__ __forceinline__ float2 cmul(float2 a, float2 b) {
    return make_float2(a.x * b.x - a.y * b.y, a.x * b.y + a.y * b.x);
}

// pack two floats to bf16x2 word (hi -> upper 16, lo -> lower 16)
__device__ __forceinline__ unsigned bf2(float hi, float lo) {
    unsigned r;
    asm("cvt.rn.bf16x2.f32 %0, %1, %2;" : "=r"(r) : "f"(hi), "f"(lo));
    return r;
}

// packed complex bf16x2 word <-> float2 (exact widening)
__device__ __forceinline__ float2 upk(unsigned w) {
    return make_float2(__uint_as_float(w << 16),
                       __uint_as_float(w & 0xFFFF0000u));
}
__device__ __forceinline__ unsigned pk(float2 v) { return bf2(v.y, v.x); }

__device__ __forceinline__ void mma16(float c[4], unsigned a0, unsigned a1,
                                      unsigned a2, unsigned a3,
                                      unsigned b0, unsigned b1) {
    asm volatile(
        "mma.sync.aligned.m16n8k16.row.col.f32.bf16.bf16.f32 "
        "{%0,%1,%2,%3}, {%4,%5,%6,%7}, {%8,%9}, {%0,%1,%2,%3};"
        : "+f"(c[0]), "+f"(c[1]), "+f"(c[2]), "+f"(c[3])
        : "r"(a0), "r"(a1), "r"(a2), "r"(a3), "r"(b0), "r"(b1));
}

__device__ __forceinline__ void ldsm4(unsigned& r0, unsigned& r1,
                                      unsigned& r2, unsigned& r3,
                                      unsigned addr) {
    asm volatile(
        "ldmatrix.sync.aligned.m8n8.x4.shared.b16 {%0,%1,%2,%3}, [%4];"
        : "=r"(r0), "=r"(r1), "=r"(r2), "=r"(r3)
        : "r"(addr));
}

__device__ __forceinline__ float sshrink(float v) {
    return v > LAMBDA ? v - LAMBDA : (v < -LAMBDA ? v + LAMBDA : 0.f);
}

__global__ void k_init_tw() {
    int i = threadIdx.x;
    if (i < 65) {
        double a = -2.0 * 3.14159265358979323846264338327950288 * (double)i / 128.0;
        g_tw[i] = make_float2((float)cos(a), (float)sin(a));
    }
}

// ---------------------------------------------------------------------------
// Pre-pack weights into the exact padded smem image (bf16x2, [o][i-word]).
// ---------------------------------------------------------------------------
__global__ void k_pack_w(const float* __restrict__ w1,
                         const float* __restrict__ w2) {
    const int n = blockIdx.x, t = threadIdx.x;
    const float* src[4] = {w1 + n * BS * BS, w1 + NB * BS * BS + n * BS * BS,
                           w2 + n * BS * BS, w2 + NB * BS * BS + n * BS * BS};
    unsigned* dst = g_Wp + (size_t)n * 4 * 96 * 52;
    for (int idx = t; idx < 96 * 52; idx += 256) {
        int o = idx / 52, iw = idx - o * 52;
#pragma unroll
        for (int m = 0; m < 4; m++) {
            unsigned v = 0u;
            if (iw < 48) {
                int i0 = 2 * iw;
                v = bf2(src[m][(i0 + 1) * 96 + o], src[m][i0 * 96 + o]);
            }
            dst[m * 96 * 52 + idx] = v;
        }
    }
}

// ----- register butterflies -----
template <bool INV>
__device__ __forceinline__ float2 rot90(float2 v) {
    return INV ? make_float2(-v.y, v.x) : make_float2(v.y, -v.x);
}

template <bool INV>
__device__ __forceinline__ void bf4_0(float2& x0, float2& x1, float2& x2,
                                      float2& x3) {
    float2 y0 = make_float2(x0.x + x1.x, x0.y + x1.y);
    float2 y1 = make_float2(x0.x - x1.x, x0.y - x1.y);
    float2 y2 = make_float2(x2.x + x3.x, x2.y + x3.y);
    float2 y3 = make_float2(x2.x - x3.x, x2.y - x3.y);
    float2 u3 = rot90<INV>(y3);
    x0 = make_float2(y0.x + y2.x, y0.y + y2.y);
    x2 = make_float2(y0.x - y2.x, y0.y - y2.y);
    x1 = make_float2(y1.x + u3.x, y1.y + u3.y);
    x3 = make_float2(y1.x - u3.x, y1.y - u3.y);
}

template <bool INV>
__device__ __forceinline__ void bf8_0(float2* x) {
    bf4_0<INV>(x[0], x[1], x[2], x[3]);
    bf4_0<INV>(x[4], x[5], x[6], x[7]);
    const float I = INV ? 1.f : -1.f;
    const float2 t1 = make_float2(C4F, I * C4F);
    const float2 t3 = make_float2(-C4F, I * C4F);
    { float2 a = x[0], u = x[4];
      x[0] = make_float2(a.x + u.x, a.y + u.y);
      x[4] = make_float2(a.x - u.x, a.y - u.y); }
    { float2 a = x[1], u = cmul(x[5], t1);
      x[1] = make_float2(a.x + u.x, a.y + u.y);
      x[5] = make_float2(a.x - u.x, a.y - u.y); }
    { float2 a = x[2], u = rot90<INV>(x[6]);
      x[2] = make_float2(a.x + u.x, a.y + u.y);
      x[6] = make_float2(a.x - u.x, a.y - u.y); }
    { float2 a = x[3], u = cmul(x[7], t3);
      x[3] = make_float2(a.x + u.x, a.y + u.y);
      x[7] = make_float2(a.x - u.x, a.y - u.y); }
}

template <bool INV>
__device__ __forceinline__ void bf16pt(float2* x) {
    bf8_0<INV>(x);
    bf8_0<INV>(x + 8);
    const float I = INV ? 1.f : -1.f;
    const float2 w1 = make_float2(C8F, I * S8F);
    const float2 w2 = make_float2(C4F, I * C4F);
    const float2 w3 = make_float2(S8F, I * C8F);
    const float2 w5 = make_float2(-S8F, I * C8F);
    const float2 w6 = make_float2(-C4F, I * C4F);
    const float2 w7 = make_float2(-C8F, I * S8F);
#pragma unroll
    for (int m = 0; m < 8; m++) {
        float2 u;
        if (m == 0) u = x[8];
        else if (m == 1) u = cmul(x[9], w1);
        else if (m == 2) u = cmul(x[10], w2);
        else if (m == 3) u = cmul(x[11], w3);
        else if (m == 4) u = rot90<INV>(x[12]);
        else if (m == 5) u = cmul(x[13], w5);
        else if (m == 6) u = cmul(x[14], w6);
        else u = cmul(x[15], w7);
        float2 a = x[m];
        x[m] = make_float2(a.x + u.x, a.y + u.y);
        x[m + 8] = make_float2(a.x - u.x, a.y - u.y);
    }
}

// Generic radix-2^3 with provided twiddles (w[0]; w[1],w[2]; w[3..6]).
__device__ __forceinline__ void bf8(float2 x[8], const float2 w[7]) {
    float2 t1 = cmul(x[1], w[0]), t3 = cmul(x[3], w[0]);
    float2 y0 = make_float2(x[0].x + t1.x, x[0].y + t1.y);
    float2 y1 = make_float2(x[0].x - t1.x, x[0].y - t1.y);
    float2 y2 = make_float2(x[2].x + t3.x, x[2].y + t3.y);
    float2 y3 = make_float2(x[2].x - t3.x, x[2].y - t3.y);
    float2 u2 = cmul(y2, w[1]), u3 = cmul(y3, w[2]);
    x[0] = make_float2(y0.x + u2.x, y0.y + u2.y);
    x[2] = make_float2(y0.x - u2.x, y0.y - u2.y);
    x[1] = make_float2(y1.x + u3.x, y1.y + u3.y);
    x[3] = make_float2(y1.x - u3.x, y1.y - u3.y);
    float2 t5 = cmul(x[5], w[0]), t7 = cmul(x[7], w[0]);
    float2 z0 = make_float2(x[4].x + t5.x, x[4].y + t5.y);
    float2 z1 = make_float2(x[4].x - t5.x, x[4].y - t5.y);
    float2 z2 = make_float2(x[6].x + t7.x, x[6].y + t7.y);
    float2 z3 = make_float2(x[6].x - t7.x, x[6].y - t7.y);
    float2 v2 = cmul(z2, w[1]), v3 = cmul(z3, w[2]);
    x[4] = make_float2(z0.x + v2.x, z0.y + v2.y);
    x[6] = make_float2(z0.x - v2.x, z0.y - v2.y);
    x[5] = make_float2(z1.x + v3.x, z1.y + v3.y);
    x[7] = make_float2(z1.x - v3.x, z1.y - v3.y);
#pragma unroll
    for (int q = 0; q < 4; q++) {
        float2 u = cmul(x[q + 4], w[3 + q]);
        float2 a = x[q];
        x[q] = make_float2(a.x + u.x, a.y + u.y);
        x[q + 4] = make_float2(a.x - u.x, a.y - u.y);
    }
}

// ---------------------------------------------------------------------------
// Pass 1: real FFT length 128 along W (pack-in-pairs), 2 radix-8 passes.
// ---------------------------------------------------------------------------
__global__ __launch_bounds__(512, 2) void k_fwd_w(const float* __restrict__ x) {
    extern __shared__ float2 sm2[];
    float2* sz = sm2;               // [64][128]
    float2* stw = sm2 + 64 * 128;   // [65]
    const int t = threadIdx.x;
    if (t < 65) stw[t] = g_tw[t];
    const int cl = t & 127, q = t >> 7;
    const int b = blockIdx.z, h = blockIdx.y;
    const int c = blockIdx.x * 128 + cl;
    const float* xp = x + ((size_t)(b * HH + h) * WW) * CC + c;

#pragma unroll
    for (int rr = 0; rr < 2; rr++) {
        int j = q * 2 + rr;
        float2 xv[8];
#pragma unroll
        for (int m = 0; m < 8; m++) {
            int mm = __brev((unsigned)(j * 8 + m)) >> 26;
            xv[m] = make_float2(xp[(size_t)(2 * mm) * CC],
                                xp[(size_t)(2 * mm + 1) * CC]);
        }
        bf8_0<false>(xv);
#pragma unroll
        for (int m = 0; m < 8; m++) sz[(j * 8 + m) * 128 + cl] = xv[m];
    }
    __syncthreads();

#pragma unroll
    for (int rr = 0; rr < 2; rr++) {
        int j = q * 2 + rr;
        float2 w[7];
        w[0] = stw[j << 3];
        w[1] = stw[j << 2];
        w[2] = stw[(j + 8) << 2];
#pragma unroll
        for (int qq = 0; qq < 4; qq++) w[3 + qq] = stw[(j + qq * 8) << 1];
        float2 xv[8];
#pragma unroll
        for (int m = 0; m < 8; m++) xv[m] = sz[(j + m * 8) * 128 + cl];
        bf8(xv, w);
#pragma unroll
        for (int m = 0; m < 8; m++) sz[(j + m * 8) * 128 + cl] = xv[m];
    }
    __syncthreads();

    size_t base = ((size_t)b * WF * HH + h) * CC + c;
    const size_t ws = (size_t)HH * CC;
#pragma unroll
    for (int jj = 0; jj < 8; jj++) {
        int idx = q * 8 + jj;
        if (idx == 0) {
            float2 Z0 = sz[cl];
            g_F[base] = __float22bfloat162_rn(make_float2(Z0.x + Z0.y, 0.f));
            g_F[base + 64 * ws] = __float22bfloat162_rn(make_float2(Z0.x - Z0.y, 0.f));
            float2 Z32 = sz[32 * 128 + cl];
            g_F[base + 32 * ws] = __float22bfloat162_rn(make_float2(Z32.x, -Z32.y));
        } else {
            int k = idx;  // 1..31
            float2 Zk = sz[k * 128 + cl];
            float2 Zm = sz[(64 - k) * 128 + cl];
            float2 E = make_float2(0.5f * (Zk.x + Zm.x), 0.5f * (Zk.y - Zm.y));
            float2 D = make_float2(0.5f * (Zk.x - Zm.x), 0.5f * (Zk.y + Zm.y));
            float2 O = make_float2(D.y, -D.x);
            float2 p = cmul(stw[k], O);
            g_F[base + (size_t)k * ws] =
                __float22bfloat162_rn(make_float2(E.x + p.x, E.y + p.y));
            float2 Ec = make_float2(E.x, -E.y);
            float2 Oc = make_float2(O.x, -O.y);
            float2 qv = cmul(stw[64 - k], Oc);
            g_F[base + (size_t)(64 - k) * ws] =
                __float22bfloat162_rn(make_float2(Ec.x + qv.x, Ec.y + qv.y));
        }
    }
}

// ---------------------------------------------------------------------------
// Fused pass: FFT-H fwd + complex MLP + FFT-H inv, bf16-resident tile.
// Regions: sA [128][100] words (A/O), sT [128][100] words (packed bf16x2
// complex tile), 4 weight mats [96][52].
// Forward pass-2 writes the A matrix directly (col-pair butterflies).
// ---------------------------------------------------------------------------
__global__ __launch_bounds__(512, 1) void k_fused(const float* __restrict__ b1,
                                                  const float* __restrict__ b2) {
    extern __shared__ unsigned smu[];
    unsigned* sA = smu;                           // [128][100] words
    unsigned* sT = smu + 12800;                   // [128][100] words
    unsigned* sW1r = smu + 25600;                 // [96][52]
    unsigned* sW1i = sW1r + 4992;
    unsigned* sW2r = sW1i + 4992;
    unsigned* sW2i = sW2r + 4992;
    float2* stw = (float2*)(sW2i + 4992);         // [65]

    const int t = threadIdx.x;
    const int lane = t & 31, warp = t >> 5;
    if (t < 65) stw[t] = g_tw[t];
    const int n = blockIdx.x, wf = blockIdx.y, b = blockIdx.z;
    const size_t base = ((size_t)(b * WF + wf) * HH) * CC + n * BS;
    const unsigned* gFu = (const unsigned*)g_F;

    // Stage all four weight images (uint4 memcpy from g_Wp[n])
    {
        const uint4* src = (const uint4*)(g_Wp + (size_t)n * 4 * 96 * 52);
        uint4* dst = (uint4*)sW1r;
        for (int idx = t; idx < 4992; idx += 512) dst[idx] = src[idx];
    }

    // inverse pass-2 work map: 16 j x 96 cols = 1536 -> 3/thread
    int j8v[3], c8v[3];
#pragma unroll
    for (int r = 0; r < 3; r++) {
        int idx = r * 512 + t;
        j8v[r] = idx / 96;
        c8v[r] = idx - j8v[r] * 96;
    }

    // -------- forward pass 1: radix-16 (k=0) from g_F -> packed tile --------
#pragma unroll
    for (int rep = 0; rep < 2; rep++) {
        if (rep == 0 || t < 256) {
            int idx = rep * 512 + t;
            int j = idx / 96, col = idx - j * 96;
            float2 xv[16];
#pragma unroll
            for (int m = 0; m < 16; m++) {
                int h = __brev((unsigned)(j * 16 + m)) >> 25;
                xv[m] = upk(gFu[base + (size_t)h * CC + col]);
            }
            bf16pt<false>(xv);
            unsigned* p = sT + (j * 16) * 100 + col;
#pragma unroll
            for (int m = 0; m < 16; m++) p[m * 100] = pk(xv[m]);
        }
    }
    __syncthreads();  // covers weight staging + stw

    // -------- forward pass 2: radix-8, col pairs, writes A directly --------
    {
        const float s128 = 0.0078125f;
#pragma unroll
        for (int rep = 0; rep < 2; rep++) {
            if (rep == 0 || t < 256) {
                int idx = rep * 512 + t;
                int j = idx / 48, w2i = idx - j * 48;
                float2 w[7];
                w[0] = stw[j << 2];
                w[1] = stw[j << 1];
                w[2] = stw[(j + 16) << 1];
#pragma unroll
                for (int qq = 0; qq < 4; qq++) w[3 + qq] = stw[j + qq * 16];
                float2 xa[8], xb[8];
#pragma unroll
                for (int m = 0; m < 8; m++) {
                    int row = j + m * 16;
                    uint2 v = *(uint2*)&sT[row * 100 + 2 * w2i];
                    xa[m] = upk(v.x);
                    xb[m] = upk(v.y);
                }
                bf8(xa, w);
                bf8(xb, w);
#pragma unroll
                for (int m = 0; m < 8; m++) {
                    int row = j + m * 16;
                    sA[row * 100 + w2i] = bf2(xb[m].x * s128, xa[m].x * s128);
                    sA[row * 100 + 48 + w2i] = bf2(xb[m].y * s128, xa[m].y * s128);
                }
            }
        }
    }
    __syncthreads();

    // ---------------- MLP ----------------
    const int mgrp = warp & 3, ngrp = warp >> 2;
    const int nh = ngrp >> 1;
    const int jbase = (ngrp & 1) * 6;
    const int g = lane >> 2, tig = lane & 3;
    const int arow = mgrp * 32 + g;

    const unsigned sAaddr = (unsigned)__cvta_generic_to_shared(sA);
    const int matq = lane >> 3;
    const unsigned aBase0 = sAaddr +
        (unsigned)(((mgrp * 32 + (lane & 7) + (matq & 1) * 8) * 100 +
                    (matq >> 1) * 4) * 4);
    const unsigned aBase1 = aBase0 + 16u * 100u * 4u;
    const unsigned bOff0 = (unsigned)((((jbase * 8 + (matq >> 1) * 8 +
                                         (lane & 7)) * 52) + (matq & 1) * 4) * 4);
    const unsigned pStep = 16u * 52u * 4u;
    const unsigned w1lo = (unsigned)__cvta_generic_to_shared((nh == 0) ? sW1r : sW1i);
    const unsigned w1hi = (unsigned)__cvta_generic_to_shared((nh == 0) ? sW1i : sW1r);
    const unsigned w2lo = (unsigned)__cvta_generic_to_shared((nh == 0) ? sW2r : sW2i);
    const unsigned w2hi = (unsigned)__cvta_generic_to_shared((nh == 0) ? sW2i : sW2r);
    const unsigned sgnHi = (nh == 0) ? 0x80008000u : 0u;

    float acc[2][6][4];

    // ===== layer 1 =====
    {
        const float* bp = (nh == 0) ? (b1 + n * BS) : (b1 + NB * BS + n * BS);
#pragma unroll
        for (int j = 0; j < 6; j++) {
            int cih = (jbase + j) * 8 + 2 * tig;
            float bv0 = bp[cih], bv1 = bp[cih + 1];
#pragma unroll
            for (int mt = 0; mt < 2; mt++) {
                acc[mt][j][0] = bv0; acc[mt][j][1] = bv1;
                acc[mt][j][2] = bv0; acc[mt][j][3] = bv1;
            }
        }
#pragma unroll 2
        for (int kc = 0; kc < 12; kc++) {
            unsigned a0, a1, a2, a3, a4, a5, a6, a7;
            ldsm4(a0, a1, a2, a3, aBase0 + kc * 32);
            ldsm4(a4, a5, a6, a7, aBase1 + kc * 32);
            unsigned sgn = (kc < 6) ? 0u : sgnHi;
            unsigned wA = ((kc < 6) ? w1lo + kc * 32 : w1hi + (kc - 6) * 32) + bOff0;
            unsigned br[12];
#pragma unroll
            for (int p = 0; p < 3; p++) {
                unsigned r0, r1, r2, r3;
                ldsm4(r0, r1, r2, r3, wA + p * pStep);
                br[4 * p] = r0 ^ sgn;
                br[4 * p + 1] = r1 ^ sgn;
                br[4 * p + 2] = r2 ^ sgn;
                br[4 * p + 3] = r3 ^ sgn;
            }
#pragma unroll
            for (int j = 0; j < 6; j++) {
                mma16(acc[0][j], a0, a1, a2, a3, br[2 * j], br[2 * j + 1]);
                mma16(acc[1][j], a4, a5, a6, a7, br[2 * j], br[2 * j + 1]);
            }
        }
    }
    __syncthreads();  // all A reads done

    // write relu(O) over A (packed bf16x2)
#pragma unroll
    for (int j = 0; j < 6; j++) {
        int wcol = nh * 48 + (jbase + j) * 4 + tig;
#pragma unroll
        for (int mt = 0; mt < 2; mt++) {
            int r0 = arow + 16 * mt;
            sA[r0 * 100 + wcol] =
                bf2(fmaxf(acc[mt][j][1], 0.f), fmaxf(acc[mt][j][0], 0.f));
            sA[(r0 + 8) * 100 + wcol] =
                bf2(fmaxf(acc[mt][j][3], 0.f), fmaxf(acc[mt][j][2], 0.f));
        }
    }
    __syncthreads();

    // ===== layer 2 =====
    {
        const float* bp = (nh == 0) ? (b2 + n * BS) : (b2 + NB * BS + n * BS);
#pragma unroll
        for (int j = 0; j < 6; j++) {
            int cih = (jbase + j) * 8 + 2 * tig;
            float bv0 = bp[cih], bv1 = bp[cih + 1];
#pragma unroll
            for (int mt = 0; mt < 2; mt++) {
                acc[mt][j][0] = bv0; acc[mt][j][1] = bv1;
                acc[mt][j][2] = bv0; acc[mt][j][3] = bv1;
            }
        }
#pragma unroll 2
        for (int kc = 0; kc < 12; kc++) {
            unsigned a0, a1, a2, a3, a4, a5, a6, a7;
            ldsm4(a0, a1, a2, a3, aBase0 + kc * 32);
            ldsm4(a4, a5, a6, a7, aBase1 + kc * 32);
            unsigned sgn = (kc < 6) ? 0u : sgnHi;
            unsigned wA = ((kc < 6) ? w2lo + kc * 32 : w2hi + (kc - 6) * 32) + bOff0;
            unsigned br[12];
#pragma unroll
            for (int p = 0; p < 3; p++) {
                unsigned r0, r1, r2, r3;
                ldsm4(r0, r1, r2, r3, wA + p * pStep);
                br[4 * p] = r0 ^ sgn;
                br[4 * p + 1] = r1 ^ sgn;
                br[4 * p + 2] = r2 ^ sgn;
                br[4 * p + 3] = r3 ^ sgn;
            }
#pragma unroll
            for (int j = 0; j < 6; j++) {
                mma16(acc[0][j], a0, a1, a2, a3, br[2 * j], br[2 * j + 1]);
                mma16(acc[1][j], a4, a5, a6, a7, br[2 * j], br[2 * j + 1]);
            }
        }
    }
    __syncthreads();  // all O reads done

    // softshrink -> packed bf16 tile (bit-reversed rows), 16-bit stores
    {
        __nv_bfloat16* T16 = (__nv_bfloat16*)sT;
#pragma unroll
        for (int j = 0; j < 6; j++) {
            int ch = (jbase + j) * 8 + 2 * tig;
#pragma unroll
            for (int mt = 0; mt < 2; mt++) {
                int r0 = arow + 16 * mt, r1 = r0 + 8;
                int br0 = __brev((unsigned)r0) >> 25;
                int br1 = __brev((unsigned)r1) >> 25;
                T16[br0 * 200 + 2 * ch + nh] =
                    __float2bfloat16_rn(sshrink(acc[mt][j][0]));
                T16[br0 * 200 + 2 * (ch + 1) + nh] =
                    __float2bfloat16_rn(sshrink(acc[mt][j][1]));
                T16[br1 * 200 + 2 * ch + nh] =
                    __float2bfloat16_rn(sshrink(acc[mt][j][2]));
                T16[br1 * 200 + 2 * (ch + 1) + nh] =
                    __float2bfloat16_rn(sshrink(acc[mt][j][3]));
            }
        }
    }
    __syncthreads();

    // -------- inverse pass 1: radix-16 (k=0), packed tile in place --------
#pragma unroll
    for (int rep = 0; rep < 2; rep++) {
        if (rep == 0 || t < 256) {
            int idx = rep * 512 + t;
            int j = idx / 96, col = idx - j * 96;
            unsigned* p = sT + (j * 16) * 100 + col;
            float2 xv[16];
#pragma unroll
            for (int m = 0; m < 16; m++) xv[m] = upk(p[m * 100]);
            bf16pt<true>(xv);
#pragma unroll
            for (int m = 0; m < 16; m++) p[m * 100] = pk(xv[m]);
        }
    }
    __syncthreads();

    // -------- inverse pass 2: radix-8, scatter directly to g_F --------
    {
#pragma unroll
        for (int r = 0; r < 3; r++) {
            int j = j8v[r], col = c8v[r];
            float2 w[7];
            w[0] = stw[j << 2];
            w[1] = stw[j << 1];
            w[2] = stw[(j + 16) << 1];
#pragma unroll
            for (int qq = 0; qq < 4; qq++) w[3 + qq] = stw[j + qq * 16];
#pragma unroll
            for (int m = 0; m < 7; m++) w[m].y = -w[m].y;
            float2 xv[8];
#pragma unroll
            for (int m = 0; m < 8; m++)
                xv[m] = upk(sT[(j + m * 16) * 100 + col]);
            bf8(xv, w);
#pragma unroll
            for (int m = 0; m < 8; m++)
                g_F[base + (size_t)(j + m * 16) * CC + col] =
                    __float22bfloat162_rn(xv[m]);
        }
    }
}

// ---------------------------------------------------------------------------
// Pass 5: inverse real FFT length 128 along W + 1/128 scale + residual add.
// ---------------------------------------------------------------------------
__global__ __launch_bounds__(512, 2) void k_inv_w(const float* __restrict__ x,
                                                  float* __restrict__ out) {
    extern __shared__ float2 sm2[];
    float2* sz = sm2;               // [64][128]
    float2* stw = sm2 + 64 * 128;   // [65]
    const int t = threadIdx.x;
    if (t < 65) stw[t] = g_tw[t];
    __syncthreads();
    const int cl = t & 127, q = t >> 7;
    const int b = blockIdx.z, h = blockIdx.y;
    const int c = blockIdx.x * 128 + cl;
    size_t base = ((size_t)b * WF * HH + h) * CC + c;
    const size_t ws = (size_t)HH * CC;

#pragma unroll
    for (int jj = 0; jj < 8; jj++) {
        int idx = q * 8 + jj;
        if (idx == 0) {
            float2 X0 = __bfloat1622float2(g_F[base]);
            float2 X64 = __bfloat1622float2(g_F[base + 64 * ws]);
            sz[cl] = make_float2(X0.x + X64.x, X0.x - X64.x);  // imag dropped
            float2 X32 = __bfloat1622float2(g_F[base + 32 * ws]);
            sz[1 * 128 + cl] = make_float2(2.f * X32.x, -2.f * X32.y);
        } else {
            int k = idx;  // 1..31
            float2 Xk = __bfloat1622float2(g_F[base + (size_t)k * ws]);
            float2 Xm = __bfloat1622float2(g_F[base + (size_t)(64 - k) * ws]);
            float2 A = make_float2(Xk.x + Xm.x, Xk.y - Xm.y);
            float2 D = make_float2(Xk.x - Xm.x, Xk.y + Xm.y);
            float2 wc = make_float2(stw[k].x, -stw[k].y);
            float2 tv = cmul(wc, D);
            sz[(__brev((unsigned)k) >> 26) * 128 + cl] =
                make_float2(A.x - tv.y, A.y + tv.x);
            float2 A2 = make_float2(Xm.x + Xk.x, Xm.y - Xk.y);
            float2 D2 = make_float2(Xm.x - Xk.x, Xm.y + Xk.y);
            float2 wc2 = make_float2(stw[64 - k].x, -stw[64 - k].y);
            float2 t2 = cmul(wc2, D2);
            sz[(__brev((unsigned)(64 - k)) >> 26) * 128 + cl] =
                make_float2(A2.x - t2.y, A2.y + t2.x);
        }
    }
    __syncthreads();

#pragma unroll
    for (int s = 0; s <= 3; s += 3) {
        int hf = 1 << s;
#pragma unroll
        for (int rr = 0; rr < 2; rr++) {
            int j = q * 2 + rr;
            int k = j & (hf - 1);
            int i0 = ((j >> s) << (s + 3)) + k;
            float2 w[7];
            w[0] = stw[k << (6 - s)];
            w[1] = stw[k << (5 - s)];
            w[2] = stw[(k + hf) << (5 - s)];
#pragma unroll
            for (int qq = 0; qq < 4; qq++) w[3 + qq] = stw[(k + qq * hf) << (4 - s)];
#pragma unroll
            for (int m = 0; m < 7; m++) w[m].y = -w[m].y;
            float2 xv[8];
#pragma unroll
            for (int m = 0; m < 8; m++) xv[m] = sz[(i0 + m * hf) * 128 + cl];
            bf8(xv, w);
#pragma unroll
            for (int m = 0; m < 8; m++) sz[(i0 + m * hf) * 128 + cl] = xv[m];
        }
        __syncthreads();
    }

    const size_t xbase = ((size_t)(b * HH + h) * WW) * CC + c;
#pragma unroll
    for (int mm = 0; mm < 16; mm++) {
        int m = q * 16 + mm;
        float2 z = sz[m * 128 + cl];
        size_t i0 = xbase + (size_t)(2 * m) * CC;
        size_t i1 = xbase + (size_t)(2 * m + 1) * CC;
        out[i0] = z.x * (1.f / 128.f) + x[i0];
        out[i1] = z.y * (1.f / 128.f) + x[i1];
    }
}

// ---------------------------------------------------------------------------
extern "C" void kernel_launch(void* const* d_in, const int* in_sizes, int n_in,
                              void* d_out, int out_size) {
    const float* x  = (const float*)d_in[0];
    const float* w1 = (const float*)d_in[1];
    const float* b1 = (const float*)d_in[2];
    const float* w2 = (const float*)d_in[3];
    const float* b2 = (const float*)d_in[4];
    float* out = (float*)d_out;

    const size_t sm_fftw = (size_t)(64 * 128 + 65) * sizeof(float2);       // 66056
    const size_t sm_fus  = (size_t)(2 * 12800 + 4 * 4992) * 4 + 65 * 8;    // 182792

    cudaFuncSetAttribute(k_fwd_w, cudaFuncAttributeMaxDynamicSharedMemorySize, (int)sm_fftw);
    cudaFuncSetAttribute(k_fused, cudaFuncAttributeMaxDynamicSharedMemorySize, (int)sm_fus);
    cudaFuncSetAttribute(k_inv_w, cudaFuncAttributeMaxDynamicSharedMemorySize, (int)sm_fftw);

    k_init_tw<<<1, 128>>>();
    k_pack_w<<<NB, 256>>>(w1, w2);
    k_fwd_w<<<dim3(6, 128, 8), 512, sm_fftw>>>(x);
    k_fused<<<dim3(8, 65, 8), 512, sm_fus>>>(b1, b2);
    k_inv_w<<<dim3(6, 128, 8), 512, sm_fftw>>>(x, out);
}

// round 15
// speedup vs baseline: 5.1688x; 1.0746x over previous
#include <cuda_runtime.h>
#include <cuda_bf16.h>
#include <math.h>

#define BB 8
#define HH 128
#define WW 128
#define CC 768
#define NB 8
#define BS 96
#define WF 65
#define LAMBDA 0.01f

#define C4F 0.70710678118654752440f
#define C8F 0.92387953251128675613f
#define S8F 0.38268343236508977173f

// Frequency-domain scratch (bf16 transport): [b][wf][h][c]
__device__ __nv_bfloat162 g_F[(size_t)BB * WF * HH * CC];
// Twiddles: g_tw[k] = exp(-2*pi*i*k/128), k=0..64
__device__ float2 g_tw[65];
// Pre-packed bf16x2 weight images: [n][4 mats][96 o][52 words]
__device__ __align__(16) unsigned g_Wp[(size_t)NB * 4 * 96 * 52];

__device__ __forceinline__ float2 cmul(float2 a, float2 b) {
    return make_float2(a.x * b.x - a.y * b.y, a.x * b.y + a.y * b.x);
}

__device__ __forceinline__ unsigned bf2(float hi, float lo) {
    unsigned r;
    asm("cvt.rn.bf16x2.f32 %0, %1, %2;" : "=r"(r) : "f"(hi), "f"(lo));
    return r;
}

// packed complex bf16x2 word <-> float2 (exact widening)
__device__ __forceinline__ float2 upk(unsigned w) {
    return make_float2(__uint_as_float(w << 16),
                       __uint_as_float(w & 0xFFFF0000u));
}
__device__ __forceinline__ unsigned pk(float2 v) { return bf2(v.y, v.x); }

__device__ __forceinline__ void mma16(float c[4], unsigned a0, unsigned a1,
                                      unsigned a2, unsigned a3,
                                      unsigned b0, unsigned b1) {
    asm volatile(
        "mma.sync.aligned.m16n8k16.row.col.f32.bf16.bf16.f32 "
        "{%0,%1,%2,%3}, {%4,%5,%6,%7}, {%8,%9}, {%0,%1,%2,%3};"
        : "+f"(c[0]), "+f"(c[1]), "+f"(c[2]), "+f"(c[3])
        : "r"(a0), "r"(a1), "r"(a2), "r"(a3), "r"(b0), "r"(b1));
}

__device__ __forceinline__ void ldsm4(unsigned& r0, unsigned& r1,
                                      unsigned& r2, unsigned& r3,
                                      unsigned addr) {
    asm volatile(
        "ldmatrix.sync.aligned.m8n8.x4.shared.b16 {%0,%1,%2,%3}, [%4];"
        : "=r"(r0), "=r"(r1), "=r"(r2), "=r"(r3)
        : "r"(addr));
}

__device__ __forceinline__ float sshrink(float v) {
    return v > LAMBDA ? v - LAMBDA : (v < -LAMBDA ? v + LAMBDA : 0.f);
}

__global__ void k_init_tw() {
    int i = threadIdx.x;
    if (i < 65) {
        double a = -2.0 * 3.14159265358979323846264338327950288 * (double)i / 128.0;
        g_tw[i] = make_float2((float)cos(a), (float)sin(a));
    }
}

// ---------------------------------------------------------------------------
// Pre-pack weights into the exact padded smem image (bf16x2, [o][i-word]).
// mats: 0=W1r, 1=W1i, 2=W2r, 3=W2i.
// ---------------------------------------------------------------------------
__global__ void k_pack_w(const float* __restrict__ w1,
                         const float* __restrict__ w2) {
    const int n = blockIdx.x, t = threadIdx.x;
    const float* src[4] = {w1 + n * BS * BS, w1 + NB * BS * BS + n * BS * BS,
                           w2 + n * BS * BS, w2 + NB * BS * BS + n * BS * BS};
    unsigned* dst = g_Wp + (size_t)n * 4 * 96 * 52;
    for (int idx = t; idx < 96 * 52; idx += 256) {
        int o = idx / 52, iw = idx - o * 52;
#pragma unroll
        for (int m = 0; m < 4; m++) {
            unsigned v = 0u;
            if (iw < 48) {
                int i0 = 2 * iw;
                v = bf2(src[m][(i0 + 1) * 96 + o], src[m][i0 * 96 + o]);
            }
            dst[m * 96 * 52 + idx] = v;
        }
    }
}

// ----- register butterflies -----
template <bool INV>
__device__ __forceinline__ float2 rot90(float2 v) {
    return INV ? make_float2(-v.y, v.x) : make_float2(v.y, -v.x);
}

template <bool INV>
__device__ __forceinline__ void bf4_0(float2& x0, float2& x1, float2& x2,
                                      float2& x3) {
    float2 y0 = make_float2(x0.x + x1.x, x0.y + x1.y);
    float2 y1 = make_float2(x0.x - x1.x, x0.y - x1.y);
    float2 y2 = make_float2(x2.x + x3.x, x2.y + x3.y);
    float2 y3 = make_float2(x2.x - x3.x, x2.y - x3.y);
    float2 u3 = rot90<INV>(y3);
    x0 = make_float2(y0.x + y2.x, y0.y + y2.y);
    x2 = make_float2(y0.x - y2.x, y0.y - y2.y);
    x1 = make_float2(y1.x + u3.x, y1.y + u3.y);
    x3 = make_float2(y1.x - u3.x, y1.y - u3.y);
}

template <bool INV>
__device__ __forceinline__ void bf8_0(float2* x) {
    bf4_0<INV>(x[0], x[1], x[2], x[3]);
    bf4_0<INV>(x[4], x[5], x[6], x[7]);
    const float I = INV ? 1.f : -1.f;
    const float2 t1 = make_float2(C4F, I * C4F);
    const float2 t3 = make_float2(-C4F, I * C4F);
    { float2 a = x[0], u = x[4];
      x[0] = make_float2(a.x + u.x, a.y + u.y);
      x[4] = make_float2(a.x - u.x, a.y - u.y); }
    { float2 a = x[1], u = cmul(x[5], t1);
      x[1] = make_float2(a.x + u.x, a.y + u.y);
      x[5] = make_float2(a.x - u.x, a.y - u.y); }
    { float2 a = x[2], u = rot90<INV>(x[6]);
      x[2] = make_float2(a.x + u.x, a.y + u.y);
      x[6] = make_float2(a.x - u.x, a.y - u.y); }
    { float2 a = x[3], u = cmul(x[7], t3);
      x[3] = make_float2(a.x + u.x, a.y + u.y);
      x[7] = make_float2(a.x - u.x, a.y - u.y); }
}

template <bool INV>
__device__ __forceinline__ void bf16pt(float2* x) {
    bf8_0<INV>(x);
    bf8_0<INV>(x + 8);
    const float I = INV ? 1.f : -1.f;
    const float2 w1 = make_float2(C8F, I * S8F);
    const float2 w2 = make_float2(C4F, I * C4F);
    const float2 w3 = make_float2(S8F, I * C8F);
    const float2 w5 = make_float2(-S8F, I * C8F);
    const float2 w6 = make_float2(-C4F, I * C4F);
    const float2 w7 = make_float2(-C8F, I * S8F);
#pragma unroll
    for (int m = 0; m < 8; m++) {
        float2 u;
        if (m == 0) u = x[8];
        else if (m == 1) u = cmul(x[9], w1);
        else if (m == 2) u = cmul(x[10], w2);
        else if (m == 3) u = cmul(x[11], w3);
        else if (m == 4) u = rot90<INV>(x[12]);
        else if (m == 5) u = cmul(x[13], w5);
        else if (m == 6) u = cmul(x[14], w6);
        else u = cmul(x[15], w7);
        float2 a = x[m];
        x[m] = make_float2(a.x + u.x, a.y + u.y);
        x[m + 8] = make_float2(a.x - u.x, a.y - u.y);
    }
}

// Generic radix-2^3 with provided twiddles (w[0]; w[1],w[2]; w[3..6]).
__device__ __forceinline__ void bf8(float2 x[8], const float2 w[7]) {
    float2 t1 = cmul(x[1], w[0]), t3 = cmul(x[3], w[0]);
    float2 y0 = make_float2(x[0].x + t1.x, x[0].y + t1.y);
    float2 y1 = make_float2(x[0].x - t1.x, x[0].y - t1.y);
    float2 y2 = make_float2(x[2].x + t3.x, x[2].y + t3.y);
    float2 y3 = make_float2(x[2].x - t3.x, x[2].y - t3.y);
    float2 u2 = cmul(y2, w[1]), u3 = cmul(y3, w[2]);
    x[0] = make_float2(y0.x + u2.x, y0.y + u2.y);
    x[2] = make_float2(y0.x - u2.x, y0.y - u2.y);
    x[1] = make_float2(y1.x + u3.x, y1.y + u3.y);
    x[3] = make_float2(y1.x - u3.x, y1.y - u3.y);
    float2 t5 = cmul(x[5], w[0]), t7 = cmul(x[7], w[0]);
    float2 z0 = make_float2(x[4].x + t5.x, x[4].y + t5.y);
    float2 z1 = make_float2(x[4].x - t5.x, x[4].y - t5.y);
    float2 z2 = make_float2(x[6].x + t7.x, x[6].y + t7.y);
    float2 z3 = make_float2(x[6].x - t7.x, x[6].y - t7.y);
    float2 v2 = cmul(z2, w[1]), v3 = cmul(z3, w[2]);
    x[4] = make_float2(z0.x + v2.x, z0.y + v2.y);
    x[6] = make_float2(z0.x - v2.x, z0.y - v2.y);
    x[5] = make_float2(z1.x + v3.x, z1.y + v3.y);
    x[7] = make_float2(z1.x - v3.x, z1.y - v3.y);
#pragma unroll
    for (int q = 0; q < 4; q++) {
        float2 u = cmul(x[q + 4], w[3 + q]);
        float2 a = x[q];
        x[q] = make_float2(a.x + u.x, a.y + u.y);
        x[q + 4] = make_float2(a.x - u.x, a.y - u.y);
    }
}

// ---------------------------------------------------------------------------
// Pass 1: real FFT length 128 along W (pack-in-pairs), 2 radix-8 passes.
// ---------------------------------------------------------------------------
__global__ __launch_bounds__(512, 2) void k_fwd_w(const float* __restrict__ x) {
    extern __shared__ float2 sm2[];
    float2* sz = sm2;               // [64][128]
    float2* stw = sm2 + 64 * 128;   // [65]
    const int t = threadIdx.x;
    if (t < 65) stw[t] = g_tw[t];
    const int cl = t & 127, q = t >> 7;
    const int b = blockIdx.z, h = blockIdx.y;
    const int c = blockIdx.x * 128 + cl;
    const float* xp = x + ((size_t)(b * HH + h) * WW) * CC + c;

#pragma unroll
    for (int rr = 0; rr < 2; rr++) {
        int j = q * 2 + rr;
        float2 xv[8];
#pragma unroll
        for (int m = 0; m < 8; m++) {
            int mm = __brev((unsigned)(j * 8 + m)) >> 26;
            xv[m] = make_float2(xp[(size_t)(2 * mm) * CC],
                                xp[(size_t)(2 * mm + 1) * CC]);
        }
        bf8_0<false>(xv);
#pragma unroll
        for (int m = 0; m < 8; m++) sz[(j * 8 + m) * 128 + cl] = xv[m];
    }
    __syncthreads();

#pragma unroll
    for (int rr = 0; rr < 2; rr++) {
        int j = q * 2 + rr;
        float2 w[7];
        w[0] = stw[j << 3];
        w[1] = stw[j << 2];
        w[2] = stw[(j + 8) << 2];
#pragma unroll
        for (int qq = 0; qq < 4; qq++) w[3 + qq] = stw[(j + qq * 8) << 1];
        float2 xv[8];
#pragma unroll
        for (int m = 0; m < 8; m++) xv[m] = sz[(j + m * 8) * 128 + cl];
        bf8(xv, w);
#pragma unroll
        for (int m = 0; m < 8; m++) sz[(j + m * 8) * 128 + cl] = xv[m];
    }
    __syncthreads();

    size_t base = ((size_t)b * WF * HH + h) * CC + c;
    const size_t ws = (size_t)HH * CC;
#pragma unroll
    for (int jj = 0; jj < 8; jj++) {
        int idx = q * 8 + jj;
        if (idx == 0) {
            float2 Z0 = sz[cl];
            g_F[base] = __float22bfloat162_rn(make_float2(Z0.x + Z0.y, 0.f));
            g_F[base + 64 * ws] = __float22bfloat162_rn(make_float2(Z0.x - Z0.y, 0.f));
            float2 Z32 = sz[32 * 128 + cl];
            g_F[base + 32 * ws] = __float22bfloat162_rn(make_float2(Z32.x, -Z32.y));
        } else {
            int k = idx;  // 1..31
            float2 Zk = sz[k * 128 + cl];
            float2 Zm = sz[(64 - k) * 128 + cl];
            float2 E = make_float2(0.5f * (Zk.x + Zm.x), 0.5f * (Zk.y - Zm.y));
            float2 D = make_float2(0.5f * (Zk.x - Zm.x), 0.5f * (Zk.y + Zm.y));
            float2 O = make_float2(D.y, -D.x);
            float2 p = cmul(stw[k], O);
            g_F[base + (size_t)k * ws] =
                __float22bfloat162_rn(make_float2(E.x + p.x, E.y + p.y));
            float2 Ec = make_float2(E.x, -E.y);
            float2 Oc = make_float2(O.x, -O.y);
            float2 qv = cmul(stw[64 - k], Oc);
            g_F[base + (size_t)(64 - k) * ws] =
                __float22bfloat162_rn(make_float2(Ec.x + qv.x, Ec.y + qv.y));
        }
    }
}

// ---------------------------------------------------------------------------
// Fused pass: FFT-H fwd + complex MLP + FFT-H inv. 256 threads, 2 CTAs/SM.
// smem overlay: sA [128][100] | sSH (tile [128][100] OR weight pair
// [2][96][52]) | tw. W1 staged after fwd FFT; W2 staged between layers.
// ---------------------------------------------------------------------------
__global__ __launch_bounds__(256, 2) void k_fused(const float* __restrict__ b1,
                                                  const float* __restrict__ b2) {
    extern __shared__ unsigned smu[];
    unsigned* sA = smu;                           // [128][100] words
    unsigned* sSH = smu + 12800;                  // [128][100] words (overlay)
    unsigned* sWr = sSH;                          // [96][52] (overlay view)
    unsigned* sWi = sSH + 4992;                   // [96][52]
    float2* stw = (float2*)(smu + 25600);         // [65]

    const int t = threadIdx.x;
    const int lane = t & 31, warp = t >> 5;
    if (t < 65) stw[t] = g_tw[t];
    const int n = blockIdx.x, wf = blockIdx.y, b = blockIdx.z;
    const size_t base = ((size_t)(b * WF + wf) * HH) * CC + n * BS;
    const unsigned* gFu = (const unsigned*)g_F;
    const uint4* wsrc = (const uint4*)(g_Wp + (size_t)n * 4 * 96 * 52);

    // -------- forward pass 1: radix-16 (k=0) from g_F -> packed tile --------
    __syncthreads();  // stw visible
#pragma unroll
    for (int rep = 0; rep < 3; rep++) {
        int idx = rep * 256 + t;
        int j = idx / 96, col = idx - j * 96;
        float2 xv[16];
#pragma unroll
        for (int m = 0; m < 16; m++) {
            int h = __brev((unsigned)(j * 16 + m)) >> 25;
            xv[m] = upk(gFu[base + (size_t)h * CC + col]);
        }
        bf16pt<false>(xv);
        unsigned* p = sSH + (j * 16) * 100 + col;
#pragma unroll
        for (int m = 0; m < 16; m++) p[m * 100] = pk(xv[m]);
    }
    __syncthreads();

    // -------- forward pass 2: radix-8, col pairs, writes A directly --------
    {
        const float s128 = 0.0078125f;
#pragma unroll
        for (int rep = 0; rep < 3; rep++) {
            int idx = rep * 256 + t;
            int j = idx / 48, w2i = idx - j * 48;
            float2 w[7];
            w[0] = stw[j << 2];
            w[1] = stw[j << 1];
            w[2] = stw[(j + 16) << 1];
#pragma unroll
            for (int qq = 0; qq < 4; qq++) w[3 + qq] = stw[j + qq * 16];
            float2 xa[8], xb[8];
#pragma unroll
            for (int m = 0; m < 8; m++) {
                int row = j + m * 16;
                uint2 v = *(uint2*)&sSH[row * 100 + 2 * w2i];
                xa[m] = upk(v.x);
                xb[m] = upk(v.y);
            }
            bf8(xa, w);
            bf8(xb, w);
#pragma unroll
            for (int m = 0; m < 8; m++) {
                int row = j + m * 16;
                sA[row * 100 + w2i] = bf2(xb[m].x * s128, xa[m].x * s128);
                sA[row * 100 + 48 + w2i] = bf2(xb[m].y * s128, xa[m].y * s128);
            }
        }
    }
    __syncthreads();  // tile consumed -> safe to overlay weights

    // Stage W1 (mats 0,1) over the tile region
    {
        uint4* dst = (uint4*)sWr;
        for (int idx = t; idx < 2496; idx += 256) dst[idx] = wsrc[idx];
    }
    __syncthreads();

    // ---------------- MLP ----------------
    const int mgrp = warp & 3, nh = warp >> 2;   // 8 warps: 4 x 2
    const int g = lane >> 2, tig = lane & 3;
    const int arow = mgrp * 32 + g;

    const unsigned sAaddr = (unsigned)__cvta_generic_to_shared(sA);
    const int matq = lane >> 3;
    const unsigned aBase0 = sAaddr +
        (unsigned)(((mgrp * 32 + (lane & 7) + (matq & 1) * 8) * 100 +
                    (matq >> 1) * 4) * 4);
    const unsigned aBase1 = aBase0 + 16u * 100u * 4u;
    const unsigned bOff0 = (unsigned)(((((matq >> 1) * 8 +
                                         (lane & 7)) * 52) + (matq & 1) * 4) * 4);
    const unsigned pStep = 16u * 52u * 4u;
    const unsigned wLo = (unsigned)__cvta_generic_to_shared((nh == 0) ? sWr : sWi);
    const unsigned wHi = (unsigned)__cvta_generic_to_shared((nh == 0) ? sWi : sWr);
    const unsigned sgnHi = (nh == 0) ? 0x80008000u : 0u;

    float acc[2][12][4];

    // ===== layer 1 =====
    {
        const float* bp = (nh == 0) ? (b1 + n * BS) : (b1 + NB * BS + n * BS);
#pragma unroll
        for (int j = 0; j < 12; j++) {
            int cih = j * 8 + 2 * tig;
            float bv0 = bp[cih], bv1 = bp[cih + 1];
#pragma unroll
            for (int mt = 0; mt < 2; mt++) {
                acc[mt][j][0] = bv0; acc[mt][j][1] = bv1;
                acc[mt][j][2] = bv0; acc[mt][j][3] = bv1;
            }
        }
#pragma unroll 1
        for (int kc = 0; kc < 12; kc++) {
            unsigned a0, a1, a2, a3, a4, a5, a6, a7;
            ldsm4(a0, a1, a2, a3, aBase0 + kc * 32);
            ldsm4(a4, a5, a6, a7, aBase1 + kc * 32);
            unsigned sgn = (kc < 6) ? 0u : sgnHi;
            unsigned wA = ((kc < 6) ? wLo + kc * 32 : wHi + (kc - 6) * 32) + bOff0;
#pragma unroll
            for (int p = 0; p < 6; p++) {
                unsigned r0, r1, r2, r3;
                ldsm4(r0, r1, r2, r3, wA + p * pStep);
                r0 ^= sgn; r1 ^= sgn; r2 ^= sgn; r3 ^= sgn;
                mma16(acc[0][2 * p], a0, a1, a2, a3, r0, r1);
                mma16(acc[1][2 * p], a4, a5, a6, a7, r0, r1);
                mma16(acc[0][2 * p + 1], a0, a1, a2, a3, r2, r3);
                mma16(acc[1][2 * p + 1], a4, a5, a6, a7, r2, r3);
            }
        }
    }
    // write relu(O) over A (packed bf16x2)
#pragma unroll
    for (int j = 0; j < 12; j++) {
        int wcol = nh * 48 + j * 4 + tig;
#pragma unroll
        for (int mt = 0; mt < 2; mt++) {
            int r0 = arow + 16 * mt;
            sA[r0 * 100 + wcol] =
                bf2(fmaxf(acc[mt][j][1], 0.f), fmaxf(acc[mt][j][0], 0.f));
            sA[(r0 + 8) * 100 + wcol] =
                bf2(fmaxf(acc[mt][j][3], 0.f), fmaxf(acc[mt][j][2], 0.f));
        }
    }
    __syncthreads();  // W1 reads + relu writes complete

    // Stage W2 (mats 2,3) over W1
    {
        uint4* dst = (uint4*)sWr;
        for (int idx = t; idx < 2496; idx += 256) dst[idx] = wsrc[2496 + idx];
    }
    __syncthreads();

    // ===== layer 2 =====
    {
        const float* bp = (nh == 0) ? (b2 + n * BS) : (b2 + NB * BS + n * BS);
#pragma unroll
        for (int j = 0; j < 12; j++) {
            int cih = j * 8 + 2 * tig;
            float bv0 = bp[cih], bv1 = bp[cih + 1];
#pragma unroll
            for (int mt = 0; mt < 2; mt++) {
                acc[mt][j][0] = bv0; acc[mt][j][1] = bv1;
                acc[mt][j][2] = bv0; acc[mt][j][3] = bv1;
            }
        }
#pragma unroll 1
        for (int kc = 0; kc < 12; kc++) {
            unsigned a0, a1, a2, a3, a4, a5, a6, a7;
            ldsm4(a0, a1, a2, a3, aBase0 + kc * 32);
            ldsm4(a4, a5, a6, a7, aBase1 + kc * 32);
            unsigned sgn = (kc < 6) ? 0u : sgnHi;
            unsigned wA = ((kc < 6) ? wLo + kc * 32 : wHi + (kc - 6) * 32) + bOff0;
#pragma unroll
            for (int p = 0; p < 6; p++) {
                unsigned r0, r1, r2, r3;
                ldsm4(r0, r1, r2, r3, wA + p * pStep);
                r0 ^= sgn; r1 ^= sgn; r2 ^= sgn; r3 ^= sgn;
                mma16(acc[0][2 * p], a0, a1, a2, a3, r0, r1);
                mma16(acc[1][2 * p], a4, a5, a6, a7, r0, r1);
                mma16(acc[0][2 * p + 1], a0, a1, a2, a3, r2, r3);
                mma16(acc[1][2 * p + 1], a4, a5, a6, a7, r2, r3);
            }
        }
    }
    __syncthreads();  // W2 reads done -> safe to overlay tile

    // softshrink -> packed bf16 tile (bit-reversed rows), 16-bit stores
    {
        __nv_bfloat16* T16 = (__nv_bfloat16*)sSH;
#pragma unroll
        for (int j = 0; j < 12; j++) {
            int ch = j * 8 + 2 * tig;
#pragma unroll
            for (int mt = 0; mt < 2; mt++) {
                int r0 = arow + 16 * mt, r1 = r0 + 8;
                int br0 = __brev((unsigned)r0) >> 25;
                int br1 = __brev((unsigned)r1) >> 25;
                T16[br0 * 200 + 2 * ch + nh] =
                    __float2bfloat16_rn(sshrink(acc[mt][j][0]));
                T16[br0 * 200 + 2 * (ch + 1) + nh] =
                    __float2bfloat16_rn(sshrink(acc[mt][j][1]));
                T16[br1 * 200 + 2 * ch + nh] =
                    __float2bfloat16_rn(sshrink(acc[mt][j][2]));
                T16[br1 * 200 + 2 * (ch + 1) + nh] =
                    __float2bfloat16_rn(sshrink(acc[mt][j][3]));
            }
        }
    }
    __syncthreads();

    // -------- inverse pass 1: radix-16 (k=0), packed tile in place --------
#pragma unroll
    for (int rep = 0; rep < 3; rep++) {
        int idx = rep * 256 + t;
        int j = idx / 96, col = idx - j * 96;
        unsigned* p = sSH + (j * 16) * 100 + col;
        float2 xv[16];
#pragma unroll
        for (int m = 0; m < 16; m++) xv[m] = upk(p[m * 100]);
        bf16pt<true>(xv);
#pragma unroll
        for (int m = 0; m < 16; m++) p[m * 100] = pk(xv[m]);
    }
    __syncthreads();

    // -------- inverse pass 2: radix-8, scatter directly to g_F --------
#pragma unroll
    for (int rep = 0; rep < 6; rep++) {
        int idx = rep * 256 + t;
        int j = idx / 96, col = idx - j * 96;
        float2 w[7];
        w[0] = stw[j << 2];
        w[1] = stw[j << 1];
        w[2] = stw[(j + 16) << 1];
#pragma unroll
        for (int qq = 0; qq < 4; qq++) w[3 + qq] = stw[j + qq * 16];
#pragma unroll
        for (int m = 0; m < 7; m++) w[m].y = -w[m].y;
        float2 xv[8];
#pragma unroll
        for (int m = 0; m < 8; m++)
            xv[m] = upk(sSH[(j + m * 16) * 100 + col]);
        bf8(xv, w);
#pragma unroll
        for (int m = 0; m < 8; m++)
            g_F[base + (size_t)(j + m * 16) * CC + col] =
                __float22bfloat162_rn(xv[m]);
    }
}

// ---------------------------------------------------------------------------
// Pass 5: inverse real FFT length 128 along W + 1/128 scale + residual add.
// ---------------------------------------------------------------------------
__global__ __launch_bounds__(512, 2) void k_inv_w(const float* __restrict__ x,
                                                  float* __restrict__ out) {
    extern __shared__ float2 sm2[];
    float2* sz = sm2;               // [64][128]
    float2* stw = sm2 + 64 * 128;   // [65]
    const int t = threadIdx.x;
    if (t < 65) stw[t] = g_tw[t];
    __syncthreads();
    const int cl = t & 127, q = t >> 7;
    const int b = blockIdx.z, h = blockIdx.y;
    const int c = blockIdx.x * 128 + cl;
    size_t base = ((size_t)b * WF * HH + h) * CC + c;
    const size_t ws = (size_t)HH * CC;

#pragma unroll
    for (int jj = 0; jj < 8; jj++) {
        int idx = q * 8 + jj;
        if (idx == 0) {
            float2 X0 = __bfloat1622float2(g_F[base]);
            float2 X64 = __bfloat1622float2(g_F[base + 64 * ws]);
            sz[cl] = make_float2(X0.x + X64.x, X0.x - X64.x);  // imag dropped
            float2 X32 = __bfloat1622float2(g_F[base + 32 * ws]);
            sz[1 * 128 + cl] = make_float2(2.f * X32.x, -2.f * X32.y);
        } else {
            int k = idx;  // 1..31
            float2 Xk = __bfloat1622float2(g_F[base + (size_t)k * ws]);
            float2 Xm = __bfloat1622float2(g_F[base + (size_t)(64 - k) * ws]);
            float2 A = make_float2(Xk.x + Xm.x, Xk.y - Xm.y);
            float2 D = make_float2(Xk.x - Xm.x, Xk.y + Xm.y);
            float2 wc = make_float2(stw[k].x, -stw[k].y);
            float2 tv = cmul(wc, D);
            sz[(__brev((unsigned)k) >> 26) * 128 + cl] =
                make_float2(A.x - tv.y, A.y + tv.x);
            float2 A2 = make_float2(Xm.x + Xk.x, Xm.y - Xk.y);
            float2 D2 = make_float2(Xm.x - Xk.x, Xm.y + Xk.y);
            float2 wc2 = make_float2(stw[64 - k].x, -stw[64 - k].y);
            float2 t2 = cmul(wc2, D2);
            sz[(__brev((unsigned)(64 - k)) >> 26) * 128 + cl] =
                make_float2(A2.x - t2.y, A2.y + t2.x);
        }
    }
    __syncthreads();

#pragma unroll
    for (int s = 0; s <= 3; s += 3) {
        int hf = 1 << s;
#pragma unroll
        for (int rr = 0; rr < 2; rr++) {
            int j = q * 2 + rr;
            int k = j & (hf - 1);
            int i0 = ((j >> s) << (s + 3)) + k;
            float2 w[7];
            w[0] = stw[k << (6 - s)];
            w[1] = stw[k << (5 - s)];
            w[2] = stw[(k + hf) << (5 - s)];
#pragma unroll
            for (int qq = 0; qq < 4; qq++) w[3 + qq] = stw[(k + qq * hf) << (4 - s)];
#pragma unroll
            for (int m = 0; m < 7; m++) w[m].y = -w[m].y;
            float2 xv[8];
#pragma unroll
            for (int m = 0; m < 8; m++) xv[m] = sz[(i0 + m * hf) * 128 + cl];
            bf8(xv, w);
#pragma unroll
            for (int m = 0; m < 8; m++) sz[(i0 + m * hf) * 128 + cl] = xv[m];
        }
        __syncthreads();
    }

    const size_t xbase = ((size_t)(b * HH + h) * WW) * CC + c;
#pragma unroll
    for (int mm = 0; mm < 16; mm++) {
        int m = q * 16 + mm;
        float2 z = sz[m * 128 + cl];
        size_t i0 = xbase + (size_t)(2 * m) * CC;
        size_t i1 = xbase + (size_t)(2 * m + 1) * CC;
        out[i0] = z.x * (1.f / 128.f) + x[i0];
        out[i1] = z.y * (1.f / 128.f) + x[i1];
    }
}

// ---------------------------------------------------------------------------
extern "C" void kernel_launch(void* const* d_in, const int* in_sizes, int n_in,
                              void* d_out, int out_size) {
    const float* x  = (const float*)d_in[0];
    const float* w1 = (const float*)d_in[1];
    const float* b1 = (const float*)d_in[2];
    const float* w2 = (const float*)d_in[3];
    const float* b2 = (const float*)d_in[4];
    float* out = (float*)d_out;

    const size_t sm_fftw = (size_t)(64 * 128 + 65) * sizeof(float2);   // 66056
    const size_t sm_fus  = (size_t)(25600) * 4 + 65 * 8;               // 102920

    cudaFuncSetAttribute(k_fwd_w, cudaFuncAttributeMaxDynamicSharedMemorySize, (int)sm_fftw);
    cudaFuncSetAttribute(k_fused, cudaFuncAttributeMaxDynamicSharedMemorySize, (int)sm_fus);
    cudaFuncSetAttribute(k_inv_w, cudaFuncAttributeMaxDynamicSharedMemorySize, (int)sm_fftw);

    k_init_tw<<<1, 128>>>();
    k_pack_w<<<NB, 256>>>(w1, w2);
    k_fwd_w<<<dim3(6, 128, 8), 512, sm_fftw>>>(x);
    k_fused<<<dim3(8, 65, 8), 256, sm_fus>>>(b1, b2);
    k_inv_w<<<dim3(6, 128, 8), 512, sm_fftw>>>(x, out);
}